// round 1
// baseline (speedup 1.0000x reference)
#include <cuda_runtime.h>
#include <math.h>

#define E_DIM 1024
#define SEQ   2048
#define BATCH 2
#define NHEAD 16
#define DK    64
#define MROWS (BATCH * SEQ)   // 4096

// Scratch (no allocations allowed in kernel_launch)
__device__ float g_q[MROWS * E_DIM];
__device__ float g_k[MROWS * E_DIM];
__device__ float g_v[MROWS * E_DIM];
__device__ float g_mix[MROWS * E_DIM];

// ---------------------------------------------------------------------------
// C[M,N] = A[M,K] * B[N,K]^T  (both operands K-contiguous; M=4096, N=K=1024)
// 128x128 block, BK=16, 256 threads, 8x8 micro-tile
// ---------------------------------------------------------------------------
__device__ __forceinline__ void gemm_body(const float* __restrict__ A,
                                          const float* __restrict__ B,
                                          float* __restrict__ C)
{
    __shared__ float As[16][128];
    __shared__ float Bs[16][128];

    const int tid = threadIdx.x;
    const int tx  = tid & 15;        // 16 col groups
    const int ty  = tid >> 4;        // 16 row groups
    const int bn  = blockIdx.x;
    const int bm  = blockIdx.y;
    const int lrow = tid >> 2;       // 0..63
    const int lcol = (tid & 3) << 2; // 0,4,8,12

    float acc[8][8];
#pragma unroll
    for (int i = 0; i < 8; i++)
#pragma unroll
        for (int j = 0; j < 8; j++) acc[i][j] = 0.f;

    const float* Abase = A + (size_t)(bm * 128) * E_DIM;
    const float* Bbase = B + (size_t)(bn * 128) * E_DIM;

    for (int kt = 0; kt < E_DIM; kt += 16) {
#pragma unroll
        for (int rr = 0; rr < 2; rr++) {
            int r = lrow + rr * 64;
            float4 av = *(const float4*)(Abase + (size_t)r * E_DIM + kt + lcol);
            As[lcol + 0][r] = av.x; As[lcol + 1][r] = av.y;
            As[lcol + 2][r] = av.z; As[lcol + 3][r] = av.w;
            float4 bv = *(const float4*)(Bbase + (size_t)r * E_DIM + kt + lcol);
            Bs[lcol + 0][r] = bv.x; Bs[lcol + 1][r] = bv.y;
            Bs[lcol + 2][r] = bv.z; Bs[lcol + 3][r] = bv.w;
        }
        __syncthreads();
#pragma unroll
        for (int kk = 0; kk < 16; kk++) {
            float4 a0 = *(const float4*)&As[kk][ty * 8];
            float4 a1 = *(const float4*)&As[kk][ty * 8 + 4];
            float4 b0 = *(const float4*)&Bs[kk][tx * 8];
            float4 b1 = *(const float4*)&Bs[kk][tx * 8 + 4];
            float a[8] = {a0.x, a0.y, a0.z, a0.w, a1.x, a1.y, a1.z, a1.w};
            float b[8] = {b0.x, b0.y, b0.z, b0.w, b1.x, b1.y, b1.z, b1.w};
#pragma unroll
            for (int i = 0; i < 8; i++)
#pragma unroll
                for (int j = 0; j < 8; j++)
                    acc[i][j] = fmaf(a[i], b[j], acc[i][j]);
        }
        __syncthreads();
    }
#pragma unroll
    for (int i = 0; i < 8; i++) {
        float* crow = C + (size_t)(bm * 128 + ty * 8 + i) * E_DIM + bn * 128 + tx * 8;
        *(float4*)(crow)     = make_float4(acc[i][0], acc[i][1], acc[i][2], acc[i][3]);
        *(float4*)(crow + 4) = make_float4(acc[i][4], acc[i][5], acc[i][6], acc[i][7]);
    }
}

__global__ __launch_bounds__(256) void qkv_gemm(const float* __restrict__ x,
                                                const float* __restrict__ Wq,
                                                const float* __restrict__ Wk,
                                                const float* __restrict__ Wv)
{
    const float* B = (blockIdx.z == 0) ? Wq : (blockIdx.z == 1) ? Wk : Wv;
    float* C       = (blockIdx.z == 0) ? g_q : (blockIdx.z == 1) ? g_k : g_v;
    gemm_body(x, B, C);
}

__global__ __launch_bounds__(256) void out_gemm(const float* __restrict__ Wo,
                                                float* __restrict__ C)
{
    gemm_body(g_mix, Wo, C);
}

// ---------------------------------------------------------------------------
// Flash attention per (b,h): Q tile 128, KV tile 64, 256 threads.
// Softmax scale (1/8) folded into Q load. Quantum constant added in epilogue.
// Output written directly in [B,S,E] "mixed" layout.
// ---------------------------------------------------------------------------
#define BQ   128
#define BKV  64
#define PADW 68   // row stride in floats (float4-aligned, conflict-reducing pad)
#define ATTN_SMEM ((BQ + 2 * BKV + BQ) * PADW * 4)

__global__ __launch_bounds__(256) void attn_kernel(const float* __restrict__ qp)
{
    extern __shared__ float sm[];
    float* Qs = sm;                   // [BQ][PADW]
    float* Ks = Qs + BQ * PADW;       // [BKV][PADW]
    float* Vs = Ks + BKV * PADW;      // [BKV][PADW]
    float* Ps = Vs + BKV * PADW;      // [BQ][PADW]

    const int tid   = threadIdx.x;
    const int qt    = blockIdx.x;
    const int bh    = blockIdx.y;
    const int b     = bh >> 4;
    const int h     = bh & 15;
    const int qbase = qt * BQ;

    const float cq = cosf(qp[0] + qp[1]);   // q_params[0,0] + q_params[0,1]

    const int row_t = tid >> 4;   // 16 groups of 8 q-rows
    const int col_t = tid & 15;   // 16 groups of 4 cols
    const int r0 = row_t * 8;
    const int c0 = col_t * 4;

    const int lc = (tid & 15) * 4;  // loader col
    const int lr = tid >> 4;        // loader row

    const float* qptr = g_q + (size_t)(b * SEQ + qbase) * E_DIM + h * DK;
    const float* kptr = g_k + (size_t)(b * SEQ) * E_DIM + h * DK;
    const float* vptr = g_v + (size_t)(b * SEQ) * E_DIM + h * DK;

    // Load Q tile, pre-scaled by 1/sqrt(dk) = 0.125
#pragma unroll
    for (int rr = lr; rr < BQ; rr += 16) {
        float4 v = *(const float4*)(qptr + (size_t)rr * E_DIM + lc);
        *(float4*)&Qs[rr * PADW + lc] =
            make_float4(v.x * 0.125f, v.y * 0.125f, v.z * 0.125f, v.w * 0.125f);
    }

    float m[8], l[8], acc[8][4];
#pragma unroll
    for (int i = 0; i < 8; i++) {
        m[i] = -1e30f; l[i] = 0.f;
#pragma unroll
        for (int j = 0; j < 4; j++) acc[i][j] = 0.f;
    }

    for (int kv = 0; kv < SEQ; kv += BKV) {
        __syncthreads();  // prior PV done (and Q tile published on iter 0)
#pragma unroll
        for (int rr = lr; rr < BKV; rr += 16) {
            *(float4*)&Ks[rr * PADW + lc] =
                *(const float4*)(kptr + (size_t)(kv + rr) * E_DIM + lc);
            *(float4*)&Vs[rr * PADW + lc] =
                *(const float4*)(vptr + (size_t)(kv + rr) * E_DIM + lc);
        }
        __syncthreads();

        // ---- scores: S = (Q/8) . K^T  (8 rows x 4 cols per thread) ----
        float s[8][4];
#pragma unroll
        for (int i = 0; i < 8; i++)
#pragma unroll
            for (int j = 0; j < 4; j++) s[i][j] = 0.f;

#pragma unroll
        for (int k4 = 0; k4 < DK; k4 += 4) {
            float4 bfr[4];
#pragma unroll
            for (int j = 0; j < 4; j++)
                bfr[j] = *(const float4*)&Ks[(c0 + j) * PADW + k4];
#pragma unroll
            for (int i = 0; i < 8; i++) {
                float4 a = *(const float4*)&Qs[(r0 + i) * PADW + k4];
#pragma unroll
                for (int j = 0; j < 4; j++) {
                    s[i][j] = fmaf(a.x, bfr[j].x, s[i][j]);
                    s[i][j] = fmaf(a.y, bfr[j].y, s[i][j]);
                    s[i][j] = fmaf(a.z, bfr[j].z, s[i][j]);
                    s[i][j] = fmaf(a.w, bfr[j].w, s[i][j]);
                }
            }
        }

        // ---- online softmax (row groups = 16 consecutive lanes) ----
#pragma unroll
        for (int i = 0; i < 8; i++) {
            float tm = fmaxf(fmaxf(s[i][0], s[i][1]), fmaxf(s[i][2], s[i][3]));
            tm = fmaxf(tm, __shfl_xor_sync(0xffffffffu, tm, 1));
            tm = fmaxf(tm, __shfl_xor_sync(0xffffffffu, tm, 2));
            tm = fmaxf(tm, __shfl_xor_sync(0xffffffffu, tm, 4));
            tm = fmaxf(tm, __shfl_xor_sync(0xffffffffu, tm, 8));
            float mnew = fmaxf(m[i], tm);
            float sc = __expf(m[i] - mnew);
            float rs = 0.f;
#pragma unroll
            for (int j = 0; j < 4; j++) {
                s[i][j] = __expf(s[i][j] - mnew);
                rs += s[i][j];
            }
            rs += __shfl_xor_sync(0xffffffffu, rs, 1);
            rs += __shfl_xor_sync(0xffffffffu, rs, 2);
            rs += __shfl_xor_sync(0xffffffffu, rs, 4);
            rs += __shfl_xor_sync(0xffffffffu, rs, 8);
            l[i] = l[i] * sc + rs;
            m[i] = mnew;
#pragma unroll
            for (int j = 0; j < 4; j++) acc[i][j] *= sc;
            *(float4*)&Ps[(r0 + i) * PADW + c0] =
                make_float4(s[i][0], s[i][1], s[i][2], s[i][3]);
        }
        __syncthreads();

        // ---- acc += P . V  (8 rows x 4 d-cols per thread) ----
#pragma unroll
        for (int c4 = 0; c4 < BKV; c4 += 4) {
            float4 vv[4];
#pragma unroll
            for (int cc = 0; cc < 4; cc++)
                vv[cc] = *(const float4*)&Vs[(c4 + cc) * PADW + c0];
#pragma unroll
            for (int i = 0; i < 8; i++) {
                float4 p = *(const float4*)&Ps[(r0 + i) * PADW + c4];
                acc[i][0] = fmaf(p.x, vv[0].x, acc[i][0]);
                acc[i][1] = fmaf(p.x, vv[0].y, acc[i][1]);
                acc[i][2] = fmaf(p.x, vv[0].z, acc[i][2]);
                acc[i][3] = fmaf(p.x, vv[0].w, acc[i][3]);
                acc[i][0] = fmaf(p.y, vv[1].x, acc[i][0]);
                acc[i][1] = fmaf(p.y, vv[1].y, acc[i][1]);
                acc[i][2] = fmaf(p.y, vv[1].z, acc[i][2]);
                acc[i][3] = fmaf(p.y, vv[1].w, acc[i][3]);
                acc[i][0] = fmaf(p.z, vv[2].x, acc[i][0]);
                acc[i][1] = fmaf(p.z, vv[2].y, acc[i][1]);
                acc[i][2] = fmaf(p.z, vv[2].z, acc[i][2]);
                acc[i][3] = fmaf(p.z, vv[2].w, acc[i][3]);
                acc[i][0] = fmaf(p.w, vv[3].x, acc[i][0]);
                acc[i][1] = fmaf(p.w, vv[3].y, acc[i][1]);
                acc[i][2] = fmaf(p.w, vv[3].z, acc[i][2]);
                acc[i][3] = fmaf(p.w, vv[3].w, acc[i][3]);
            }
        }
    }

    // ---- epilogue: normalize, add quantum constant to channels [0,4) ----
    const float addc = (c0 < 4) ? cq : 0.f;  // c0==0 covers exactly d=0..3
    float* mout = g_mix + (size_t)(b * SEQ + qbase) * E_DIM + h * DK;
#pragma unroll
    for (int i = 0; i < 8; i++) {
        float inv = 1.f / l[i];
        *(float4*)(mout + (size_t)(r0 + i) * E_DIM + c0) =
            make_float4(acc[i][0] * inv + addc, acc[i][1] * inv + addc,
                        acc[i][2] * inv + addc, acc[i][3] * inv + addc);
    }
}

// ---------------------------------------------------------------------------
extern "C" void kernel_launch(void* const* d_in, const int* in_sizes, int n_in,
                              void* d_out, int out_size)
{
    const float* x  = (const float*)d_in[0];
    const float* Wq = (const float*)d_in[1];
    const float* Wk = (const float*)d_in[2];
    const float* Wv = (const float*)d_in[3];
    const float* Wo = (const float*)d_in[4];
    const float* qp = (const float*)d_in[5];
    float* out = (float*)d_out;

    cudaFuncSetAttribute(attn_kernel,
                         cudaFuncAttributeMaxDynamicSharedMemorySize, ATTN_SMEM);

    qkv_gemm<<<dim3(8, 32, 3), 256>>>(x, Wq, Wk, Wv);
    attn_kernel<<<dim3(SEQ / BQ, BATCH * NHEAD), 256, ATTN_SMEM>>>(qp);
    out_gemm<<<dim3(8, 32), 256>>>(Wo, out);
}

// round 3
// speedup vs baseline: 1.3113x; 1.3113x over previous
#include <cuda_runtime.h>
#include <cuda_bf16.h>
#include <math.h>
#include <cstdint>

#define E_DIM 1024
#define SEQ   2048
#define BATCH 2
#define NHEAD 16
#define DK    64
#define MROWS (BATCH * SEQ)   // 4096

// ---------------------------------------------------------------------------
// Scratch (device globals; no allocations allowed)
// ---------------------------------------------------------------------------
__device__ float g_q[MROWS * E_DIM];
__device__ float g_k[MROWS * E_DIM];
__device__ float g_v[MROWS * E_DIM];
__device__ __nv_bfloat16 g_xhi[MROWS * E_DIM];
__device__ __nv_bfloat16 g_xlo[MROWS * E_DIM];
__device__ __nv_bfloat16 g_whi[4][E_DIM * E_DIM];   // q,k,v,o
__device__ __nv_bfloat16 g_wlo[4][E_DIM * E_DIM];
__device__ __nv_bfloat16 g_mhi[MROWS * E_DIM];
__device__ __nv_bfloat16 g_mlo[MROWS * E_DIM];

// ---------------------------------------------------------------------------
// Helpers
// ---------------------------------------------------------------------------
__device__ __forceinline__ uint32_t smem_to_u32(const void* p) {
    uint32_t a;
    asm("{ .reg .u64 t; cvta.to.shared.u64 t, %1; cvt.u32.u64 %0, t; }"
        : "=r"(a) : "l"(p));
    return a;
}
#define SWZ(o) ((o) ^ (((o) >> 3) & 0x70))

#define LDMATRIX_X4(r0, r1, r2, r3, addr) \
    asm volatile("ldmatrix.sync.aligned.m8n8.x4.shared.b16 {%0,%1,%2,%3}, [%4];" \
                 : "=r"(r0), "=r"(r1), "=r"(r2), "=r"(r3) : "r"(addr))

#define MMA_BF16(d, a, b) \
    asm volatile("mma.sync.aligned.m16n8k16.row.col.f32.bf16.bf16.f32 " \
                 "{%0,%1,%2,%3}, {%4,%5,%6,%7}, {%8,%9}, {%0,%1,%2,%3};" \
                 : "+f"((d)[0]), "+f"((d)[1]), "+f"((d)[2]), "+f"((d)[3]) \
                 : "r"((a)[0]), "r"((a)[1]), "r"((a)[2]), "r"((a)[3]), \
                   "r"((b)[0]), "r"((b)[1]))

// ---------------------------------------------------------------------------
// Prep: fp32 -> (hi, lo) bf16 split
// ---------------------------------------------------------------------------
__global__ __launch_bounds__(256) void prep_kernel(const float* __restrict__ src,
                                                   __nv_bfloat16* __restrict__ hi,
                                                   __nv_bfloat16* __restrict__ lo,
                                                   int n4)
{
    int i = blockIdx.x * 256 + threadIdx.x;
    if (i >= n4) return;
    float4 v = ((const float4*)src)[i];
    __nv_bfloat16 h0 = __float2bfloat16(v.x), h1 = __float2bfloat16(v.y);
    __nv_bfloat16 h2 = __float2bfloat16(v.z), h3 = __float2bfloat16(v.w);
    __nv_bfloat16 l0 = __float2bfloat16(v.x - __bfloat162float(h0));
    __nv_bfloat16 l1 = __float2bfloat16(v.y - __bfloat162float(h1));
    __nv_bfloat16 l2 = __float2bfloat16(v.z - __bfloat162float(h2));
    __nv_bfloat16 l3 = __float2bfloat16(v.w - __bfloat162float(h3));
    uint2 hv, lv;
    hv.x = (uint32_t)__bfloat16_as_ushort(h0) | ((uint32_t)__bfloat16_as_ushort(h1) << 16);
    hv.y = (uint32_t)__bfloat16_as_ushort(h2) | ((uint32_t)__bfloat16_as_ushort(h3) << 16);
    lv.x = (uint32_t)__bfloat16_as_ushort(l0) | ((uint32_t)__bfloat16_as_ushort(l1) << 16);
    lv.y = (uint32_t)__bfloat16_as_ushort(l2) | ((uint32_t)__bfloat16_as_ushort(l3) << 16);
    ((uint2*)hi)[i] = hv;
    ((uint2*)lo)[i] = lv;
}

// ---------------------------------------------------------------------------
// GEMM via mma.sync: C[M,N] = A[M,K]*B[N,K]^T, hi/lo bf16, fp32 accum.
// CTA 128x128, K chunk 64, 256 threads, warp tile 32m x 64n.
// smem: Ahi,Alo,Bhi,Blo tiles [128][64] bf16 (16KB each, 64KB total)
// ---------------------------------------------------------------------------
#define S_AHI 0
#define S_ALO 16384
#define S_BHI 32768
#define S_BLO 49152
#define G_SMEM 65536

__device__ __forceinline__ void gemm_mma_body(const __nv_bfloat16* __restrict__ Ahi,
                                              const __nv_bfloat16* __restrict__ Alo,
                                              const __nv_bfloat16* __restrict__ Bhi,
                                              const __nv_bfloat16* __restrict__ Blo,
                                              float* __restrict__ C)
{
    extern __shared__ __align__(1024) char sm[];
    const uint32_t smb = smem_to_u32(sm);
    const int tid  = threadIdx.x;
    const int w    = tid >> 5;
    const int lane = tid & 31;
    const int bm   = blockIdx.y;
    const int bn   = blockIdx.x;
    const int m0w  = (w & 3) * 32;
    const int n0w  = (w >> 2) * 64;

    float acc[2][8][4];
#pragma unroll
    for (int mt = 0; mt < 2; mt++)
#pragma unroll
        for (int nt = 0; nt < 8; nt++)
#pragma unroll
            for (int j = 0; j < 4; j++) acc[mt][nt][j] = 0.f;

    // loader indices
    const int lrow0 = tid >> 3;        // 0..31
    const int lchk  = tid & 7;         // 16B chunk within 128B row

    // ldmatrix A addresses (per mt set in loop)
    const int a_r   = (lane & 7) + ((lane >> 3) & 1) * 8;
    const int a_c16 = lane >> 4;
    // ldmatrix B addresses
    const int b_r   = (lane & 7) + ((lane >> 4) & 1) * 8;
    const int b_c16 = (lane >> 3) & 1;

    for (int kt = 0; kt < 16; kt++) {
#pragma unroll
        for (int it = 0; it < 4; it++) {
            int r = lrow0 + it * 32;
            uint32_t soff = SWZ((uint32_t)(r * 128 + lchk * 16));
            size_t ga = (size_t)(bm * 128 + r) * E_DIM + kt * 64 + lchk * 8;
            size_t gb = (size_t)(bn * 128 + r) * E_DIM + kt * 64 + lchk * 8;
            *(uint4*)(sm + S_AHI + soff) = *(const uint4*)(Ahi + ga);
            *(uint4*)(sm + S_ALO + soff) = *(const uint4*)(Alo + ga);
            *(uint4*)(sm + S_BHI + soff) = *(const uint4*)(Bhi + gb);
            *(uint4*)(sm + S_BLO + soff) = *(const uint4*)(Blo + gb);
        }
        __syncthreads();

#pragma unroll
        for (int ks = 0; ks < 4; ks++) {
            uint32_t afh[2][4], afl[2][4];
#pragma unroll
            for (int mt = 0; mt < 2; mt++) {
                int row = m0w + mt * 16 + a_r;
                uint32_t off = SWZ((uint32_t)(row * 128 + ks * 32 + a_c16 * 16));
                LDMATRIX_X4(afh[mt][0], afh[mt][1], afh[mt][2], afh[mt][3], smb + S_AHI + off);
                LDMATRIX_X4(afl[mt][0], afl[mt][1], afl[mt][2], afl[mt][3], smb + S_ALO + off);
            }
            uint32_t bfh[8][2], bfl[8][2];
#pragma unroll
            for (int ntp = 0; ntp < 4; ntp++) {
                int nrow = n0w + ntp * 16 + b_r;
                uint32_t off = SWZ((uint32_t)(nrow * 128 + ks * 32 + b_c16 * 16));
                LDMATRIX_X4(bfh[2 * ntp][0], bfh[2 * ntp][1],
                            bfh[2 * ntp + 1][0], bfh[2 * ntp + 1][1], smb + S_BHI + off);
                LDMATRIX_X4(bfl[2 * ntp][0], bfl[2 * ntp][1],
                            bfl[2 * ntp + 1][0], bfl[2 * ntp + 1][1], smb + S_BLO + off);
            }
#pragma unroll
            for (int mt = 0; mt < 2; mt++)
#pragma unroll
                for (int nt = 0; nt < 8; nt++) {
                    MMA_BF16(acc[mt][nt], afh[mt], bfh[nt]);
                    MMA_BF16(acc[mt][nt], afh[mt], bfl[nt]);
                    MMA_BF16(acc[mt][nt], afl[mt], bfh[nt]);
                }
        }
        __syncthreads();
    }

    // epilogue
#pragma unroll
    for (int mt = 0; mt < 2; mt++) {
        int m = bm * 128 + m0w + mt * 16 + (lane >> 2);
#pragma unroll
        for (int nt = 0; nt < 8; nt++) {
            int n = bn * 128 + n0w + nt * 8 + (lane & 3) * 2;
            float* p = C + (size_t)m * E_DIM + n;
            *(float2*)p = make_float2(acc[mt][nt][0], acc[mt][nt][1]);
            *(float2*)(p + (size_t)8 * E_DIM) = make_float2(acc[mt][nt][2], acc[mt][nt][3]);
        }
    }
}

__global__ __launch_bounds__(256) void qkv_gemm_mma()
{
    int z = blockIdx.z;
    float* C = (z == 0) ? g_q : (z == 1) ? g_k : g_v;
    gemm_mma_body(g_xhi, g_xlo, g_whi[z], g_wlo[z], C);
}

__global__ __launch_bounds__(256) void out_gemm_mma(float* __restrict__ C)
{
    gemm_mma_body(g_mhi, g_mlo, g_whi[3], g_wlo[3], C);
}

// ---------------------------------------------------------------------------
// Flash attention per (b,h): Q tile 128, KV tile 64, 256 threads (fp32 SIMT).
// Epilogue writes mixed output as hi/lo bf16 for the O-projection GEMM.
// ---------------------------------------------------------------------------
#define BQ   128
#define BKV  64
#define PADW 68
#define ATTN_SMEM ((BQ + 2 * BKV + BQ) * PADW * 4)

__global__ __launch_bounds__(256) void attn_kernel(const float* __restrict__ qp)
{
    extern __shared__ float smf[];
    float* Qs = smf;
    float* Ks = Qs + BQ * PADW;
    float* Vs = Ks + BKV * PADW;
    float* Ps = Vs + BKV * PADW;

    const int tid   = threadIdx.x;
    const int qt    = blockIdx.x;
    const int bh    = blockIdx.y;
    const int b     = bh >> 4;
    const int h     = bh & 15;
    const int qbase = qt * BQ;

    const float cq = cosf(qp[0] + qp[1]);

    const int r0 = (tid >> 4) * 8;
    const int c0 = (tid & 15) * 4;
    const int lc = (tid & 15) * 4;
    const int lr = tid >> 4;

    const float* qptr = g_q + (size_t)(b * SEQ + qbase) * E_DIM + h * DK;
    const float* kptr = g_k + (size_t)(b * SEQ) * E_DIM + h * DK;
    const float* vptr = g_v + (size_t)(b * SEQ) * E_DIM + h * DK;

#pragma unroll
    for (int rr = lr; rr < BQ; rr += 16) {
        float4 v = *(const float4*)(qptr + (size_t)rr * E_DIM + lc);
        *(float4*)&Qs[rr * PADW + lc] =
            make_float4(v.x * 0.125f, v.y * 0.125f, v.z * 0.125f, v.w * 0.125f);
    }

    float m[8], l[8], acc[8][4];
#pragma unroll
    for (int i = 0; i < 8; i++) {
        m[i] = -1e30f; l[i] = 0.f;
#pragma unroll
        for (int j = 0; j < 4; j++) acc[i][j] = 0.f;
    }

    for (int kv = 0; kv < SEQ; kv += BKV) {
        __syncthreads();
#pragma unroll
        for (int rr = lr; rr < BKV; rr += 16) {
            *(float4*)&Ks[rr * PADW + lc] =
                *(const float4*)(kptr + (size_t)(kv + rr) * E_DIM + lc);
            *(float4*)&Vs[rr * PADW + lc] =
                *(const float4*)(vptr + (size_t)(kv + rr) * E_DIM + lc);
        }
        __syncthreads();

        float s[8][4];
#pragma unroll
        for (int i = 0; i < 8; i++)
#pragma unroll
            for (int j = 0; j < 4; j++) s[i][j] = 0.f;

#pragma unroll
        for (int k4 = 0; k4 < DK; k4 += 4) {
            float4 bfr[4];
#pragma unroll
            for (int j = 0; j < 4; j++)
                bfr[j] = *(const float4*)&Ks[(c0 + j) * PADW + k4];
#pragma unroll
            for (int i = 0; i < 8; i++) {
                float4 a = *(const float4*)&Qs[(r0 + i) * PADW + k4];
#pragma unroll
                for (int j = 0; j < 4; j++) {
                    s[i][j] = fmaf(a.x, bfr[j].x, s[i][j]);
                    s[i][j] = fmaf(a.y, bfr[j].y, s[i][j]);
                    s[i][j] = fmaf(a.z, bfr[j].z, s[i][j]);
                    s[i][j] = fmaf(a.w, bfr[j].w, s[i][j]);
                }
            }
        }

#pragma unroll
        for (int i = 0; i < 8; i++) {
            float tm = fmaxf(fmaxf(s[i][0], s[i][1]), fmaxf(s[i][2], s[i][3]));
            tm = fmaxf(tm, __shfl_xor_sync(0xffffffffu, tm, 1));
            tm = fmaxf(tm, __shfl_xor_sync(0xffffffffu, tm, 2));
            tm = fmaxf(tm, __shfl_xor_sync(0xffffffffu, tm, 4));
            tm = fmaxf(tm, __shfl_xor_sync(0xffffffffu, tm, 8));
            float mnew = fmaxf(m[i], tm);
            float sc = __expf(m[i] - mnew);
            float rs = 0.f;
#pragma unroll
            for (int j = 0; j < 4; j++) {
                s[i][j] = __expf(s[i][j] - mnew);
                rs += s[i][j];
            }
            rs += __shfl_xor_sync(0xffffffffu, rs, 1);
            rs += __shfl_xor_sync(0xffffffffu, rs, 2);
            rs += __shfl_xor_sync(0xffffffffu, rs, 4);
            rs += __shfl_xor_sync(0xffffffffu, rs, 8);
            l[i] = l[i] * sc + rs;
            m[i] = mnew;
#pragma unroll
            for (int j = 0; j < 4; j++) acc[i][j] *= sc;
            *(float4*)&Ps[(r0 + i) * PADW + c0] =
                make_float4(s[i][0], s[i][1], s[i][2], s[i][3]);
        }
        __syncthreads();

#pragma unroll
        for (int c4 = 0; c4 < BKV; c4 += 4) {
            float4 vv[4];
#pragma unroll
            for (int cc = 0; cc < 4; cc++)
                vv[cc] = *(const float4*)&Vs[(c4 + cc) * PADW + c0];
#pragma unroll
            for (int i = 0; i < 8; i++) {
                float4 p = *(const float4*)&Ps[(r0 + i) * PADW + c4];
                acc[i][0] = fmaf(p.x, vv[0].x, acc[i][0]);
                acc[i][1] = fmaf(p.x, vv[0].y, acc[i][1]);
                acc[i][2] = fmaf(p.x, vv[0].z, acc[i][2]);
                acc[i][3] = fmaf(p.x, vv[0].w, acc[i][3]);
                acc[i][0] = fmaf(p.y, vv[1].x, acc[i][0]);
                acc[i][1] = fmaf(p.y, vv[1].y, acc[i][1]);
                acc[i][2] = fmaf(p.y, vv[1].z, acc[i][2]);
                acc[i][3] = fmaf(p.y, vv[1].w, acc[i][3]);
                acc[i][0] = fmaf(p.z, vv[2].x, acc[i][0]);
                acc[i][1] = fmaf(p.z, vv[2].y, acc[i][1]);
                acc[i][2] = fmaf(p.z, vv[2].z, acc[i][2]);
                acc[i][3] = fmaf(p.z, vv[2].w, acc[i][3]);
                acc[i][0] = fmaf(p.w, vv[3].x, acc[i][0]);
                acc[i][1] = fmaf(p.w, vv[3].y, acc[i][1]);
                acc[i][2] = fmaf(p.w, vv[3].z, acc[i][2]);
                acc[i][3] = fmaf(p.w, vv[3].w, acc[i][3]);
            }
        }
    }

    // epilogue: normalize, +c on d<4, write hi/lo bf16 mix
    const float addc = (c0 < 4) ? cq : 0.f;
    const size_t obase = (size_t)(b * SEQ + qbase) * E_DIM + h * DK + c0;
#pragma unroll
    for (int i = 0; i < 8; i++) {
        float inv = 1.f / l[i];
        float o[4];
#pragma unroll
        for (int j = 0; j < 4; j++) o[j] = acc[i][j] * inv + addc;
        __nv_bfloat16 hb[4], lb[4];
#pragma unroll
        for (int j = 0; j < 4; j++) {
            hb[j] = __float2bfloat16(o[j]);
            lb[j] = __float2bfloat16(o[j] - __bfloat162float(hb[j]));
        }
        uint2 hv, lv;
        hv.x = (uint32_t)__bfloat16_as_ushort(hb[0]) | ((uint32_t)__bfloat16_as_ushort(hb[1]) << 16);
        hv.y = (uint32_t)__bfloat16_as_ushort(hb[2]) | ((uint32_t)__bfloat16_as_ushort(hb[3]) << 16);
        lv.x = (uint32_t)__bfloat16_as_ushort(lb[0]) | ((uint32_t)__bfloat16_as_ushort(lb[1]) << 16);
        lv.y = (uint32_t)__bfloat16_as_ushort(lb[2]) | ((uint32_t)__bfloat16_as_ushort(lb[3]) << 16);
        *(uint2*)(g_mhi + obase + (size_t)(r0 + i) * E_DIM) = hv;
        *(uint2*)(g_mlo + obase + (size_t)(r0 + i) * E_DIM) = lv;
    }
}

// ---------------------------------------------------------------------------
extern "C" void kernel_launch(void* const* d_in, const int* in_sizes, int n_in,
                              void* d_out, int out_size)
{
    const float* x  = (const float*)d_in[0];
    const float* Wq = (const float*)d_in[1];
    const float* Wk = (const float*)d_in[2];
    const float* Wv = (const float*)d_in[3];
    const float* Wo = (const float*)d_in[4];
    const float* qp = (const float*)d_in[5];
    float* out = (float*)d_out;

    cudaFuncSetAttribute(qkv_gemm_mma, cudaFuncAttributeMaxDynamicSharedMemorySize, G_SMEM);
    cudaFuncSetAttribute(out_gemm_mma, cudaFuncAttributeMaxDynamicSharedMemorySize, G_SMEM);
    cudaFuncSetAttribute(attn_kernel,  cudaFuncAttributeMaxDynamicSharedMemorySize, ATTN_SMEM);

    __nv_bfloat16 *xhi, *xlo, *whi, *wlo;
    cudaGetSymbolAddress((void**)&xhi, g_xhi);
    cudaGetSymbolAddress((void**)&xlo, g_xlo);
    cudaGetSymbolAddress((void**)&whi, g_whi);
    cudaGetSymbolAddress((void**)&wlo, g_wlo);

    const int NW = E_DIM * E_DIM;             // 1M
    prep_kernel<<<(MROWS * E_DIM / 4 + 255) / 256, 256>>>(x, xhi, xlo, MROWS * E_DIM / 4);
    prep_kernel<<<(NW / 4 + 255) / 256, 256>>>(Wq, whi + 0 * NW, wlo + 0 * NW, NW / 4);
    prep_kernel<<<(NW / 4 + 255) / 256, 256>>>(Wk, whi + 1 * NW, wlo + 1 * NW, NW / 4);
    prep_kernel<<<(NW / 4 + 255) / 256, 256>>>(Wv, whi + 2 * NW, wlo + 2 * NW, NW / 4);
    prep_kernel<<<(NW / 4 + 255) / 256, 256>>>(Wo, whi + 3 * NW, wlo + 3 * NW, NW / 4);

    qkv_gemm_mma<<<dim3(8, 32, 3), 256, G_SMEM>>>();
    attn_kernel<<<dim3(SEQ / BQ, BATCH * NHEAD), 256, ATTN_SMEM>>>(qp);
    out_gemm_mma<<<dim3(8, 32), 256, G_SMEM>>>(out);
}

// round 4
// speedup vs baseline: 2.9490x; 2.2489x over previous
#include <cuda_runtime.h>
#include <cuda_bf16.h>
#include <math.h>
#include <cstdint>

#define E_DIM 1024
#define SEQ   2048
#define BATCH 2
#define NHEAD 16
#define DK    64
#define MROWS (BATCH * SEQ)   // 4096

// ---------------------------------------------------------------------------
// Scratch (device globals; no allocations allowed)
// ---------------------------------------------------------------------------
__device__ __nv_bfloat16 g_xhi[MROWS * E_DIM];
__device__ __nv_bfloat16 g_xlo[MROWS * E_DIM];
__device__ __nv_bfloat16 g_whi[4][E_DIM * E_DIM];   // q,k,v,o
__device__ __nv_bfloat16 g_wlo[4][E_DIM * E_DIM];
__device__ __nv_bfloat16 g_qhi[MROWS * E_DIM];
__device__ __nv_bfloat16 g_qlo[MROWS * E_DIM];
__device__ __nv_bfloat16 g_khi[MROWS * E_DIM];
__device__ __nv_bfloat16 g_klo[MROWS * E_DIM];
__device__ __nv_bfloat16 g_vhi[MROWS * E_DIM];
__device__ __nv_bfloat16 g_vlo[MROWS * E_DIM];
__device__ __nv_bfloat16 g_mhi[MROWS * E_DIM];
__device__ __nv_bfloat16 g_mlo[MROWS * E_DIM];

// ---------------------------------------------------------------------------
// Helpers
// ---------------------------------------------------------------------------
__device__ __forceinline__ uint32_t smem_to_u32(const void* p) {
    uint32_t a;
    asm("{ .reg .u64 t; cvta.to.shared.u64 t, %1; cvt.u32.u64 %0, t; }"
        : "=r"(a) : "l"(p));
    return a;
}
#define SWZ(o) ((o) ^ (((o) >> 3) & 0x70))

#define LDMATRIX_X4(r0, r1, r2, r3, addr) \
    asm volatile("ldmatrix.sync.aligned.m8n8.x4.shared.b16 {%0,%1,%2,%3}, [%4];" \
                 : "=r"(r0), "=r"(r1), "=r"(r2), "=r"(r3) : "r"(addr))

#define LDMATRIX_X4_T(r0, r1, r2, r3, addr) \
    asm volatile("ldmatrix.sync.aligned.m8n8.x4.trans.shared.b16 {%0,%1,%2,%3}, [%4];" \
                 : "=r"(r0), "=r"(r1), "=r"(r2), "=r"(r3) : "r"(addr))

#define MMA_BF16(d, a, b) \
    asm volatile("mma.sync.aligned.m16n8k16.row.col.f32.bf16.bf16.f32 " \
                 "{%0,%1,%2,%3}, {%4,%5,%6,%7}, {%8,%9}, {%0,%1,%2,%3};" \
                 : "+f"((d)[0]), "+f"((d)[1]), "+f"((d)[2]), "+f"((d)[3]) \
                 : "r"((a)[0]), "r"((a)[1]), "r"((a)[2]), "r"((a)[3]), \
                   "r"((b)[0]), "r"((b)[1]))

#define CP_ASYNC16(s, g) \
    asm volatile("cp.async.cg.shared.global [%0], [%1], 16;" :: "r"(s), "l"(g))
#define CP_COMMIT() asm volatile("cp.async.commit_group;" ::: "memory")

// pack two floats -> bf16x2 hi word + bf16x2 residual word
__device__ __forceinline__ void pack_hilo(float a, float b, unsigned& h, unsigned& l) {
    asm("cvt.rn.bf16x2.f32 %0, %1, %2;" : "=r"(h) : "f"(b), "f"(a));
    float fa = __uint_as_float(h << 16);
    float fb = __uint_as_float(h & 0xffff0000u);
    asm("cvt.rn.bf16x2.f32 %0, %1, %2;" : "=r"(l) : "f"(b - fb), "f"(a - fa));
}

// ---------------------------------------------------------------------------
// Prep: fp32 -> (hi, lo) bf16 split
// ---------------------------------------------------------------------------
__global__ __launch_bounds__(256) void prep_kernel(const float* __restrict__ src,
                                                   __nv_bfloat16* __restrict__ hi,
                                                   __nv_bfloat16* __restrict__ lo,
                                                   int n4)
{
    int i = blockIdx.x * 256 + threadIdx.x;
    if (i >= n4) return;
    float4 v = ((const float4*)src)[i];
    unsigned h0, l0, h1, l1;
    pack_hilo(v.x, v.y, h0, l0);
    pack_hilo(v.z, v.w, h1, l1);
    ((uint2*)hi)[i] = make_uint2(h0, h1);
    ((uint2*)lo)[i] = make_uint2(l0, l1);
}

// ---------------------------------------------------------------------------
// GEMM via mma.sync: C[M,N] = A[M,K]*B[N,K]^T, hi/lo bf16, fp32 accum.
// CTA 128x128, K chunk 64, 256 threads, warp tile 32m x 64n.
// OUTMODE 0: fp32 out.  OUTMODE 1: bf16 hi/lo out (scaled).
// ---------------------------------------------------------------------------
#define S_AHI 0
#define S_ALO 16384
#define S_BHI 32768
#define S_BLO 49152
#define G_SMEM 65536

template<int OUTMODE>
__device__ __forceinline__ void gemm_mma_body(const __nv_bfloat16* __restrict__ Ahi,
                                              const __nv_bfloat16* __restrict__ Alo,
                                              const __nv_bfloat16* __restrict__ Bhi,
                                              const __nv_bfloat16* __restrict__ Blo,
                                              float* __restrict__ Cf,
                                              __nv_bfloat16* __restrict__ Chi,
                                              __nv_bfloat16* __restrict__ Clo,
                                              float scale)
{
    extern __shared__ __align__(1024) char sm[];
    const uint32_t smb = smem_to_u32(sm);
    const int tid  = threadIdx.x;
    const int w    = tid >> 5;
    const int lane = tid & 31;
    const int bm   = blockIdx.y;
    const int bn   = blockIdx.x;
    const int m0w  = (w & 3) * 32;
    const int n0w  = (w >> 2) * 64;

    float acc[2][8][4];
#pragma unroll
    for (int mt = 0; mt < 2; mt++)
#pragma unroll
        for (int nt = 0; nt < 8; nt++)
#pragma unroll
            for (int j = 0; j < 4; j++) acc[mt][nt][j] = 0.f;

    const int lrow0 = tid >> 3;
    const int lchk  = tid & 7;

    const int a_r   = (lane & 7) + ((lane >> 3) & 1) * 8;
    const int a_c16 = lane >> 4;
    const int b_r   = (lane & 7) + ((lane >> 4) & 1) * 8;
    const int b_c16 = (lane >> 3) & 1;

    for (int kt = 0; kt < 16; kt++) {
#pragma unroll
        for (int it = 0; it < 4; it++) {
            int r = lrow0 + it * 32;
            uint32_t soff = SWZ((uint32_t)(r * 128 + lchk * 16));
            size_t ga = (size_t)(bm * 128 + r) * E_DIM + kt * 64 + lchk * 8;
            size_t gb = (size_t)(bn * 128 + r) * E_DIM + kt * 64 + lchk * 8;
            *(uint4*)(sm + S_AHI + soff) = *(const uint4*)(Ahi + ga);
            *(uint4*)(sm + S_ALO + soff) = *(const uint4*)(Alo + ga);
            *(uint4*)(sm + S_BHI + soff) = *(const uint4*)(Bhi + gb);
            *(uint4*)(sm + S_BLO + soff) = *(const uint4*)(Blo + gb);
        }
        __syncthreads();

#pragma unroll
        for (int ks = 0; ks < 4; ks++) {
            uint32_t afh[2][4], afl[2][4];
#pragma unroll
            for (int mt = 0; mt < 2; mt++) {
                int row = m0w + mt * 16 + a_r;
                uint32_t off = SWZ((uint32_t)(row * 128 + ks * 32 + a_c16 * 16));
                LDMATRIX_X4(afh[mt][0], afh[mt][1], afh[mt][2], afh[mt][3], smb + S_AHI + off);
                LDMATRIX_X4(afl[mt][0], afl[mt][1], afl[mt][2], afl[mt][3], smb + S_ALO + off);
            }
            uint32_t bfh[8][2], bfl[8][2];
#pragma unroll
            for (int ntp = 0; ntp < 4; ntp++) {
                int nrow = n0w + ntp * 16 + b_r;
                uint32_t off = SWZ((uint32_t)(nrow * 128 + ks * 32 + b_c16 * 16));
                LDMATRIX_X4(bfh[2 * ntp][0], bfh[2 * ntp][1],
                            bfh[2 * ntp + 1][0], bfh[2 * ntp + 1][1], smb + S_BHI + off);
                LDMATRIX_X4(bfl[2 * ntp][0], bfl[2 * ntp][1],
                            bfl[2 * ntp + 1][0], bfl[2 * ntp + 1][1], smb + S_BLO + off);
            }
#pragma unroll
            for (int mt = 0; mt < 2; mt++)
#pragma unroll
                for (int nt = 0; nt < 8; nt++) {
                    MMA_BF16(acc[mt][nt], afh[mt], bfh[nt]);
                    MMA_BF16(acc[mt][nt], afh[mt], bfl[nt]);
                    MMA_BF16(acc[mt][nt], afl[mt], bfh[nt]);
                }
        }
        __syncthreads();
    }

#pragma unroll
    for (int mt = 0; mt < 2; mt++) {
        size_t m = (size_t)(bm * 128 + m0w + mt * 16 + (lane >> 2));
#pragma unroll
        for (int nt = 0; nt < 8; nt++) {
            size_t n = (size_t)(bn * 128 + n0w + nt * 8 + (lane & 3) * 2);
            if (OUTMODE == 0) {
                float* p = Cf + m * E_DIM + n;
                *(float2*)p = make_float2(acc[mt][nt][0], acc[mt][nt][1]);
                *(float2*)(p + (size_t)8 * E_DIM) = make_float2(acc[mt][nt][2], acc[mt][nt][3]);
            } else {
                unsigned hh, ll;
                pack_hilo(acc[mt][nt][0] * scale, acc[mt][nt][1] * scale, hh, ll);
                *(unsigned*)(Chi + m * E_DIM + n) = hh;
                *(unsigned*)(Clo + m * E_DIM + n) = ll;
                pack_hilo(acc[mt][nt][2] * scale, acc[mt][nt][3] * scale, hh, ll);
                *(unsigned*)(Chi + (m + 8) * E_DIM + n) = hh;
                *(unsigned*)(Clo + (m + 8) * E_DIM + n) = ll;
            }
        }
    }
}

__global__ __launch_bounds__(256) void qkv_gemm_mma()
{
    int z = blockIdx.z;
    __nv_bfloat16* Chi = (z == 0) ? g_qhi : (z == 1) ? g_khi : g_vhi;
    __nv_bfloat16* Clo = (z == 0) ? g_qlo : (z == 1) ? g_klo : g_vlo;
    float scale = (z == 0) ? 0.125f : 1.0f;   // fold 1/sqrt(dk) into Q
    gemm_mma_body<1>(g_xhi, g_xlo, g_whi[z], g_wlo[z], nullptr, Chi, Clo, scale);
}

__global__ __launch_bounds__(256) void out_gemm_mma(float* __restrict__ C)
{
    gemm_mma_body<0>(g_mhi, g_mlo, g_whi[3], g_wlo[3], C, nullptr, nullptr, 1.0f);
}

// ---------------------------------------------------------------------------
// Flash attention with mma.sync, hi/lo bf16. Per CTA: 128 q rows of one (b,h).
// 8 warps x 16 q-rows. KV tile 64, double-buffered cp.async.
// smem: 2 stages x (Khi,Klo,Vhi,Vlo)[64][64] bf16 = 64KB.
// ---------------------------------------------------------------------------
#define A_KHI 0
#define A_KLO 8192
#define A_VHI 16384
#define A_VLO 24576
#define ASTAGE 32768
#define ATTN_SMEM 65536
#define NKV (SEQ / 64)   // 32

__global__ __launch_bounds__(256, 1) void attn_mma(const float* __restrict__ qp)
{
    extern __shared__ __align__(1024) char sm[];
    const uint32_t smb = smem_to_u32(sm);
    const int tid  = threadIdx.x;
    const int wid  = tid >> 5;
    const int lane = tid & 31;
    const int bh   = blockIdx.y;
    const int b    = bh >> 4;
    const int h    = bh & 15;
    const int qbase = blockIdx.x * 128;
    const int wq0   = wid * 16;
    const float cq  = cosf(qp[0] + qp[1]);

    const size_t bS = (size_t)b * SEQ;
    const int h64 = h * 64;

    // ---- Q fragments (direct LDG, held for whole loop) ----
    unsigned qh[4][4], ql[4][4];
    {
        const size_t base = (bS + qbase + wq0 + (lane >> 2)) * E_DIM + h64 + (lane & 3) * 2;
        const __nv_bfloat16* qhp = g_qhi + base;
        const __nv_bfloat16* qlp = g_qlo + base;
#pragma unroll
        for (int ks = 0; ks < 4; ks++) {
            qh[ks][0] = *(const unsigned*)(qhp + ks * 16);
            qh[ks][1] = *(const unsigned*)(qhp + 8 * E_DIM + ks * 16);
            qh[ks][2] = *(const unsigned*)(qhp + ks * 16 + 8);
            qh[ks][3] = *(const unsigned*)(qhp + 8 * E_DIM + ks * 16 + 8);
            ql[ks][0] = *(const unsigned*)(qlp + ks * 16);
            ql[ks][1] = *(const unsigned*)(qlp + 8 * E_DIM + ks * 16);
            ql[ks][2] = *(const unsigned*)(qlp + ks * 16 + 8);
            ql[ks][3] = *(const unsigned*)(qlp + 8 * E_DIM + ks * 16 + 8);
        }
    }

    // ---- cp.async loader geometry (2 chunks of 16B per thread per buffer) ----
    const __nv_bfloat16* khg = g_khi + bS * E_DIM + h64;
    const __nv_bfloat16* klg = g_klo + bS * E_DIM + h64;
    const __nv_bfloat16* vhg = g_vhi + bS * E_DIM + h64;
    const __nv_bfloat16* vlg = g_vlo + bS * E_DIM + h64;
    const int crow0 = tid >> 3;                 // 0..31 (second chunk +32)
    const int ccol  = (tid & 7) * 8;            // element col
    const uint32_t sco  = SWZ((uint32_t)(crow0 * 128 + (tid & 7) * 16));
    const uint32_t sco2 = SWZ((uint32_t)((crow0 + 32) * 128 + (tid & 7) * 16));

    auto issue_stage = [&](int st) {
        const uint32_t sb = smb + (uint32_t)(st & 1) * ASTAGE;
        const size_t r0 = (size_t)(st * 64 + crow0) * E_DIM + ccol;
        const size_t r1 = r0 + (size_t)32 * E_DIM;
        CP_ASYNC16(sb + A_KHI + sco,  khg + r0);
        CP_ASYNC16(sb + A_KHI + sco2, khg + r1);
        CP_ASYNC16(sb + A_KLO + sco,  klg + r0);
        CP_ASYNC16(sb + A_KLO + sco2, klg + r1);
        CP_ASYNC16(sb + A_VHI + sco,  vhg + r0);
        CP_ASYNC16(sb + A_VHI + sco2, vhg + r1);
        CP_ASYNC16(sb + A_VLO + sco,  vlg + r0);
        CP_ASYNC16(sb + A_VLO + sco2, vlg + r1);
        CP_COMMIT();
    };

    issue_stage(0);
    issue_stage(1);

    float m0 = -1e30f, m1 = -1e30f, l0 = 0.f, l1 = 0.f;
    float oacc[8][4];
#pragma unroll
    for (int nt = 0; nt < 8; nt++)
#pragma unroll
        for (int j = 0; j < 4; j++) oacc[nt][j] = 0.f;

    const int brow = (lane & 7) + ((lane >> 4) & 1) * 8;
    const int bc16 = (lane >> 3) & 1;
    const int vrow = lane & 15;
    const int vcs  = (lane >> 4) * 16;

    for (int it = 0; it < NKV; it++) {
        if (it < NKV - 1) asm volatile("cp.async.wait_group 1;" ::: "memory");
        else              asm volatile("cp.async.wait_group 0;" ::: "memory");
        __syncthreads();

        const uint32_t sb = smb + (uint32_t)(it & 1) * ASTAGE;

        // ---- S = Q.K^T (hi/lo, 3 passes) ----
        float sacc[8][4];
#pragma unroll
        for (int nt = 0; nt < 8; nt++)
#pragma unroll
            for (int j = 0; j < 4; j++) sacc[nt][j] = 0.f;

#pragma unroll
        for (int ks = 0; ks < 4; ks++) {
            unsigned kh2[8][2], kl2[8][2];
#pragma unroll
            for (int ntp = 0; ntp < 4; ntp++) {
                uint32_t off = SWZ((uint32_t)((ntp * 16 + brow) * 128 + ks * 32 + bc16 * 16));
                LDMATRIX_X4(kh2[2 * ntp][0], kh2[2 * ntp][1],
                            kh2[2 * ntp + 1][0], kh2[2 * ntp + 1][1], sb + A_KHI + off);
                LDMATRIX_X4(kl2[2 * ntp][0], kl2[2 * ntp][1],
                            kl2[2 * ntp + 1][0], kl2[2 * ntp + 1][1], sb + A_KLO + off);
            }
#pragma unroll
            for (int nt = 0; nt < 8; nt++) {
                MMA_BF16(sacc[nt], qh[ks], kh2[nt]);
                MMA_BF16(sacc[nt], qh[ks], kl2[nt]);
                MMA_BF16(sacc[nt], ql[ks], kh2[nt]);
            }
        }

        // ---- online softmax on fragment layout (rows r and r+8) ----
        float mn0 = m0, mn1 = m1;
#pragma unroll
        for (int nt = 0; nt < 8; nt++) {
            mn0 = fmaxf(mn0, fmaxf(sacc[nt][0], sacc[nt][1]));
            mn1 = fmaxf(mn1, fmaxf(sacc[nt][2], sacc[nt][3]));
        }
        mn0 = fmaxf(mn0, __shfl_xor_sync(0xffffffffu, mn0, 1));
        mn0 = fmaxf(mn0, __shfl_xor_sync(0xffffffffu, mn0, 2));
        mn1 = fmaxf(mn1, __shfl_xor_sync(0xffffffffu, mn1, 1));
        mn1 = fmaxf(mn1, __shfl_xor_sync(0xffffffffu, mn1, 2));
        float sc0 = __expf(m0 - mn0);
        float sc1 = __expf(m1 - mn1);
        m0 = mn0; m1 = mn1;
        float rs0 = 0.f, rs1 = 0.f;
#pragma unroll
        for (int nt = 0; nt < 8; nt++) {
            sacc[nt][0] = __expf(sacc[nt][0] - m0); rs0 += sacc[nt][0];
            sacc[nt][1] = __expf(sacc[nt][1] - m0); rs0 += sacc[nt][1];
            sacc[nt][2] = __expf(sacc[nt][2] - m1); rs1 += sacc[nt][2];
            sacc[nt][3] = __expf(sacc[nt][3] - m1); rs1 += sacc[nt][3];
        }
        rs0 += __shfl_xor_sync(0xffffffffu, rs0, 1);
        rs0 += __shfl_xor_sync(0xffffffffu, rs0, 2);
        rs1 += __shfl_xor_sync(0xffffffffu, rs1, 1);
        rs1 += __shfl_xor_sync(0xffffffffu, rs1, 2);
        l0 = l0 * sc0 + rs0;
        l1 = l1 * sc1 + rs1;
#pragma unroll
        for (int nt = 0; nt < 8; nt++) {
            oacc[nt][0] *= sc0; oacc[nt][1] *= sc0;
            oacc[nt][2] *= sc1; oacc[nt][3] *= sc1;
        }

        // ---- O += P.V (P from registers; V via ldmatrix.trans; 3 passes) ----
#pragma unroll
        for (int j = 0; j < 4; j++) {
            unsigned ph[4], pl[4];
            pack_hilo(sacc[2 * j][0],     sacc[2 * j][1],     ph[0], pl[0]);
            pack_hilo(sacc[2 * j][2],     sacc[2 * j][3],     ph[1], pl[1]);
            pack_hilo(sacc[2 * j + 1][0], sacc[2 * j + 1][1], ph[2], pl[2]);
            pack_hilo(sacc[2 * j + 1][2], sacc[2 * j + 1][3], ph[3], pl[3]);
            unsigned vh2[8][2], vl2[8][2];
#pragma unroll
            for (int dp = 0; dp < 4; dp++) {
                uint32_t off = SWZ((uint32_t)((j * 16 + vrow) * 128 + dp * 32 + vcs));
                LDMATRIX_X4_T(vh2[2 * dp][0], vh2[2 * dp][1],
                              vh2[2 * dp + 1][0], vh2[2 * dp + 1][1], sb + A_VHI + off);
                LDMATRIX_X4_T(vl2[2 * dp][0], vl2[2 * dp][1],
                              vl2[2 * dp + 1][0], vl2[2 * dp + 1][1], sb + A_VLO + off);
            }
#pragma unroll
            for (int nt = 0; nt < 8; nt++) {
                MMA_BF16(oacc[nt], ph, vh2[nt]);
                MMA_BF16(oacc[nt], ph, vl2[nt]);
                MMA_BF16(oacc[nt], pl, vh2[nt]);
            }
        }

        __syncthreads();
        if (it < NKV - 2) issue_stage(it + 2);
    }

    // ---- epilogue: normalize, +c on dk<4, write hi/lo bf16 mix ----
    const float inv0 = 1.f / l0;
    const float inv1 = 1.f / l1;
    const size_t row0 = (bS + qbase + wq0 + (lane >> 2)) * E_DIM + h64 + (lane & 3) * 2;
    const size_t row1 = row0 + 8 * E_DIM;
    const bool adds = ((lane & 3) < 2);
#pragma unroll
    for (int nt = 0; nt < 8; nt++) {
        const float add = (nt == 0 && adds) ? cq : 0.f;
        float v0 = oacc[nt][0] * inv0 + add;
        float v1 = oacc[nt][1] * inv0 + add;
        float v2 = oacc[nt][2] * inv1 + add;
        float v3 = oacc[nt][3] * inv1 + add;
        unsigned hh, ll;
        pack_hilo(v0, v1, hh, ll);
        *(unsigned*)(g_mhi + row0 + nt * 8) = hh;
        *(unsigned*)(g_mlo + row0 + nt * 8) = ll;
        pack_hilo(v2, v3, hh, ll);
        *(unsigned*)(g_mhi + row1 + nt * 8) = hh;
        *(unsigned*)(g_mlo + row1 + nt * 8) = ll;
    }
}

// ---------------------------------------------------------------------------
extern "C" void kernel_launch(void* const* d_in, const int* in_sizes, int n_in,
                              void* d_out, int out_size)
{
    const float* x  = (const float*)d_in[0];
    const float* Wq = (const float*)d_in[1];
    const float* Wk = (const float*)d_in[2];
    const float* Wv = (const float*)d_in[3];
    const float* Wo = (const float*)d_in[4];
    const float* qp = (const float*)d_in[5];
    float* out = (float*)d_out;

    cudaFuncSetAttribute(qkv_gemm_mma, cudaFuncAttributeMaxDynamicSharedMemorySize, G_SMEM);
    cudaFuncSetAttribute(out_gemm_mma, cudaFuncAttributeMaxDynamicSharedMemorySize, G_SMEM);
    cudaFuncSetAttribute(attn_mma,     cudaFuncAttributeMaxDynamicSharedMemorySize, ATTN_SMEM);

    __nv_bfloat16 *xhi, *xlo, *whi, *wlo;
    cudaGetSymbolAddress((void**)&xhi, g_xhi);
    cudaGetSymbolAddress((void**)&xlo, g_xlo);
    cudaGetSymbolAddress((void**)&whi, g_whi);
    cudaGetSymbolAddress((void**)&wlo, g_wlo);

    const int NW = E_DIM * E_DIM;
    prep_kernel<<<(MROWS * E_DIM / 4 + 255) / 256, 256>>>(x, xhi, xlo, MROWS * E_DIM / 4);
    prep_kernel<<<(NW / 4 + 255) / 256, 256>>>(Wq, whi + 0 * (size_t)NW, wlo + 0 * (size_t)NW, NW / 4);
    prep_kernel<<<(NW / 4 + 255) / 256, 256>>>(Wk, whi + 1 * (size_t)NW, wlo + 1 * (size_t)NW, NW / 4);
    prep_kernel<<<(NW / 4 + 255) / 256, 256>>>(Wv, whi + 2 * (size_t)NW, wlo + 2 * (size_t)NW, NW / 4);
    prep_kernel<<<(NW / 4 + 255) / 256, 256>>>(Wo, whi + 3 * (size_t)NW, wlo + 3 * (size_t)NW, NW / 4);

    qkv_gemm_mma<<<dim3(8, 32, 3), 256, G_SMEM>>>();
    attn_mma<<<dim3(SEQ / 128, BATCH * NHEAD), 256, ATTN_SMEM>>>(qp);
    out_gemm_mma<<<dim3(8, 32), 256, G_SMEM>>>(out);
}

// round 5
// speedup vs baseline: 3.1908x; 1.0820x over previous
#include <cuda_runtime.h>
#include <cuda_bf16.h>
#include <math.h>
#include <cstdint>

#define E_DIM 1024
#define SEQ   2048
#define BATCH 2
#define NHEAD 16
#define DK    64
#define MROWS (BATCH * SEQ)   // 4096

// ---------------------------------------------------------------------------
// Scratch (device globals; no allocations allowed)
// ---------------------------------------------------------------------------
__device__ __nv_bfloat16 g_xhi[MROWS * E_DIM];
__device__ __nv_bfloat16 g_xlo[MROWS * E_DIM];
__device__ __nv_bfloat16 g_whi[4][E_DIM * E_DIM];   // q,k,v,o
__device__ __nv_bfloat16 g_wlo[4][E_DIM * E_DIM];
__device__ __nv_bfloat16 g_qhi[MROWS * E_DIM];
__device__ __nv_bfloat16 g_qlo[MROWS * E_DIM];
__device__ __nv_bfloat16 g_khi[MROWS * E_DIM];
__device__ __nv_bfloat16 g_klo[MROWS * E_DIM];
__device__ __nv_bfloat16 g_vhi[MROWS * E_DIM];
__device__ __nv_bfloat16 g_vlo[MROWS * E_DIM];
__device__ __nv_bfloat16 g_mhi[MROWS * E_DIM];
__device__ __nv_bfloat16 g_mlo[MROWS * E_DIM];

// ---------------------------------------------------------------------------
// Helpers
// ---------------------------------------------------------------------------
__device__ __forceinline__ uint32_t smem_to_u32(const void* p) {
    uint32_t a;
    asm("{ .reg .u64 t; cvta.to.shared.u64 t, %1; cvt.u32.u64 %0, t; }"
        : "=r"(a) : "l"(p));
    return a;
}
#define SWZ(o) ((o) ^ (((o) >> 3) & 0x70))

#define LDMATRIX_X4(r0, r1, r2, r3, addr) \
    asm volatile("ldmatrix.sync.aligned.m8n8.x4.shared.b16 {%0,%1,%2,%3}, [%4];" \
                 : "=r"(r0), "=r"(r1), "=r"(r2), "=r"(r3) : "r"(addr))

#define LDMATRIX_X4_T(r0, r1, r2, r3, addr) \
    asm volatile("ldmatrix.sync.aligned.m8n8.x4.trans.shared.b16 {%0,%1,%2,%3}, [%4];" \
                 : "=r"(r0), "=r"(r1), "=r"(r2), "=r"(r3) : "r"(addr))

#define MMA_BF16(d, a, b) \
    asm volatile("mma.sync.aligned.m16n8k16.row.col.f32.bf16.bf16.f32 " \
                 "{%0,%1,%2,%3}, {%4,%5,%6,%7}, {%8,%9}, {%0,%1,%2,%3};" \
                 : "+f"((d)[0]), "+f"((d)[1]), "+f"((d)[2]), "+f"((d)[3]) \
                 : "r"((a)[0]), "r"((a)[1]), "r"((a)[2]), "r"((a)[3]), \
                   "r"((b)[0]), "r"((b)[1]))

#define CP_ASYNC16(s, g) \
    asm volatile("cp.async.cg.shared.global [%0], [%1], 16;" :: "r"(s), "l"(g))
#define CP_COMMIT() asm volatile("cp.async.commit_group;" ::: "memory")
#define CP_WAIT1() asm volatile("cp.async.wait_group 1;" ::: "memory")
#define CP_WAIT0() asm volatile("cp.async.wait_group 0;" ::: "memory")

// pack two floats -> bf16x2 hi word + bf16x2 residual word
__device__ __forceinline__ void pack_hilo(float a, float b, unsigned& h, unsigned& l) {
    asm("cvt.rn.bf16x2.f32 %0, %1, %2;" : "=r"(h) : "f"(b), "f"(a));
    float fa = __uint_as_float(h << 16);
    float fb = __uint_as_float(h & 0xffff0000u);
    asm("cvt.rn.bf16x2.f32 %0, %1, %2;" : "=r"(l) : "f"(b - fb), "f"(a - fa));
}

// ---------------------------------------------------------------------------
// Prep: fp32 -> (hi, lo) bf16 split
// ---------------------------------------------------------------------------
__global__ __launch_bounds__(256) void prep_kernel(const float* __restrict__ src,
                                                   __nv_bfloat16* __restrict__ hi,
                                                   __nv_bfloat16* __restrict__ lo,
                                                   int n4)
{
    int i = blockIdx.x * 256 + threadIdx.x;
    if (i >= n4) return;
    float4 v = ((const float4*)src)[i];
    unsigned h0, l0, h1, l1;
    pack_hilo(v.x, v.y, h0, l0);
    pack_hilo(v.z, v.w, h1, l1);
    ((uint2*)hi)[i] = make_uint2(h0, h1);
    ((uint2*)lo)[i] = make_uint2(l0, l1);
}

// ---------------------------------------------------------------------------
// Pipelined GEMM via mma.sync: C[M,N] = A[M,K]*B[N,K]^T, hi/lo bf16, fp32 acc.
// CTA 128x128, BK=32, 3-stage cp.async pipeline, 256 threads, warp 32m x 64n.
// smem row layout per tile: [hi 32 bf16 (64B) | lo 32 bf16 (64B)] = 128B.
// Stage = A tile 16KB + B tile 16KB = 32KB. 3 stages = 96KB.
// ---------------------------------------------------------------------------
#define GS_A 0
#define GS_B 16384
#define GSTAGE 32768
#define G_SMEM (3 * GSTAGE)
#define NKT (E_DIM / 32)   // 32

template<int OUTMODE>
__device__ __forceinline__ void gemm_mma_body(const __nv_bfloat16* __restrict__ Ahi,
                                              const __nv_bfloat16* __restrict__ Alo,
                                              const __nv_bfloat16* __restrict__ Bhi,
                                              const __nv_bfloat16* __restrict__ Blo,
                                              float* __restrict__ Cf,
                                              __nv_bfloat16* __restrict__ Chi,
                                              __nv_bfloat16* __restrict__ Clo,
                                              float scale)
{
    extern __shared__ __align__(1024) char sm[];
    const uint32_t smb = smem_to_u32(sm);
    const int tid  = threadIdx.x;
    const int w    = tid >> 5;
    const int lane = tid & 31;
    const int bm   = blockIdx.y;
    const int bn   = blockIdx.x;
    const int m0w  = (w & 3) * 32;
    const int n0w  = (w >> 2) * 64;

    float acc[2][8][4];
#pragma unroll
    for (int mt = 0; mt < 2; mt++)
#pragma unroll
        for (int nt = 0; nt < 8; nt++)
#pragma unroll
            for (int j = 0; j < 4; j++) acc[mt][nt][j] = 0.f;

    // loader: 8 chunks/row (c<4: hi, c>=4: lo), 32 row-groups
    const int chunk = tid & 7;
    const int rbase = tid >> 3;          // 0..31
    const bool use_hi = (chunk < 4);
    const int ccol = (chunk & 3) * 8;    // element col within BK=32
    const __nv_bfloat16* Asrc = use_hi ? Ahi : Alo;
    const __nv_bfloat16* Bsrc = use_hi ? Bhi : Blo;
    uint32_t sofs[4];
#pragma unroll
    for (int p = 0; p < 4; p++)
        sofs[p] = SWZ((uint32_t)((rbase + 32 * p) * 128 + chunk * 16));

    auto issue = [&](int kt, int st) {
        const uint32_t sb = smb + (uint32_t)st * GSTAGE;
        const int col = kt * 32 + ccol;
#pragma unroll
        for (int p = 0; p < 4; p++) {
            int r = rbase + 32 * p;
            CP_ASYNC16(sb + GS_A + sofs[p], Asrc + (size_t)(bm * 128 + r) * E_DIM + col);
            CP_ASYNC16(sb + GS_B + sofs[p], Bsrc + (size_t)(bn * 128 + r) * E_DIM + col);
        }
        CP_COMMIT();
    };

    issue(0, 0);
    issue(1, 1);

    const int a_r   = (lane & 7) + ((lane >> 3) & 1) * 8;
    const int a_c16 = lane >> 4;
    const int b_r   = (lane & 7) + ((lane >> 4) & 1) * 8;
    const int b_c16 = (lane >> 3) & 1;

    int st = 0;
    for (int kt = 0; kt < NKT; kt++) {
        if (kt < NKT - 1) CP_WAIT1(); else CP_WAIT0();
        __syncthreads();
        const uint32_t sb = smb + (uint32_t)st * GSTAGE;

        if (kt + 2 < NKT) {
            int st2 = st + 2; if (st2 >= 3) st2 -= 3;
            issue(kt + 2, st2);
        }

#pragma unroll
        for (int ks = 0; ks < 2; ks++) {
            uint32_t afh[2][4], afl[2][4];
#pragma unroll
            for (int mt = 0; mt < 2; mt++) {
                int row = m0w + mt * 16 + a_r;
                uint32_t offh = SWZ((uint32_t)(row * 128 + ks * 32 + a_c16 * 16));
                uint32_t offl = SWZ((uint32_t)(row * 128 + 64 + ks * 32 + a_c16 * 16));
                LDMATRIX_X4(afh[mt][0], afh[mt][1], afh[mt][2], afh[mt][3], sb + GS_A + offh);
                LDMATRIX_X4(afl[mt][0], afl[mt][1], afl[mt][2], afl[mt][3], sb + GS_A + offl);
            }
            uint32_t bfh[8][2], bfl[8][2];
#pragma unroll
            for (int ntp = 0; ntp < 4; ntp++) {
                int nrow = n0w + ntp * 16 + b_r;
                uint32_t offh = SWZ((uint32_t)(nrow * 128 + ks * 32 + b_c16 * 16));
                uint32_t offl = SWZ((uint32_t)(nrow * 128 + 64 + ks * 32 + b_c16 * 16));
                LDMATRIX_X4(bfh[2 * ntp][0], bfh[2 * ntp][1],
                            bfh[2 * ntp + 1][0], bfh[2 * ntp + 1][1], sb + GS_B + offh);
                LDMATRIX_X4(bfl[2 * ntp][0], bfl[2 * ntp][1],
                            bfl[2 * ntp + 1][0], bfl[2 * ntp + 1][1], sb + GS_B + offl);
            }
#pragma unroll
            for (int mt = 0; mt < 2; mt++)
#pragma unroll
                for (int nt = 0; nt < 8; nt++) {
                    MMA_BF16(acc[mt][nt], afh[mt], bfh[nt]);
                    MMA_BF16(acc[mt][nt], afh[mt], bfl[nt]);
                    MMA_BF16(acc[mt][nt], afl[mt], bfh[nt]);
                }
        }
        st++; if (st >= 3) st = 0;
    }

#pragma unroll
    for (int mt = 0; mt < 2; mt++) {
        size_t m = (size_t)(bm * 128 + m0w + mt * 16 + (lane >> 2));
#pragma unroll
        for (int nt = 0; nt < 8; nt++) {
            size_t n = (size_t)(bn * 128 + n0w + nt * 8 + (lane & 3) * 2);
            if (OUTMODE == 0) {
                float* p = Cf + m * E_DIM + n;
                *(float2*)p = make_float2(acc[mt][nt][0], acc[mt][nt][1]);
                *(float2*)(p + (size_t)8 * E_DIM) = make_float2(acc[mt][nt][2], acc[mt][nt][3]);
            } else {
                unsigned hh, ll;
                pack_hilo(acc[mt][nt][0] * scale, acc[mt][nt][1] * scale, hh, ll);
                *(unsigned*)(Chi + m * E_DIM + n) = hh;
                *(unsigned*)(Clo + m * E_DIM + n) = ll;
                pack_hilo(acc[mt][nt][2] * scale, acc[mt][nt][3] * scale, hh, ll);
                *(unsigned*)(Chi + (m + 8) * E_DIM + n) = hh;
                *(unsigned*)(Clo + (m + 8) * E_DIM + n) = ll;
            }
        }
    }
}

__global__ __launch_bounds__(256) void qkv_gemm_mma()
{
    int z = blockIdx.z;
    __nv_bfloat16* Chi = (z == 0) ? g_qhi : (z == 1) ? g_khi : g_vhi;
    __nv_bfloat16* Clo = (z == 0) ? g_qlo : (z == 1) ? g_klo : g_vlo;
    float scale = (z == 0) ? 0.125f : 1.0f;   // fold 1/sqrt(dk) into Q
    gemm_mma_body<1>(g_xhi, g_xlo, g_whi[z], g_wlo[z], nullptr, Chi, Clo, scale);
}

__global__ __launch_bounds__(256) void out_gemm_mma(float* __restrict__ C)
{
    gemm_mma_body<0>(g_mhi, g_mlo, g_whi[3], g_wlo[3], C, nullptr, nullptr, 1.0f);
}

// ---------------------------------------------------------------------------
// Flash attention with mma.sync, hi/lo bf16. Per CTA: 128 q rows of one (b,h).
// 8 warps x 16 q-rows. KV tile 64, 3-stage cp.async pipeline (one sync/iter).
// smem: 3 stages x (Khi,Klo,Vhi,Vlo)[64][64] bf16 = 96KB.
// ---------------------------------------------------------------------------
#define A_KHI 0
#define A_KLO 8192
#define A_VHI 16384
#define A_VLO 24576
#define ASTAGE 32768
#define ATTN_SMEM (3 * ASTAGE)
#define NKV (SEQ / 64)   // 32

__global__ __launch_bounds__(256, 1) void attn_mma(const float* __restrict__ qp)
{
    extern __shared__ __align__(1024) char sm[];
    const uint32_t smb = smem_to_u32(sm);
    const int tid  = threadIdx.x;
    const int wid  = tid >> 5;
    const int lane = tid & 31;
    const int bh   = blockIdx.y;
    const int b    = bh >> 4;
    const int h    = bh & 15;
    const int qbase = blockIdx.x * 128;
    const int wq0   = wid * 16;
    const float cq  = cosf(qp[0] + qp[1]);

    const size_t bS = (size_t)b * SEQ;
    const int h64 = h * 64;

    // ---- cp.async loader geometry ----
    const __nv_bfloat16* khg = g_khi + bS * E_DIM + h64;
    const __nv_bfloat16* klg = g_klo + bS * E_DIM + h64;
    const __nv_bfloat16* vhg = g_vhi + bS * E_DIM + h64;
    const __nv_bfloat16* vlg = g_vlo + bS * E_DIM + h64;
    const int crow0 = tid >> 3;
    const int ccol  = (tid & 7) * 8;
    const uint32_t sco  = SWZ((uint32_t)(crow0 * 128 + (tid & 7) * 16));
    const uint32_t sco2 = SWZ((uint32_t)((crow0 + 32) * 128 + (tid & 7) * 16));

    auto issue_stage = [&](int it, int st) {
        const uint32_t sb = smb + (uint32_t)st * ASTAGE;
        const size_t r0 = (size_t)(it * 64 + crow0) * E_DIM + ccol;
        const size_t r1 = r0 + (size_t)32 * E_DIM;
        CP_ASYNC16(sb + A_KHI + sco,  khg + r0);
        CP_ASYNC16(sb + A_KHI + sco2, khg + r1);
        CP_ASYNC16(sb + A_KLO + sco,  klg + r0);
        CP_ASYNC16(sb + A_KLO + sco2, klg + r1);
        CP_ASYNC16(sb + A_VHI + sco,  vhg + r0);
        CP_ASYNC16(sb + A_VHI + sco2, vhg + r1);
        CP_ASYNC16(sb + A_VLO + sco,  vlg + r0);
        CP_ASYNC16(sb + A_VLO + sco2, vlg + r1);
        CP_COMMIT();
    };

    issue_stage(0, 0);
    issue_stage(1, 1);

    // ---- Q fragments (direct LDG, held for whole loop; overlaps stage 0/1) ----
    unsigned qh[4][4], ql[4][4];
    {
        const size_t base = (bS + qbase + wq0 + (lane >> 2)) * E_DIM + h64 + (lane & 3) * 2;
        const __nv_bfloat16* qhp = g_qhi + base;
        const __nv_bfloat16* qlp = g_qlo + base;
#pragma unroll
        for (int ks = 0; ks < 4; ks++) {
            qh[ks][0] = *(const unsigned*)(qhp + ks * 16);
            qh[ks][1] = *(const unsigned*)(qhp + 8 * E_DIM + ks * 16);
            qh[ks][2] = *(const unsigned*)(qhp + ks * 16 + 8);
            qh[ks][3] = *(const unsigned*)(qhp + 8 * E_DIM + ks * 16 + 8);
            ql[ks][0] = *(const unsigned*)(qlp + ks * 16);
            ql[ks][1] = *(const unsigned*)(qlp + 8 * E_DIM + ks * 16);
            ql[ks][2] = *(const unsigned*)(qlp + ks * 16 + 8);
            ql[ks][3] = *(const unsigned*)(qlp + 8 * E_DIM + ks * 16 + 8);
        }
    }

    float m0 = -1e30f, m1 = -1e30f, l0 = 0.f, l1 = 0.f;
    float oacc[8][4];
#pragma unroll
    for (int nt = 0; nt < 8; nt++)
#pragma unroll
        for (int j = 0; j < 4; j++) oacc[nt][j] = 0.f;

    const int brow = (lane & 7) + ((lane >> 4) & 1) * 8;
    const int bc16 = (lane >> 3) & 1;
    const int vrow = lane & 15;
    const int vcs  = (lane >> 4) * 16;

    int st = 0;
    for (int it = 0; it < NKV; it++) {
        if (it < NKV - 1) CP_WAIT1(); else CP_WAIT0();
        __syncthreads();

        const uint32_t sb = smb + (uint32_t)st * ASTAGE;

        if (it + 2 < NKV) {
            int st2 = st + 2; if (st2 >= 3) st2 -= 3;
            issue_stage(it + 2, st2);
        }

        // ---- S = Q.K^T (hi/lo, 3 passes) ----
        float sacc[8][4];
#pragma unroll
        for (int nt = 0; nt < 8; nt++)
#pragma unroll
            for (int j = 0; j < 4; j++) sacc[nt][j] = 0.f;

#pragma unroll
        for (int ks = 0; ks < 4; ks++) {
            unsigned kh2[8][2], kl2[8][2];
#pragma unroll
            for (int ntp = 0; ntp < 4; ntp++) {
                uint32_t off = SWZ((uint32_t)((ntp * 16 + brow) * 128 + ks * 32 + bc16 * 16));
                LDMATRIX_X4(kh2[2 * ntp][0], kh2[2 * ntp][1],
                            kh2[2 * ntp + 1][0], kh2[2 * ntp + 1][1], sb + A_KHI + off);
                LDMATRIX_X4(kl2[2 * ntp][0], kl2[2 * ntp][1],
                            kl2[2 * ntp + 1][0], kl2[2 * ntp + 1][1], sb + A_KLO + off);
            }
#pragma unroll
            for (int nt = 0; nt < 8; nt++) {
                MMA_BF16(sacc[nt], qh[ks], kh2[nt]);
                MMA_BF16(sacc[nt], qh[ks], kl2[nt]);
                MMA_BF16(sacc[nt], ql[ks], kh2[nt]);
            }
        }

        // ---- online softmax on fragment layout ----
        float mn0 = m0, mn1 = m1;
#pragma unroll
        for (int nt = 0; nt < 8; nt++) {
            mn0 = fmaxf(mn0, fmaxf(sacc[nt][0], sacc[nt][1]));
            mn1 = fmaxf(mn1, fmaxf(sacc[nt][2], sacc[nt][3]));
        }
        mn0 = fmaxf(mn0, __shfl_xor_sync(0xffffffffu, mn0, 1));
        mn0 = fmaxf(mn0, __shfl_xor_sync(0xffffffffu, mn0, 2));
        mn1 = fmaxf(mn1, __shfl_xor_sync(0xffffffffu, mn1, 1));
        mn1 = fmaxf(mn1, __shfl_xor_sync(0xffffffffu, mn1, 2));
        float sc0 = __expf(m0 - mn0);
        float sc1 = __expf(m1 - mn1);
        m0 = mn0; m1 = mn1;
        float rs0 = 0.f, rs1 = 0.f;
#pragma unroll
        for (int nt = 0; nt < 8; nt++) {
            sacc[nt][0] = __expf(sacc[nt][0] - m0); rs0 += sacc[nt][0];
            sacc[nt][1] = __expf(sacc[nt][1] - m0); rs0 += sacc[nt][1];
            sacc[nt][2] = __expf(sacc[nt][2] - m1); rs1 += sacc[nt][2];
            sacc[nt][3] = __expf(sacc[nt][3] - m1); rs1 += sacc[nt][3];
        }
        rs0 += __shfl_xor_sync(0xffffffffu, rs0, 1);
        rs0 += __shfl_xor_sync(0xffffffffu, rs0, 2);
        rs1 += __shfl_xor_sync(0xffffffffu, rs1, 1);
        rs1 += __shfl_xor_sync(0xffffffffu, rs1, 2);
        l0 = l0 * sc0 + rs0;
        l1 = l1 * sc1 + rs1;
#pragma unroll
        for (int nt = 0; nt < 8; nt++) {
            oacc[nt][0] *= sc0; oacc[nt][1] *= sc0;
            oacc[nt][2] *= sc1; oacc[nt][3] *= sc1;
        }

        // ---- O += P.V (P from registers; V via ldmatrix.trans; 3 passes) ----
#pragma unroll
        for (int j = 0; j < 4; j++) {
            unsigned ph[4], pl[4];
            pack_hilo(sacc[2 * j][0],     sacc[2 * j][1],     ph[0], pl[0]);
            pack_hilo(sacc[2 * j][2],     sacc[2 * j][3],     ph[1], pl[1]);
            pack_hilo(sacc[2 * j + 1][0], sacc[2 * j + 1][1], ph[2], pl[2]);
            pack_hilo(sacc[2 * j + 1][2], sacc[2 * j + 1][3], ph[3], pl[3]);
            unsigned vh2[8][2], vl2[8][2];
#pragma unroll
            for (int dp = 0; dp < 4; dp++) {
                uint32_t off = SWZ((uint32_t)((j * 16 + vrow) * 128 + dp * 32 + vcs));
                LDMATRIX_X4_T(vh2[2 * dp][0], vh2[2 * dp][1],
                              vh2[2 * dp + 1][0], vh2[2 * dp + 1][1], sb + A_VHI + off);
                LDMATRIX_X4_T(vl2[2 * dp][0], vl2[2 * dp][1],
                              vl2[2 * dp + 1][0], vl2[2 * dp + 1][1], sb + A_VLO + off);
            }
#pragma unroll
            for (int nt = 0; nt < 8; nt++) {
                MMA_BF16(oacc[nt], ph, vh2[nt]);
                MMA_BF16(oacc[nt], ph, vl2[nt]);
                MMA_BF16(oacc[nt], pl, vh2[nt]);
            }
        }

        st++; if (st >= 3) st = 0;
    }

    // ---- epilogue: normalize, +c on dk<4, write hi/lo bf16 mix ----
    const float inv0 = 1.f / l0;
    const float inv1 = 1.f / l1;
    const size_t row0 = (bS + qbase + wq0 + (lane >> 2)) * E_DIM + h64 + (lane & 3) * 2;
    const size_t row1 = row0 + 8 * E_DIM;
    const bool adds = ((lane & 3) < 2);
#pragma unroll
    for (int nt = 0; nt < 8; nt++) {
        const float add = (nt == 0 && adds) ? cq : 0.f;
        float v0 = oacc[nt][0] * inv0 + add;
        float v1 = oacc[nt][1] * inv0 + add;
        float v2 = oacc[nt][2] * inv1 + add;
        float v3 = oacc[nt][3] * inv1 + add;
        unsigned hh, ll;
        pack_hilo(v0, v1, hh, ll);
        *(unsigned*)(g_mhi + row0 + nt * 8) = hh;
        *(unsigned*)(g_mlo + row0 + nt * 8) = ll;
        pack_hilo(v2, v3, hh, ll);
        *(unsigned*)(g_mhi + row1 + nt * 8) = hh;
        *(unsigned*)(g_mlo + row1 + nt * 8) = ll;
    }
}

// ---------------------------------------------------------------------------
extern "C" void kernel_launch(void* const* d_in, const int* in_sizes, int n_in,
                              void* d_out, int out_size)
{
    const float* x  = (const float*)d_in[0];
    const float* Wq = (const float*)d_in[1];
    const float* Wk = (const float*)d_in[2];
    const float* Wv = (const float*)d_in[3];
    const float* Wo = (const float*)d_in[4];
    const float* qp = (const float*)d_in[5];
    float* out = (float*)d_out;

    cudaFuncSetAttribute(qkv_gemm_mma, cudaFuncAttributeMaxDynamicSharedMemorySize, G_SMEM);
    cudaFuncSetAttribute(out_gemm_mma, cudaFuncAttributeMaxDynamicSharedMemorySize, G_SMEM);
    cudaFuncSetAttribute(attn_mma,     cudaFuncAttributeMaxDynamicSharedMemorySize, ATTN_SMEM);

    __nv_bfloat16 *xhi, *xlo, *whi, *wlo;
    cudaGetSymbolAddress((void**)&xhi, g_xhi);
    cudaGetSymbolAddress((void**)&xlo, g_xlo);
    cudaGetSymbolAddress((void**)&whi, g_whi);
    cudaGetSymbolAddress((void**)&wlo, g_wlo);

    const int NW = E_DIM * E_DIM;
    prep_kernel<<<(MROWS * E_DIM / 4 + 255) / 256, 256>>>(x, xhi, xlo, MROWS * E_DIM / 4);
    prep_kernel<<<(NW / 4 + 255) / 256, 256>>>(Wq, whi + 0 * (size_t)NW, wlo + 0 * (size_t)NW, NW / 4);
    prep_kernel<<<(NW / 4 + 255) / 256, 256>>>(Wk, whi + 1 * (size_t)NW, wlo + 1 * (size_t)NW, NW / 4);
    prep_kernel<<<(NW / 4 + 255) / 256, 256>>>(Wv, whi + 2 * (size_t)NW, wlo + 2 * (size_t)NW, NW / 4);
    prep_kernel<<<(NW / 4 + 255) / 256, 256>>>(Wo, whi + 3 * (size_t)NW, wlo + 3 * (size_t)NW, NW / 4);

    qkv_gemm_mma<<<dim3(8, 32, 3), 256, G_SMEM>>>();
    attn_mma<<<dim3(SEQ / 128, BATCH * NHEAD), 256, ATTN_SMEM>>>(qp);
    out_gemm_mma<<<dim3(8, 32), 256, G_SMEM>>>(out);
}

// round 6
// speedup vs baseline: 3.6251x; 1.1361x over previous
#include <cuda_runtime.h>
#include <cuda_bf16.h>
#include <math.h>
#include <cstdint>

#define E_DIM 1024
#define SEQ   2048
#define BATCH 2
#define NHEAD 16
#define DK    64
#define MROWS (BATCH * SEQ)   // 4096

// ---------------------------------------------------------------------------
// Scratch (device globals; no allocations allowed)
// ---------------------------------------------------------------------------
__device__ __nv_bfloat16 g_xhi[MROWS * E_DIM];
__device__ __nv_bfloat16 g_xlo[MROWS * E_DIM];
__device__ __nv_bfloat16 g_whi[4][E_DIM * E_DIM];   // q,k,v,o
__device__ __nv_bfloat16 g_wlo[4][E_DIM * E_DIM];
__device__ __nv_bfloat16 g_qhi[MROWS * E_DIM];
__device__ __nv_bfloat16 g_qlo[MROWS * E_DIM];
__device__ __nv_bfloat16 g_khi[MROWS * E_DIM];
__device__ __nv_bfloat16 g_klo[MROWS * E_DIM];
__device__ __nv_bfloat16 g_vhi[MROWS * E_DIM];
__device__ __nv_bfloat16 g_vlo[MROWS * E_DIM];
__device__ __nv_bfloat16 g_mhi[MROWS * E_DIM];
__device__ __nv_bfloat16 g_mlo[MROWS * E_DIM];

// ---------------------------------------------------------------------------
// Helpers
// ---------------------------------------------------------------------------
__device__ __forceinline__ uint32_t smem_to_u32(const void* p) {
    uint32_t a;
    asm("{ .reg .u64 t; cvta.to.shared.u64 t, %1; cvt.u32.u64 %0, t; }"
        : "=r"(a) : "l"(p));
    return a;
}
#define SWZ(o) ((o) ^ (((o) >> 3) & 0x70))

#define LDMATRIX_X4(r0, r1, r2, r3, addr) \
    asm volatile("ldmatrix.sync.aligned.m8n8.x4.shared.b16 {%0,%1,%2,%3}, [%4];" \
                 : "=r"(r0), "=r"(r1), "=r"(r2), "=r"(r3) : "r"(addr))

#define LDMATRIX_X4_T(r0, r1, r2, r3, addr) \
    asm volatile("ldmatrix.sync.aligned.m8n8.x4.trans.shared.b16 {%0,%1,%2,%3}, [%4];" \
                 : "=r"(r0), "=r"(r1), "=r"(r2), "=r"(r3) : "r"(addr))

#define MMA_BF16(d, a, b) \
    asm volatile("mma.sync.aligned.m16n8k16.row.col.f32.bf16.bf16.f32 " \
                 "{%0,%1,%2,%3}, {%4,%5,%6,%7}, {%8,%9}, {%0,%1,%2,%3};" \
                 : "+f"((d)[0]), "+f"((d)[1]), "+f"((d)[2]), "+f"((d)[3]) \
                 : "r"((a)[0]), "r"((a)[1]), "r"((a)[2]), "r"((a)[3]), \
                   "r"((b)[0]), "r"((b)[1]))

#define CP_ASYNC16(s, g) \
    asm volatile("cp.async.cg.shared.global [%0], [%1], 16;" :: "r"(s), "l"(g))
#define CP_COMMIT() asm volatile("cp.async.commit_group;" ::: "memory")
#define CP_WAIT1() asm volatile("cp.async.wait_group 1;" ::: "memory")
#define CP_WAIT0() asm volatile("cp.async.wait_group 0;" ::: "memory")

// pack two floats -> bf16x2 hi word + bf16x2 residual word
__device__ __forceinline__ void pack_hilo(float a, float b, unsigned& h, unsigned& l) {
    asm("cvt.rn.bf16x2.f32 %0, %1, %2;" : "=r"(h) : "f"(b), "f"(a));
    float fa = __uint_as_float(h << 16);
    float fb = __uint_as_float(h & 0xffff0000u);
    asm("cvt.rn.bf16x2.f32 %0, %1, %2;" : "=r"(l) : "f"(b - fb), "f"(a - fa));
}

// ---------------------------------------------------------------------------
// Prep: fp32 -> (hi, lo) bf16 split
// ---------------------------------------------------------------------------
__global__ __launch_bounds__(256) void prep_kernel(const float* __restrict__ src,
                                                   __nv_bfloat16* __restrict__ hi,
                                                   __nv_bfloat16* __restrict__ lo,
                                                   int n4)
{
    int i = blockIdx.x * 256 + threadIdx.x;
    if (i >= n4) return;
    float4 v = ((const float4*)src)[i];
    unsigned h0, l0, h1, l1;
    pack_hilo(v.x, v.y, h0, l0);
    pack_hilo(v.z, v.w, h1, l1);
    ((uint2*)hi)[i] = make_uint2(h0, h1);
    ((uint2*)lo)[i] = make_uint2(l0, l1);
}

// ---------------------------------------------------------------------------
// Pipelined GEMM: C[M,N] = A[M,K]*B[N,K]^T, hi/lo bf16, fp32 acc.
// CTA 256x128, BK=32, warp 64m x 64n, 3-stage cp.async pipeline, 256 threads.
// smem row: [hi 32 bf16 | lo 32 bf16] = 128B. Stage = A 32KB + B 16KB = 48KB.
// ---------------------------------------------------------------------------
#define GS_A 0
#define GS_B 32768
#define GSTAGE 49152
#define G_SMEM (3 * GSTAGE)
#define NKT (E_DIM / 32)   // 32

template<int OUTMODE>
__device__ __forceinline__ void gemm_mma_body(const __nv_bfloat16* __restrict__ Ahi,
                                              const __nv_bfloat16* __restrict__ Alo,
                                              const __nv_bfloat16* __restrict__ Bhi,
                                              const __nv_bfloat16* __restrict__ Blo,
                                              float* __restrict__ Cf,
                                              __nv_bfloat16* __restrict__ Chi,
                                              __nv_bfloat16* __restrict__ Clo,
                                              float scale)
{
    extern __shared__ __align__(1024) char sm[];
    const uint32_t smb = smem_to_u32(sm);
    const int tid  = threadIdx.x;
    const int w    = tid >> 5;
    const int lane = tid & 31;
    const int bm   = blockIdx.y;
    const int bn   = blockIdx.x;
    const int m0w  = (w & 3) * 64;
    const int n0w  = (w >> 2) * 64;

    float acc[4][8][4];
#pragma unroll
    for (int mt = 0; mt < 4; mt++)
#pragma unroll
        for (int nt = 0; nt < 8; nt++)
#pragma unroll
            for (int j = 0; j < 4; j++) acc[mt][nt][j] = 0.f;

    // loader: 8 chunks/row (c<4: hi, c>=4: lo)
    const int chunk = tid & 7;
    const int rbase = tid >> 3;          // 0..31
    const bool use_hi = (chunk < 4);
    const int ccol = (chunk & 3) * 8;
    const __nv_bfloat16* Asrc = use_hi ? Ahi : Alo;
    const __nv_bfloat16* Bsrc = use_hi ? Bhi : Blo;
    uint32_t sofs[8];
#pragma unroll
    for (int p = 0; p < 8; p++)
        sofs[p] = SWZ((uint32_t)((rbase + 32 * p) * 128 + chunk * 16));

    auto issue = [&](int kt, int st) {
        const uint32_t sb = smb + (uint32_t)st * GSTAGE;
        const int col = kt * 32 + ccol;
#pragma unroll
        for (int p = 0; p < 8; p++)
            CP_ASYNC16(sb + GS_A + sofs[p],
                       Asrc + (size_t)(bm * 256 + rbase + 32 * p) * E_DIM + col);
#pragma unroll
        for (int p = 0; p < 4; p++)
            CP_ASYNC16(sb + GS_B + sofs[p],
                       Bsrc + (size_t)(bn * 128 + rbase + 32 * p) * E_DIM + col);
        CP_COMMIT();
    };

    issue(0, 0);
    issue(1, 1);

    const int a_r   = (lane & 7) + ((lane >> 3) & 1) * 8;
    const int a_c16 = lane >> 4;
    const int b_r   = (lane & 7) + ((lane >> 4) & 1) * 8;
    const int b_c16 = (lane >> 3) & 1;

    int st = 0;
    for (int kt = 0; kt < NKT; kt++) {
        if (kt < NKT - 1) CP_WAIT1(); else CP_WAIT0();
        __syncthreads();
        const uint32_t sb = smb + (uint32_t)st * GSTAGE;

        if (kt + 2 < NKT) {
            int st2 = st + 2; if (st2 >= 3) st2 -= 3;
            issue(kt + 2, st2);
        }

#pragma unroll
        for (int ks = 0; ks < 2; ks++) {
            uint32_t afh[4][4], afl[4][4];
#pragma unroll
            for (int mt = 0; mt < 4; mt++) {
                int row = m0w + mt * 16 + a_r;
                uint32_t offh = SWZ((uint32_t)(row * 128 + ks * 32 + a_c16 * 16));
                uint32_t offl = SWZ((uint32_t)(row * 128 + 64 + ks * 32 + a_c16 * 16));
                LDMATRIX_X4(afh[mt][0], afh[mt][1], afh[mt][2], afh[mt][3], sb + GS_A + offh);
                LDMATRIX_X4(afl[mt][0], afl[mt][1], afl[mt][2], afl[mt][3], sb + GS_A + offl);
            }
            uint32_t bfh[8][2], bfl[8][2];
#pragma unroll
            for (int ntp = 0; ntp < 4; ntp++) {
                int nrow = n0w + ntp * 16 + b_r;
                uint32_t offh = SWZ((uint32_t)(nrow * 128 + ks * 32 + b_c16 * 16));
                uint32_t offl = SWZ((uint32_t)(nrow * 128 + 64 + ks * 32 + b_c16 * 16));
                LDMATRIX_X4(bfh[2 * ntp][0], bfh[2 * ntp][1],
                            bfh[2 * ntp + 1][0], bfh[2 * ntp + 1][1], sb + GS_B + offh);
                LDMATRIX_X4(bfl[2 * ntp][0], bfl[2 * ntp][1],
                            bfl[2 * ntp + 1][0], bfl[2 * ntp + 1][1], sb + GS_B + offl);
            }
#pragma unroll
            for (int mt = 0; mt < 4; mt++)
#pragma unroll
                for (int nt = 0; nt < 8; nt++) {
                    MMA_BF16(acc[mt][nt], afh[mt], bfh[nt]);
                    MMA_BF16(acc[mt][nt], afh[mt], bfl[nt]);
                    MMA_BF16(acc[mt][nt], afl[mt], bfh[nt]);
                }
        }
        st++; if (st >= 3) st = 0;
    }

#pragma unroll
    for (int mt = 0; mt < 4; mt++) {
        size_t m = (size_t)(bm * 256 + m0w + mt * 16 + (lane >> 2));
#pragma unroll
        for (int nt = 0; nt < 8; nt++) {
            size_t n = (size_t)(bn * 128 + n0w + nt * 8 + (lane & 3) * 2);
            if (OUTMODE == 0) {
                float* p = Cf + m * E_DIM + n;
                *(float2*)p = make_float2(acc[mt][nt][0], acc[mt][nt][1]);
                *(float2*)(p + (size_t)8 * E_DIM) = make_float2(acc[mt][nt][2], acc[mt][nt][3]);
            } else {
                unsigned hh, ll;
                pack_hilo(acc[mt][nt][0] * scale, acc[mt][nt][1] * scale, hh, ll);
                *(unsigned*)(Chi + m * E_DIM + n) = hh;
                *(unsigned*)(Clo + m * E_DIM + n) = ll;
                pack_hilo(acc[mt][nt][2] * scale, acc[mt][nt][3] * scale, hh, ll);
                *(unsigned*)(Chi + (m + 8) * E_DIM + n) = hh;
                *(unsigned*)(Clo + (m + 8) * E_DIM + n) = ll;
            }
        }
    }
}

__global__ __launch_bounds__(256, 1) void qkv_gemm_mma()
{
    int z = blockIdx.z;
    __nv_bfloat16* Chi = (z == 0) ? g_qhi : (z == 1) ? g_khi : g_vhi;
    __nv_bfloat16* Clo = (z == 0) ? g_qlo : (z == 1) ? g_klo : g_vlo;
    float scale = (z == 0) ? 0.125f : 1.0f;   // fold 1/sqrt(dk) into Q
    gemm_mma_body<1>(g_xhi, g_xlo, g_whi[z], g_wlo[z], nullptr, Chi, Clo, scale);
}

__global__ __launch_bounds__(256, 1) void out_gemm_mma(float* __restrict__ C)
{
    gemm_mma_body<0>(g_mhi, g_mlo, g_whi[3], g_wlo[3], C, nullptr, nullptr, 1.0f);
}

// ---------------------------------------------------------------------------
// Flash attention, mma.sync hi/lo bf16. Per CTA: 256 q rows of one (b,h).
// 8 warps x 32 q-rows (2 m16 tiles). KV tile 64, 3-stage cp.async pipeline.
// Q staged in smem (re-ldmatrix'ed per ks). smem = 64KB Q + 3x32KB = 160KB.
// ---------------------------------------------------------------------------
#define AQ_HI 0
#define AQ_LO 32768
#define AST0  65536
#define A_KHI 0
#define A_KLO 8192
#define A_VHI 16384
#define A_VLO 24576
#define ASTAGE 32768
#define ATTN_SMEM (AST0 + 3 * ASTAGE)
#define NKV (SEQ / 64)   // 32
#define QBLK 256

__global__ __launch_bounds__(256, 1) void attn_mma(const float* __restrict__ qp)
{
    extern __shared__ __align__(1024) char sm[];
    const uint32_t smb = smem_to_u32(sm);
    const int tid  = threadIdx.x;
    const int wid  = tid >> 5;
    const int lane = tid & 31;
    const int bh   = blockIdx.y;
    const int b    = bh >> 4;
    const int h    = bh & 15;
    const int qbase = blockIdx.x * QBLK;
    const int wq0   = wid * 32;
    const float cq  = cosf(qp[0] + qp[1]);

    const size_t bS = (size_t)b * SEQ;
    const int h64 = h * 64;

    // ---- cp.async loader geometry (K/V) ----
    const __nv_bfloat16* khg = g_khi + bS * E_DIM + h64;
    const __nv_bfloat16* klg = g_klo + bS * E_DIM + h64;
    const __nv_bfloat16* vhg = g_vhi + bS * E_DIM + h64;
    const __nv_bfloat16* vlg = g_vlo + bS * E_DIM + h64;
    const int crow0 = tid >> 3;
    const int ccol  = (tid & 7) * 8;
    const uint32_t sco  = SWZ((uint32_t)(crow0 * 128 + (tid & 7) * 16));
    const uint32_t sco2 = SWZ((uint32_t)((crow0 + 32) * 128 + (tid & 7) * 16));

    auto issue_stage = [&](int it, int st) {
        const uint32_t sb = smb + AST0 + (uint32_t)st * ASTAGE;
        const size_t r0 = (size_t)(it * 64 + crow0) * E_DIM + ccol;
        const size_t r1 = r0 + (size_t)32 * E_DIM;
        CP_ASYNC16(sb + A_KHI + sco,  khg + r0);
        CP_ASYNC16(sb + A_KHI + sco2, khg + r1);
        CP_ASYNC16(sb + A_KLO + sco,  klg + r0);
        CP_ASYNC16(sb + A_KLO + sco2, klg + r1);
        CP_ASYNC16(sb + A_VHI + sco,  vhg + r0);
        CP_ASYNC16(sb + A_VHI + sco2, vhg + r1);
        CP_ASYNC16(sb + A_VLO + sco,  vlg + r0);
        CP_ASYNC16(sb + A_VLO + sco2, vlg + r1);
        CP_COMMIT();
    };

    issue_stage(0, 0);
    issue_stage(1, 1);

    // ---- stage Q (hi/lo) into smem: 256 rows x 128B each ----
    {
        const __nv_bfloat16* qhg = g_qhi + (bS + qbase) * E_DIM + h64;
        const __nv_bfloat16* qlg = g_qlo + (bS + qbase) * E_DIM + h64;
#pragma unroll
        for (int p = 0; p < 8; p++) {
            int r = crow0 + 32 * p;
            uint32_t so = SWZ((uint32_t)(r * 128 + (tid & 7) * 16));
            *(uint4*)(sm + AQ_HI + so) = *(const uint4*)(qhg + (size_t)r * E_DIM + ccol);
            *(uint4*)(sm + AQ_LO + so) = *(const uint4*)(qlg + (size_t)r * E_DIM + ccol);
        }
    }

    float mx[2][2], lsum[2][2];
    float oacc[2][8][4];
#pragma unroll
    for (int mt = 0; mt < 2; mt++) {
        mx[mt][0] = -1e30f; mx[mt][1] = -1e30f;
        lsum[mt][0] = 0.f;  lsum[mt][1] = 0.f;
#pragma unroll
        for (int nt = 0; nt < 8; nt++)
#pragma unroll
            for (int j = 0; j < 4; j++) oacc[mt][nt][j] = 0.f;
    }

    const int a_r   = (lane & 7) + ((lane >> 3) & 1) * 8;
    const int a_c16 = lane >> 4;
    const int brow  = (lane & 7) + ((lane >> 4) & 1) * 8;
    const int bc16  = (lane >> 3) & 1;
    const int vrow  = lane & 15;
    const int vcs   = (lane >> 4) * 16;

    int st = 0;
    for (int it = 0; it < NKV; it++) {
        if (it < NKV - 1) CP_WAIT1(); else CP_WAIT0();
        __syncthreads();

        const uint32_t sb = smb + AST0 + (uint32_t)st * ASTAGE;

        if (it + 2 < NKV) {
            int st2 = st + 2; if (st2 >= 3) st2 -= 3;
            issue_stage(it + 2, st2);
        }

        // ---- S = Q.K^T (hi/lo, 3 passes), 2 m-tiles ----
        float sacc[2][8][4];
#pragma unroll
        for (int mt = 0; mt < 2; mt++)
#pragma unroll
            for (int nt = 0; nt < 8; nt++)
#pragma unroll
                for (int j = 0; j < 4; j++) sacc[mt][nt][j] = 0.f;

#pragma unroll
        for (int ks = 0; ks < 4; ks++) {
            unsigned kh2[8][2], kl2[8][2];
#pragma unroll
            for (int ntp = 0; ntp < 4; ntp++) {
                uint32_t off = SWZ((uint32_t)((ntp * 16 + brow) * 128 + ks * 32 + bc16 * 16));
                LDMATRIX_X4(kh2[2 * ntp][0], kh2[2 * ntp][1],
                            kh2[2 * ntp + 1][0], kh2[2 * ntp + 1][1], sb + A_KHI + off);
                LDMATRIX_X4(kl2[2 * ntp][0], kl2[2 * ntp][1],
                            kl2[2 * ntp + 1][0], kl2[2 * ntp + 1][1], sb + A_KLO + off);
            }
#pragma unroll
            for (int mt = 0; mt < 2; mt++) {
                unsigned qfh[4], qfl[4];
                uint32_t qoff = SWZ((uint32_t)((wq0 + mt * 16 + a_r) * 128 + ks * 32 + a_c16 * 16));
                LDMATRIX_X4(qfh[0], qfh[1], qfh[2], qfh[3], smb + AQ_HI + qoff);
                LDMATRIX_X4(qfl[0], qfl[1], qfl[2], qfl[3], smb + AQ_LO + qoff);
#pragma unroll
                for (int nt = 0; nt < 8; nt++) {
                    MMA_BF16(sacc[mt][nt], qfh, kh2[nt]);
                    MMA_BF16(sacc[mt][nt], qfh, kl2[nt]);
                    MMA_BF16(sacc[mt][nt], qfl, kh2[nt]);
                }
            }
        }

        // ---- online softmax per m-tile ----
#pragma unroll
        for (int mt = 0; mt < 2; mt++) {
            float mn0 = mx[mt][0], mn1 = mx[mt][1];
#pragma unroll
            for (int nt = 0; nt < 8; nt++) {
                mn0 = fmaxf(mn0, fmaxf(sacc[mt][nt][0], sacc[mt][nt][1]));
                mn1 = fmaxf(mn1, fmaxf(sacc[mt][nt][2], sacc[mt][nt][3]));
            }
            mn0 = fmaxf(mn0, __shfl_xor_sync(0xffffffffu, mn0, 1));
            mn0 = fmaxf(mn0, __shfl_xor_sync(0xffffffffu, mn0, 2));
            mn1 = fmaxf(mn1, __shfl_xor_sync(0xffffffffu, mn1, 1));
            mn1 = fmaxf(mn1, __shfl_xor_sync(0xffffffffu, mn1, 2));
            float sc0 = __expf(mx[mt][0] - mn0);
            float sc1 = __expf(mx[mt][1] - mn1);
            mx[mt][0] = mn0; mx[mt][1] = mn1;
            float rs0 = 0.f, rs1 = 0.f;
#pragma unroll
            for (int nt = 0; nt < 8; nt++) {
                sacc[mt][nt][0] = __expf(sacc[mt][nt][0] - mn0); rs0 += sacc[mt][nt][0];
                sacc[mt][nt][1] = __expf(sacc[mt][nt][1] - mn0); rs0 += sacc[mt][nt][1];
                sacc[mt][nt][2] = __expf(sacc[mt][nt][2] - mn1); rs1 += sacc[mt][nt][2];
                sacc[mt][nt][3] = __expf(sacc[mt][nt][3] - mn1); rs1 += sacc[mt][nt][3];
            }
            rs0 += __shfl_xor_sync(0xffffffffu, rs0, 1);
            rs0 += __shfl_xor_sync(0xffffffffu, rs0, 2);
            rs1 += __shfl_xor_sync(0xffffffffu, rs1, 1);
            rs1 += __shfl_xor_sync(0xffffffffu, rs1, 2);
            lsum[mt][0] = lsum[mt][0] * sc0 + rs0;
            lsum[mt][1] = lsum[mt][1] * sc1 + rs1;
#pragma unroll
            for (int nt = 0; nt < 8; nt++) {
                oacc[mt][nt][0] *= sc0; oacc[mt][nt][1] *= sc0;
                oacc[mt][nt][2] *= sc1; oacc[mt][nt][3] *= sc1;
            }
        }

        // ---- O += P.V: V frags shared across both m-tiles ----
#pragma unroll
        for (int j = 0; j < 4; j++) {
            unsigned vh2[8][2], vl2[8][2];
#pragma unroll
            for (int dp = 0; dp < 4; dp++) {
                uint32_t off = SWZ((uint32_t)((j * 16 + vrow) * 128 + dp * 32 + vcs));
                LDMATRIX_X4_T(vh2[2 * dp][0], vh2[2 * dp][1],
                              vh2[2 * dp + 1][0], vh2[2 * dp + 1][1], sb + A_VHI + off);
                LDMATRIX_X4_T(vl2[2 * dp][0], vl2[2 * dp][1],
                              vl2[2 * dp + 1][0], vl2[2 * dp + 1][1], sb + A_VLO + off);
            }
#pragma unroll
            for (int mt = 0; mt < 2; mt++) {
                unsigned ph[4], pl[4];
                pack_hilo(sacc[mt][2 * j][0],     sacc[mt][2 * j][1],     ph[0], pl[0]);
                pack_hilo(sacc[mt][2 * j][2],     sacc[mt][2 * j][3],     ph[1], pl[1]);
                pack_hilo(sacc[mt][2 * j + 1][0], sacc[mt][2 * j + 1][1], ph[2], pl[2]);
                pack_hilo(sacc[mt][2 * j + 1][2], sacc[mt][2 * j + 1][3], ph[3], pl[3]);
#pragma unroll
                for (int nt = 0; nt < 8; nt++) {
                    MMA_BF16(oacc[mt][nt], ph, vh2[nt]);
                    MMA_BF16(oacc[mt][nt], ph, vl2[nt]);
                    MMA_BF16(oacc[mt][nt], pl, vh2[nt]);
                }
            }
        }

        st++; if (st >= 3) st = 0;
    }

    // ---- epilogue: normalize, +c on dk<4, write hi/lo bf16 mix ----
    const bool adds = ((lane & 3) < 2);
#pragma unroll
    for (int mt = 0; mt < 2; mt++) {
        const float inv0 = 1.f / lsum[mt][0];
        const float inv1 = 1.f / lsum[mt][1];
        const size_t row0 = (bS + qbase + wq0 + mt * 16 + (lane >> 2)) * E_DIM
                            + h64 + (lane & 3) * 2;
        const size_t row1 = row0 + 8 * E_DIM;
#pragma unroll
        for (int nt = 0; nt < 8; nt++) {
            const float add = (nt == 0 && adds) ? cq : 0.f;
            float v0 = oacc[mt][nt][0] * inv0 + add;
            float v1 = oacc[mt][nt][1] * inv0 + add;
            float v2 = oacc[mt][nt][2] * inv1 + add;
            float v3 = oacc[mt][nt][3] * inv1 + add;
            unsigned hh, ll;
            pack_hilo(v0, v1, hh, ll);
            *(unsigned*)(g_mhi + row0 + nt * 8) = hh;
            *(unsigned*)(g_mlo + row0 + nt * 8) = ll;
            pack_hilo(v2, v3, hh, ll);
            *(unsigned*)(g_mhi + row1 + nt * 8) = hh;
            *(unsigned*)(g_mlo + row1 + nt * 8) = ll;
        }
    }
}

// ---------------------------------------------------------------------------
extern "C" void kernel_launch(void* const* d_in, const int* in_sizes, int n_in,
                              void* d_out, int out_size)
{
    const float* x  = (const float*)d_in[0];
    const float* Wq = (const float*)d_in[1];
    const float* Wk = (const float*)d_in[2];
    const float* Wv = (const float*)d_in[3];
    const float* Wo = (const float*)d_in[4];
    const float* qp = (const float*)d_in[5];
    float* out = (float*)d_out;

    cudaFuncSetAttribute(qkv_gemm_mma, cudaFuncAttributeMaxDynamicSharedMemorySize, G_SMEM);
    cudaFuncSetAttribute(out_gemm_mma, cudaFuncAttributeMaxDynamicSharedMemorySize, G_SMEM);
    cudaFuncSetAttribute(attn_mma,     cudaFuncAttributeMaxDynamicSharedMemorySize, ATTN_SMEM);

    __nv_bfloat16 *xhi, *xlo, *whi, *wlo;
    cudaGetSymbolAddress((void**)&xhi, g_xhi);
    cudaGetSymbolAddress((void**)&xlo, g_xlo);
    cudaGetSymbolAddress((void**)&whi, g_whi);
    cudaGetSymbolAddress((void**)&wlo, g_wlo);

    const int NW = E_DIM * E_DIM;
    prep_kernel<<<(MROWS * E_DIM / 4 + 255) / 256, 256>>>(x, xhi, xlo, MROWS * E_DIM / 4);
    prep_kernel<<<(NW / 4 + 255) / 256, 256>>>(Wq, whi + 0 * (size_t)NW, wlo + 0 * (size_t)NW, NW / 4);
    prep_kernel<<<(NW / 4 + 255) / 256, 256>>>(Wk, whi + 1 * (size_t)NW, wlo + 1 * (size_t)NW, NW / 4);
    prep_kernel<<<(NW / 4 + 255) / 256, 256>>>(Wv, whi + 2 * (size_t)NW, wlo + 2 * (size_t)NW, NW / 4);
    prep_kernel<<<(NW / 4 + 255) / 256, 256>>>(Wo, whi + 3 * (size_t)NW, wlo + 3 * (size_t)NW, NW / 4);

    qkv_gemm_mma<<<dim3(8, 16, 3), 256, G_SMEM>>>();
    attn_mma<<<dim3(SEQ / QBLK, BATCH * NHEAD), 256, ATTN_SMEM>>>(qp);
    out_gemm_mma<<<dim3(8, 16), 256, G_SMEM>>>(out);
}

// round 7
// speedup vs baseline: 4.1312x; 1.1396x over previous
#include <cuda_runtime.h>
#include <cuda_bf16.h>
#include <cuda_fp16.h>
#include <math.h>
#include <cstdint>

#define E_DIM 1024
#define SEQ   2048
#define BATCH 2
#define NHEAD 16
#define DK    64
#define MROWS (BATCH * SEQ)   // 4096

// ---------------------------------------------------------------------------
// Scratch (device globals; no allocations allowed)
// ---------------------------------------------------------------------------
__device__ __nv_bfloat16 g_xhi[MROWS * E_DIM];
__device__ __nv_bfloat16 g_xlo[MROWS * E_DIM];
__device__ __nv_bfloat16 g_whi[4][E_DIM * E_DIM];   // q,k,v,o
__device__ __nv_bfloat16 g_wlo[4][E_DIM * E_DIM];
__device__ __nv_bfloat16 g_qhi[MROWS * E_DIM];      // bf16 hi/lo
__device__ __nv_bfloat16 g_qlo[MROWS * E_DIM];
__device__ __nv_bfloat16 g_khi[MROWS * E_DIM];      // bf16 hi/lo
__device__ __nv_bfloat16 g_klo[MROWS * E_DIM];
__device__ __nv_bfloat16 g_vhi[MROWS * E_DIM];      // fp16 hi/lo (bits)
__device__ __nv_bfloat16 g_vlo[MROWS * E_DIM];
__device__ __nv_bfloat16 g_mhi[MROWS * E_DIM];
__device__ __nv_bfloat16 g_mlo[MROWS * E_DIM];

// ---------------------------------------------------------------------------
// Helpers
// ---------------------------------------------------------------------------
__device__ __forceinline__ uint32_t smem_to_u32(const void* p) {
    uint32_t a;
    asm("{ .reg .u64 t; cvta.to.shared.u64 t, %1; cvt.u32.u64 %0, t; }"
        : "=r"(a) : "l"(p));
    return a;
}
#define SWZ(o) ((o) ^ (((o) >> 3) & 0x70))

#define LDMATRIX_X4(r0, r1, r2, r3, addr) \
    asm volatile("ldmatrix.sync.aligned.m8n8.x4.shared.b16 {%0,%1,%2,%3}, [%4];" \
                 : "=r"(r0), "=r"(r1), "=r"(r2), "=r"(r3) : "r"(addr))

#define LDMATRIX_X4_T(r0, r1, r2, r3, addr) \
    asm volatile("ldmatrix.sync.aligned.m8n8.x4.trans.shared.b16 {%0,%1,%2,%3}, [%4];" \
                 : "=r"(r0), "=r"(r1), "=r"(r2), "=r"(r3) : "r"(addr))

#define MMA_BF16(d, a, b) \
    asm volatile("mma.sync.aligned.m16n8k16.row.col.f32.bf16.bf16.f32 " \
                 "{%0,%1,%2,%3}, {%4,%5,%6,%7}, {%8,%9}, {%0,%1,%2,%3};" \
                 : "+f"((d)[0]), "+f"((d)[1]), "+f"((d)[2]), "+f"((d)[3]) \
                 : "r"((a)[0]), "r"((a)[1]), "r"((a)[2]), "r"((a)[3]), \
                   "r"((b)[0]), "r"((b)[1]))

#define MMA_F16(d, a, b) \
    asm volatile("mma.sync.aligned.m16n8k16.row.col.f32.f16.f16.f32 " \
                 "{%0,%1,%2,%3}, {%4,%5,%6,%7}, {%8,%9}, {%0,%1,%2,%3};" \
                 : "+f"((d)[0]), "+f"((d)[1]), "+f"((d)[2]), "+f"((d)[3]) \
                 : "r"((a)[0]), "r"((a)[1]), "r"((a)[2]), "r"((a)[3]), \
                   "r"((b)[0]), "r"((b)[1]))

#define CP_ASYNC16(s, g) \
    asm volatile("cp.async.cg.shared.global [%0], [%1], 16;" :: "r"(s), "l"(g))
#define CP_COMMIT() asm volatile("cp.async.commit_group;" ::: "memory")
#define CP_WAIT1() asm volatile("cp.async.wait_group 1;" ::: "memory")
#define CP_WAIT0() asm volatile("cp.async.wait_group 0;" ::: "memory")

// bf16 hi/lo pack: low half = first arg
__device__ __forceinline__ void pack_hilo(float a, float b, unsigned& h, unsigned& l) {
    asm("cvt.rn.bf16x2.f32 %0, %1, %2;" : "=r"(h) : "f"(b), "f"(a));
    float fa = __uint_as_float(h << 16);
    float fb = __uint_as_float(h & 0xffff0000u);
    asm("cvt.rn.bf16x2.f32 %0, %1, %2;" : "=r"(l) : "f"(b - fb), "f"(a - fa));
}
// fp16 hi/lo pack
__device__ __forceinline__ void pack_hilo_f16(float a, float b, unsigned& h, unsigned& l) {
    asm("cvt.rn.f16x2.f32 %0, %1, %2;" : "=r"(h) : "f"(b), "f"(a));
    __half2 h2 = *reinterpret_cast<__half2*>(&h);
    float2 f = __half22float2(h2);
    asm("cvt.rn.f16x2.f32 %0, %1, %2;" : "=r"(l) : "f"(b - f.y), "f"(a - f.x));
}
// fp16 single pack
__device__ __forceinline__ unsigned pack_f16(float a, float b) {
    unsigned r;
    asm("cvt.rn.f16x2.f32 %0, %1, %2;" : "=r"(r) : "f"(b), "f"(a));
    return r;
}

// ---------------------------------------------------------------------------
// Prep (single launch): fp32 -> (hi, lo) bf16 split for x and all 4 weights
// ---------------------------------------------------------------------------
#define NX4 (MROWS * E_DIM / 4)     // 1M float4 (x)
#define NW4 (E_DIM * E_DIM / 4)     // 256K float4 (each weight)

__global__ __launch_bounds__(256) void prep_all(const float* __restrict__ x,
                                                const float* __restrict__ Wq,
                                                const float* __restrict__ Wk,
                                                const float* __restrict__ Wv,
                                                const float* __restrict__ Wo)
{
    int i = blockIdx.x * 256 + threadIdx.x;
    const float* src;
    __nv_bfloat16 *hi, *lo;
    int j;
    if (i < NX4) {
        src = x; hi = g_xhi; lo = g_xlo; j = i;
    } else {
        int t = i - NX4;
        int w = t >> 18;            // / NW4
        j = t & (NW4 - 1);
        src = (w == 0) ? Wq : (w == 1) ? Wk : (w == 2) ? Wv : Wo;
        hi = g_whi[w]; lo = g_wlo[w];
    }
    float4 v = ((const float4*)src)[j];
    unsigned h0, l0, h1, l1;
    pack_hilo(v.x, v.y, h0, l0);
    pack_hilo(v.z, v.w, h1, l1);
    ((uint2*)hi)[j] = make_uint2(h0, h1);
    ((uint2*)lo)[j] = make_uint2(l0, l1);
}

// ---------------------------------------------------------------------------
// Pipelined GEMM: C[M,N] = A[M,K]*B[N,K]^T, hi/lo bf16 3-pass, fp32 acc.
// CTA 128x128 (128 threads, 4 warps of 64m x 64n), BK=32, 3-stage cp.async.
// smem row: [hi 32 bf16 | lo 32 bf16] = 128B. Stage = 16KB + 16KB = 32KB.
// 96KB smem, <=255 regs -> 2 CTAs/SM.
// outfmt: 0 = fp32, 1 = bf16 hi/lo, 2 = fp16 hi/lo
// ---------------------------------------------------------------------------
#define GS_A 0
#define GS_B 16384
#define GSTAGE 32768
#define G_SMEM (3 * GSTAGE)
#define NKT (E_DIM / 32)   // 32

__device__ __forceinline__ void gemm_mma_body(const __nv_bfloat16* __restrict__ Ahi,
                                              const __nv_bfloat16* __restrict__ Alo,
                                              const __nv_bfloat16* __restrict__ Bhi,
                                              const __nv_bfloat16* __restrict__ Blo,
                                              float* __restrict__ Cf,
                                              __nv_bfloat16* __restrict__ Chi,
                                              __nv_bfloat16* __restrict__ Clo,
                                              float scale, int outfmt)
{
    extern __shared__ __align__(1024) char sm[];
    const uint32_t smb = smem_to_u32(sm);
    const int tid  = threadIdx.x;
    const int w    = tid >> 5;
    const int lane = tid & 31;
    const int bm   = blockIdx.y;
    const int bn   = blockIdx.x;
    const int m0w  = (w & 1) * 64;
    const int n0w  = (w >> 1) * 64;

    float acc[4][8][4];
#pragma unroll
    for (int mt = 0; mt < 4; mt++)
#pragma unroll
        for (int nt = 0; nt < 8; nt++)
#pragma unroll
            for (int j = 0; j < 4; j++) acc[mt][nt][j] = 0.f;

    // loader: 8 chunks/row (c<4: hi, c>=4: lo), rows rbase+16p
    const int chunk = tid & 7;
    const int rbase = tid >> 3;          // 0..15
    const bool use_hi = (chunk < 4);
    const int ccol = (chunk & 3) * 8;
    const __nv_bfloat16* Asrc = use_hi ? Ahi : Alo;
    const __nv_bfloat16* Bsrc = use_hi ? Bhi : Blo;
    uint32_t sofs[8];
#pragma unroll
    for (int p = 0; p < 8; p++)
        sofs[p] = SWZ((uint32_t)((rbase + 16 * p) * 128 + chunk * 16));

    auto issue = [&](int kt, int st) {
        const uint32_t sb = smb + (uint32_t)st * GSTAGE;
        const int col = kt * 32 + ccol;
#pragma unroll
        for (int p = 0; p < 8; p++) {
            int r = rbase + 16 * p;
            CP_ASYNC16(sb + GS_A + sofs[p], Asrc + (size_t)(bm * 128 + r) * E_DIM + col);
            CP_ASYNC16(sb + GS_B + sofs[p], Bsrc + (size_t)(bn * 128 + r) * E_DIM + col);
        }
        CP_COMMIT();
    };

    issue(0, 0);
    issue(1, 1);

    const int a_r   = (lane & 7) + ((lane >> 3) & 1) * 8;
    const int a_c16 = lane >> 4;
    const int b_r   = (lane & 7) + ((lane >> 4) & 1) * 8;
    const int b_c16 = (lane >> 3) & 1;

    int st = 0;
    for (int kt = 0; kt < NKT; kt++) {
        if (kt < NKT - 1) CP_WAIT1(); else CP_WAIT0();
        __syncthreads();
        const uint32_t sb = smb + (uint32_t)st * GSTAGE;

        if (kt + 2 < NKT) {
            int st2 = st + 2; if (st2 >= 3) st2 -= 3;
            issue(kt + 2, st2);
        }

#pragma unroll
        for (int ks = 0; ks < 2; ks++) {
            uint32_t afh[4][4], afl[4][4];
#pragma unroll
            for (int mt = 0; mt < 4; mt++) {
                int row = m0w + mt * 16 + a_r;
                uint32_t offh = SWZ((uint32_t)(row * 128 + ks * 32 + a_c16 * 16));
                uint32_t offl = SWZ((uint32_t)(row * 128 + 64 + ks * 32 + a_c16 * 16));
                LDMATRIX_X4(afh[mt][0], afh[mt][1], afh[mt][2], afh[mt][3], sb + GS_A + offh);
                LDMATRIX_X4(afl[mt][0], afl[mt][1], afl[mt][2], afl[mt][3], sb + GS_A + offl);
            }
            uint32_t bfh[8][2], bfl[8][2];
#pragma unroll
            for (int ntp = 0; ntp < 4; ntp++) {
                int nrow = n0w + ntp * 16 + b_r;
                uint32_t offh = SWZ((uint32_t)(nrow * 128 + ks * 32 + b_c16 * 16));
                uint32_t offl = SWZ((uint32_t)(nrow * 128 + 64 + ks * 32 + b_c16 * 16));
                LDMATRIX_X4(bfh[2 * ntp][0], bfh[2 * ntp][1],
                            bfh[2 * ntp + 1][0], bfh[2 * ntp + 1][1], sb + GS_B + offh);
                LDMATRIX_X4(bfl[2 * ntp][0], bfl[2 * ntp][1],
                            bfl[2 * ntp + 1][0], bfl[2 * ntp + 1][1], sb + GS_B + offl);
            }
#pragma unroll
            for (int mt = 0; mt < 4; mt++)
#pragma unroll
                for (int nt = 0; nt < 8; nt++) {
                    MMA_BF16(acc[mt][nt], afh[mt], bfh[nt]);
                    MMA_BF16(acc[mt][nt], afh[mt], bfl[nt]);
                    MMA_BF16(acc[mt][nt], afl[mt], bfh[nt]);
                }
        }
        st++; if (st >= 3) st = 0;
    }

#pragma unroll
    for (int mt = 0; mt < 4; mt++) {
        size_t m = (size_t)(bm * 128 + m0w + mt * 16 + (lane >> 2));
#pragma unroll
        for (int nt = 0; nt < 8; nt++) {
            size_t n = (size_t)(bn * 128 + n0w + nt * 8 + (lane & 3) * 2);
            if (outfmt == 0) {
                float* p = Cf + m * E_DIM + n;
                *(float2*)p = make_float2(acc[mt][nt][0], acc[mt][nt][1]);
                *(float2*)(p + (size_t)8 * E_DIM) = make_float2(acc[mt][nt][2], acc[mt][nt][3]);
            } else if (outfmt == 1) {
                unsigned hh, ll;
                pack_hilo(acc[mt][nt][0] * scale, acc[mt][nt][1] * scale, hh, ll);
                *(unsigned*)(Chi + m * E_DIM + n) = hh;
                *(unsigned*)(Clo + m * E_DIM + n) = ll;
                pack_hilo(acc[mt][nt][2] * scale, acc[mt][nt][3] * scale, hh, ll);
                *(unsigned*)(Chi + (m + 8) * E_DIM + n) = hh;
                *(unsigned*)(Clo + (m + 8) * E_DIM + n) = ll;
            } else {
                unsigned hh, ll;
                pack_hilo_f16(acc[mt][nt][0], acc[mt][nt][1], hh, ll);
                *(unsigned*)(Chi + m * E_DIM + n) = hh;
                *(unsigned*)(Clo + m * E_DIM + n) = ll;
                pack_hilo_f16(acc[mt][nt][2], acc[mt][nt][3], hh, ll);
                *(unsigned*)(Chi + (m + 8) * E_DIM + n) = hh;
                *(unsigned*)(Clo + (m + 8) * E_DIM + n) = ll;
            }
        }
    }
}

__global__ __launch_bounds__(128, 2) void qkv_gemm_mma()
{
    int z = blockIdx.z;
    __nv_bfloat16* Chi = (z == 0) ? g_qhi : (z == 1) ? g_khi : g_vhi;
    __nv_bfloat16* Clo = (z == 0) ? g_qlo : (z == 1) ? g_klo : g_vlo;
    float scale = (z == 0) ? 0.125f : 1.0f;       // fold 1/sqrt(dk) into Q
    int fmt = (z == 2) ? 2 : 1;                   // V in fp16 hi/lo
    gemm_mma_body(g_xhi, g_xlo, g_whi[z], g_wlo[z], nullptr, Chi, Clo, scale, fmt);
}

__global__ __launch_bounds__(128, 2) void out_gemm_mma(float* __restrict__ C)
{
    gemm_mma_body(g_mhi, g_mlo, g_whi[3], g_wlo[3], C, nullptr, nullptr, 1.0f, 0);
}

// ---------------------------------------------------------------------------
// Flash attention, mma.sync. Per CTA: 128 q rows of one (b,h), 128 threads,
// 4 warps x 32 q-rows (2 m16 tiles). QK: bf16 hi/lo 3-pass. PV: fp16 P (1 word)
// x fp16 V hi/lo, 2-pass. KV tile 64, 2-stage cp.async. Q staged in smem.
// smem = 32KB Q + 2x32KB stages = 96KB -> 2 CTAs/SM.
// ---------------------------------------------------------------------------
#define AQ_HI 0
#define AQ_LO 16384
#define AST0  32768
#define A_KHI 0
#define A_KLO 8192
#define A_VHI 16384
#define A_VLO 24576
#define ASTAGE 32768
#define ATTN_SMEM (AST0 + 2 * ASTAGE)
#define NKV (SEQ / 64)   // 32
#define QBLK 128

__global__ __launch_bounds__(128, 2) void attn_mma(const float* __restrict__ qp)
{
    extern __shared__ __align__(1024) char sm[];
    const uint32_t smb = smem_to_u32(sm);
    const int tid  = threadIdx.x;
    const int wid  = tid >> 5;
    const int lane = tid & 31;
    const int bh   = blockIdx.y;
    const int b    = bh >> 4;
    const int h    = bh & 15;
    const int qbase = blockIdx.x * QBLK;
    const int wq0   = wid * 32;
    const float cq  = cosf(qp[0] + qp[1]);

    const size_t bS = (size_t)b * SEQ;
    const int h64 = h * 64;

    // ---- cp.async loader geometry (K/V): 4 buffers x 64 rows ----
    const __nv_bfloat16* khg = g_khi + bS * E_DIM + h64;
    const __nv_bfloat16* klg = g_klo + bS * E_DIM + h64;
    const __nv_bfloat16* vhg = g_vhi + bS * E_DIM + h64;
    const __nv_bfloat16* vlg = g_vlo + bS * E_DIM + h64;
    const int chunk = tid & 7;
    const int crow  = tid >> 3;           // 0..15
    const int ccol  = chunk * 8;
    uint32_t sco[4];
#pragma unroll
    for (int p = 0; p < 4; p++)
        sco[p] = SWZ((uint32_t)((crow + 16 * p) * 128 + chunk * 16));

    auto issue_stage = [&](int it, int st) {
        const uint32_t sb = smb + AST0 + (uint32_t)st * ASTAGE;
#pragma unroll
        for (int p = 0; p < 4; p++) {
            const size_t r = (size_t)(it * 64 + crow + 16 * p) * E_DIM + ccol;
            CP_ASYNC16(sb + A_KHI + sco[p], khg + r);
            CP_ASYNC16(sb + A_KLO + sco[p], klg + r);
            CP_ASYNC16(sb + A_VHI + sco[p], vhg + r);
            CP_ASYNC16(sb + A_VLO + sco[p], vlg + r);
        }
        CP_COMMIT();
    };

    issue_stage(0, 0);
    issue_stage(1, 1);

    // ---- stage Q (hi/lo) into smem: 128 rows x 128B each ----
    {
        const __nv_bfloat16* qhg = g_qhi + (bS + qbase) * E_DIM + h64;
        const __nv_bfloat16* qlg = g_qlo + (bS + qbase) * E_DIM + h64;
#pragma unroll
        for (int p = 0; p < 8; p++) {
            int r = crow + 16 * p;
            uint32_t so = SWZ((uint32_t)(r * 128 + chunk * 16));
            *(uint4*)(sm + AQ_HI + so) = *(const uint4*)(qhg + (size_t)r * E_DIM + ccol);
            *(uint4*)(sm + AQ_LO + so) = *(const uint4*)(qlg + (size_t)r * E_DIM + ccol);
        }
    }

    float mx[2][2], lsum[2][2];
    float oacc[2][8][4];
#pragma unroll
    for (int mt = 0; mt < 2; mt++) {
        mx[mt][0] = -1e30f; mx[mt][1] = -1e30f;
        lsum[mt][0] = 0.f;  lsum[mt][1] = 0.f;
#pragma unroll
        for (int nt = 0; nt < 8; nt++)
#pragma unroll
            for (int j = 0; j < 4; j++) oacc[mt][nt][j] = 0.f;
    }

    const int a_r   = (lane & 7) + ((lane >> 3) & 1) * 8;
    const int a_c16 = lane >> 4;
    const int brow  = (lane & 7) + ((lane >> 4) & 1) * 8;
    const int bc16  = (lane >> 3) & 1;
    const int vrow  = lane & 15;
    const int vcs   = (lane >> 4) * 16;

    for (int it = 0; it < NKV; it++) {
        if (it < NKV - 1) CP_WAIT1(); else CP_WAIT0();
        __syncthreads();

        const uint32_t sb = smb + AST0 + (uint32_t)(it & 1) * ASTAGE;

        // ---- S = Q.K^T (bf16 hi/lo, 3 passes), 2 m-tiles ----
        float sacc[2][8][4];
#pragma unroll
        for (int mt = 0; mt < 2; mt++)
#pragma unroll
            for (int nt = 0; nt < 8; nt++)
#pragma unroll
                for (int j = 0; j < 4; j++) sacc[mt][nt][j] = 0.f;

#pragma unroll
        for (int ks = 0; ks < 4; ks++) {
            unsigned kh2[8][2], kl2[8][2];
#pragma unroll
            for (int ntp = 0; ntp < 4; ntp++) {
                uint32_t off = SWZ((uint32_t)((ntp * 16 + brow) * 128 + ks * 32 + bc16 * 16));
                LDMATRIX_X4(kh2[2 * ntp][0], kh2[2 * ntp][1],
                            kh2[2 * ntp + 1][0], kh2[2 * ntp + 1][1], sb + A_KHI + off);
                LDMATRIX_X4(kl2[2 * ntp][0], kl2[2 * ntp][1],
                            kl2[2 * ntp + 1][0], kl2[2 * ntp + 1][1], sb + A_KLO + off);
            }
#pragma unroll
            for (int mt = 0; mt < 2; mt++) {
                unsigned qfh[4], qfl[4];
                uint32_t qoff = SWZ((uint32_t)((wq0 + mt * 16 + a_r) * 128 + ks * 32 + a_c16 * 16));
                LDMATRIX_X4(qfh[0], qfh[1], qfh[2], qfh[3], smb + AQ_HI + qoff);
                LDMATRIX_X4(qfl[0], qfl[1], qfl[2], qfl[3], smb + AQ_LO + qoff);
#pragma unroll
                for (int nt = 0; nt < 8; nt++) {
                    MMA_BF16(sacc[mt][nt], qfh, kh2[nt]);
                    MMA_BF16(sacc[mt][nt], qfh, kl2[nt]);
                    MMA_BF16(sacc[mt][nt], qfl, kh2[nt]);
                }
            }
        }

        // ---- online softmax per m-tile ----
#pragma unroll
        for (int mt = 0; mt < 2; mt++) {
            float mn0 = mx[mt][0], mn1 = mx[mt][1];
#pragma unroll
            for (int nt = 0; nt < 8; nt++) {
                mn0 = fmaxf(mn0, fmaxf(sacc[mt][nt][0], sacc[mt][nt][1]));
                mn1 = fmaxf(mn1, fmaxf(sacc[mt][nt][2], sacc[mt][nt][3]));
            }
            mn0 = fmaxf(mn0, __shfl_xor_sync(0xffffffffu, mn0, 1));
            mn0 = fmaxf(mn0, __shfl_xor_sync(0xffffffffu, mn0, 2));
            mn1 = fmaxf(mn1, __shfl_xor_sync(0xffffffffu, mn1, 1));
            mn1 = fmaxf(mn1, __shfl_xor_sync(0xffffffffu, mn1, 2));
            float sc0 = __expf(mx[mt][0] - mn0);
            float sc1 = __expf(mx[mt][1] - mn1);
            mx[mt][0] = mn0; mx[mt][1] = mn1;
            float rs0 = 0.f, rs1 = 0.f;
#pragma unroll
            for (int nt = 0; nt < 8; nt++) {
                sacc[mt][nt][0] = __expf(sacc[mt][nt][0] - mn0); rs0 += sacc[mt][nt][0];
                sacc[mt][nt][1] = __expf(sacc[mt][nt][1] - mn0); rs0 += sacc[mt][nt][1];
                sacc[mt][nt][2] = __expf(sacc[mt][nt][2] - mn1); rs1 += sacc[mt][nt][2];
                sacc[mt][nt][3] = __expf(sacc[mt][nt][3] - mn1); rs1 += sacc[mt][nt][3];
            }
            rs0 += __shfl_xor_sync(0xffffffffu, rs0, 1);
            rs0 += __shfl_xor_sync(0xffffffffu, rs0, 2);
            rs1 += __shfl_xor_sync(0xffffffffu, rs1, 1);
            rs1 += __shfl_xor_sync(0xffffffffu, rs1, 2);
            lsum[mt][0] = lsum[mt][0] * sc0 + rs0;
            lsum[mt][1] = lsum[mt][1] * sc1 + rs1;
#pragma unroll
            for (int nt = 0; nt < 8; nt++) {
                oacc[mt][nt][0] *= sc0; oacc[mt][nt][1] *= sc0;
                oacc[mt][nt][2] *= sc1; oacc[mt][nt][3] *= sc1;
            }
        }

        // ---- O += P.V: P fp16 single, V fp16 hi/lo (2 passes) ----
#pragma unroll
        for (int j = 0; j < 4; j++) {
            unsigned vh2[8][2], vl2[8][2];
#pragma unroll
            for (int dp = 0; dp < 4; dp++) {
                uint32_t off = SWZ((uint32_t)((j * 16 + vrow) * 128 + dp * 32 + vcs));
                LDMATRIX_X4_T(vh2[2 * dp][0], vh2[2 * dp][1],
                              vh2[2 * dp + 1][0], vh2[2 * dp + 1][1], sb + A_VHI + off);
                LDMATRIX_X4_T(vl2[2 * dp][0], vl2[2 * dp][1],
                              vl2[2 * dp + 1][0], vl2[2 * dp + 1][1], sb + A_VLO + off);
            }
#pragma unroll
            for (int mt = 0; mt < 2; mt++) {
                unsigned ph[4];
                ph[0] = pack_f16(sacc[mt][2 * j][0],     sacc[mt][2 * j][1]);
                ph[1] = pack_f16(sacc[mt][2 * j][2],     sacc[mt][2 * j][3]);
                ph[2] = pack_f16(sacc[mt][2 * j + 1][0], sacc[mt][2 * j + 1][1]);
                ph[3] = pack_f16(sacc[mt][2 * j + 1][2], sacc[mt][2 * j + 1][3]);
#pragma unroll
                for (int nt = 0; nt < 8; nt++) {
                    MMA_F16(oacc[mt][nt], ph, vh2[nt]);
                    MMA_F16(oacc[mt][nt], ph, vl2[nt]);
                }
            }
        }

        __syncthreads();
        if (it + 2 < NKV) issue_stage(it + 2, it & 1);
    }

    // ---- epilogue: normalize, +c on dk<4, write hi/lo bf16 mix ----
    const bool adds = ((lane & 3) < 2);
#pragma unroll
    for (int mt = 0; mt < 2; mt++) {
        const float inv0 = 1.f / lsum[mt][0];
        const float inv1 = 1.f / lsum[mt][1];
        const size_t row0 = (bS + qbase + wq0 + mt * 16 + (lane >> 2)) * E_DIM
                            + h64 + (lane & 3) * 2;
        const size_t row1 = row0 + 8 * E_DIM;
#pragma unroll
        for (int nt = 0; nt < 8; nt++) {
            const float add = (nt == 0 && adds) ? cq : 0.f;
            float v0 = oacc[mt][nt][0] * inv0 + add;
            float v1 = oacc[mt][nt][1] * inv0 + add;
            float v2 = oacc[mt][nt][2] * inv1 + add;
            float v3 = oacc[mt][nt][3] * inv1 + add;
            unsigned hh, ll;
            pack_hilo(v0, v1, hh, ll);
            *(unsigned*)(g_mhi + row0 + nt * 8) = hh;
            *(unsigned*)(g_mlo + row0 + nt * 8) = ll;
            pack_hilo(v2, v3, hh, ll);
            *(unsigned*)(g_mhi + row1 + nt * 8) = hh;
            *(unsigned*)(g_mlo + row1 + nt * 8) = ll;
        }
    }
}

// ---------------------------------------------------------------------------
extern "C" void kernel_launch(void* const* d_in, const int* in_sizes, int n_in,
                              void* d_out, int out_size)
{
    const float* x  = (const float*)d_in[0];
    const float* Wq = (const float*)d_in[1];
    const float* Wk = (const float*)d_in[2];
    const float* Wv = (const float*)d_in[3];
    const float* Wo = (const float*)d_in[4];
    const float* qp = (const float*)d_in[5];
    float* out = (float*)d_out;

    cudaFuncSetAttribute(qkv_gemm_mma, cudaFuncAttributeMaxDynamicSharedMemorySize, G_SMEM);
    cudaFuncSetAttribute(out_gemm_mma, cudaFuncAttributeMaxDynamicSharedMemorySize, G_SMEM);
    cudaFuncSetAttribute(attn_mma,     cudaFuncAttributeMaxDynamicSharedMemorySize, ATTN_SMEM);

    const int NPREP = NX4 + 4 * NW4;   // 2M float4 units
    prep_all<<<(NPREP + 255) / 256, 256>>>(x, Wq, Wk, Wv, Wo);

    qkv_gemm_mma<<<dim3(8, 32, 3), 128, G_SMEM>>>();
    attn_mma<<<dim3(SEQ / QBLK, BATCH * NHEAD), 128, ATTN_SMEM>>>(qp);
    out_gemm_mma<<<dim3(8, 32), 128, G_SMEM>>>(out);
}

// round 8
// speedup vs baseline: 4.1552x; 1.0058x over previous
#include <cuda_runtime.h>
#include <cuda_bf16.h>
#include <cuda_fp16.h>
#include <math.h>
#include <cstdint>

#define E_DIM 1024
#define SEQ   2048
#define BATCH 2
#define NHEAD 16
#define DK    64
#define MROWS (BATCH * SEQ)   // 4096

// ---------------------------------------------------------------------------
// Scratch (device globals; no allocations allowed)
// ---------------------------------------------------------------------------
__device__ __nv_bfloat16 g_xhi[MROWS * E_DIM];
__device__ __nv_bfloat16 g_xlo[MROWS * E_DIM];
__device__ __nv_bfloat16 g_whi[4][E_DIM * E_DIM];   // q,k,v,o
__device__ __nv_bfloat16 g_wlo[4][E_DIM * E_DIM];
__device__ __nv_bfloat16 g_qhi[MROWS * E_DIM];      // bf16 hi/lo
__device__ __nv_bfloat16 g_qlo[MROWS * E_DIM];
__device__ __nv_bfloat16 g_khi[MROWS * E_DIM];      // bf16 hi/lo
__device__ __nv_bfloat16 g_klo[MROWS * E_DIM];
__device__ __nv_bfloat16 g_vhi[MROWS * E_DIM];      // fp16 hi/lo (bits)
__device__ __nv_bfloat16 g_vlo[MROWS * E_DIM];
__device__ __nv_bfloat16 g_mhi[MROWS * E_DIM];
__device__ __nv_bfloat16 g_mlo[MROWS * E_DIM];

// ---------------------------------------------------------------------------
// Helpers
// ---------------------------------------------------------------------------
__device__ __forceinline__ uint32_t smem_to_u32(const void* p) {
    uint32_t a;
    asm("{ .reg .u64 t; cvta.to.shared.u64 t, %1; cvt.u32.u64 %0, t; }"
        : "=r"(a) : "l"(p));
    return a;
}
#define SWZ(o) ((o) ^ (((o) >> 3) & 0x70))

#define LDMATRIX_X4(r0, r1, r2, r3, addr) \
    asm volatile("ldmatrix.sync.aligned.m8n8.x4.shared.b16 {%0,%1,%2,%3}, [%4];" \
                 : "=r"(r0), "=r"(r1), "=r"(r2), "=r"(r3) : "r"(addr))

#define LDMATRIX_X4_T(r0, r1, r2, r3, addr) \
    asm volatile("ldmatrix.sync.aligned.m8n8.x4.trans.shared.b16 {%0,%1,%2,%3}, [%4];" \
                 : "=r"(r0), "=r"(r1), "=r"(r2), "=r"(r3) : "r"(addr))

#define MMA_BF16(d, a, b) \
    asm volatile("mma.sync.aligned.m16n8k16.row.col.f32.bf16.bf16.f32 " \
                 "{%0,%1,%2,%3}, {%4,%5,%6,%7}, {%8,%9}, {%0,%1,%2,%3};" \
                 : "+f"((d)[0]), "+f"((d)[1]), "+f"((d)[2]), "+f"((d)[3]) \
                 : "r"((a)[0]), "r"((a)[1]), "r"((a)[2]), "r"((a)[3]), \
                   "r"((b)[0]), "r"((b)[1]))

#define MMA_F16(d, a, b) \
    asm volatile("mma.sync.aligned.m16n8k16.row.col.f32.f16.f16.f32 " \
                 "{%0,%1,%2,%3}, {%4,%5,%6,%7}, {%8,%9}, {%0,%1,%2,%3};" \
                 : "+f"((d)[0]), "+f"((d)[1]), "+f"((d)[2]), "+f"((d)[3]) \
                 : "r"((a)[0]), "r"((a)[1]), "r"((a)[2]), "r"((a)[3]), \
                   "r"((b)[0]), "r"((b)[1]))

#define CP_ASYNC16(s, g) \
    asm volatile("cp.async.cg.shared.global [%0], [%1], 16;" :: "r"(s), "l"(g))
#define CP_COMMIT() asm volatile("cp.async.commit_group;" ::: "memory")
#define CP_WAIT1() asm volatile("cp.async.wait_group 1;" ::: "memory")
#define CP_WAIT0() asm volatile("cp.async.wait_group 0;" ::: "memory")

// bf16 hi/lo pack: low half = first arg
__device__ __forceinline__ void pack_hilo(float a, float b, unsigned& h, unsigned& l) {
    asm("cvt.rn.bf16x2.f32 %0, %1, %2;" : "=r"(h) : "f"(b), "f"(a));
    float fa = __uint_as_float(h << 16);
    float fb = __uint_as_float(h & 0xffff0000u);
    asm("cvt.rn.bf16x2.f32 %0, %1, %2;" : "=r"(l) : "f"(b - fb), "f"(a - fa));
}
// fp16 hi/lo pack
__device__ __forceinline__ void pack_hilo_f16(float a, float b, unsigned& h, unsigned& l) {
    asm("cvt.rn.f16x2.f32 %0, %1, %2;" : "=r"(h) : "f"(b), "f"(a));
    __half2 h2 = *reinterpret_cast<__half2*>(&h);
    float2 f = __half22float2(h2);
    asm("cvt.rn.f16x2.f32 %0, %1, %2;" : "=r"(l) : "f"(b - f.y), "f"(a - f.x));
}
// fp16 single pack
__device__ __forceinline__ unsigned pack_f16(float a, float b) {
    unsigned r;
    asm("cvt.rn.f16x2.f32 %0, %1, %2;" : "=r"(r) : "f"(b), "f"(a));
    return r;
}

// ---------------------------------------------------------------------------
// Prep (single launch): fp32 -> (hi, lo) bf16 split for x and all 4 weights
// ---------------------------------------------------------------------------
#define NX4 (MROWS * E_DIM / 4)     // 1M float4 (x)
#define NW4 (E_DIM * E_DIM / 4)     // 256K float4 (each weight)

__global__ __launch_bounds__(256) void prep_all(const float* __restrict__ x,
                                                const float* __restrict__ Wq,
                                                const float* __restrict__ Wk,
                                                const float* __restrict__ Wv,
                                                const float* __restrict__ Wo)
{
    int i = blockIdx.x * 256 + threadIdx.x;
    const float* src;
    __nv_bfloat16 *hi, *lo;
    int j;
    if (i < NX4) {
        src = x; hi = g_xhi; lo = g_xlo; j = i;
    } else {
        int t = i - NX4;
        int w = t >> 18;            // / NW4
        j = t & (NW4 - 1);
        src = (w == 0) ? Wq : (w == 1) ? Wk : (w == 2) ? Wv : Wo;
        hi = g_whi[w]; lo = g_wlo[w];
    }
    float4 v = ((const float4*)src)[j];
    unsigned h0, l0, h1, l1;
    pack_hilo(v.x, v.y, h0, l0);
    pack_hilo(v.z, v.w, h1, l1);
    ((uint2*)hi)[j] = make_uint2(h0, h1);
    ((uint2*)lo)[j] = make_uint2(l0, l1);
}

// ---------------------------------------------------------------------------
// Pipelined GEMM: C[M,N] = A[M,K]*B[N,K]^T, hi/lo bf16 3-pass, fp32 acc.
// CTA 128x64 (128 threads, 4 warps of 64m x 32n), BK=32, 3-stage cp.async.
// smem row: [hi 32 bf16 | lo 32 bf16] = 128B. Stage = A 16KB + B 8KB = 24KB.
// 72KB smem, <=170 regs -> 3 CTAs/SM (12 warps).
// outfmt: 0 = fp32, 1 = bf16 hi/lo, 2 = fp16 hi/lo
// ---------------------------------------------------------------------------
#define GS_A 0
#define GS_B 16384
#define GSTAGE 24576
#define G_SMEM (3 * GSTAGE)
#define NKT (E_DIM / 32)   // 32

__device__ __forceinline__ void gemm_mma_body(const __nv_bfloat16* __restrict__ Ahi,
                                              const __nv_bfloat16* __restrict__ Alo,
                                              const __nv_bfloat16* __restrict__ Bhi,
                                              const __nv_bfloat16* __restrict__ Blo,
                                              float* __restrict__ Cf,
                                              __nv_bfloat16* __restrict__ Chi,
                                              __nv_bfloat16* __restrict__ Clo,
                                              float scale, int outfmt)
{
    extern __shared__ __align__(1024) char sm[];
    const uint32_t smb = smem_to_u32(sm);
    const int tid  = threadIdx.x;
    const int w    = tid >> 5;
    const int lane = tid & 31;
    const int bm   = blockIdx.y;
    const int bn   = blockIdx.x;
    const int m0w  = (w & 1) * 64;
    const int n0w  = (w >> 1) * 32;

    float acc[4][4][4];
#pragma unroll
    for (int mt = 0; mt < 4; mt++)
#pragma unroll
        for (int nt = 0; nt < 4; nt++)
#pragma unroll
            for (int j = 0; j < 4; j++) acc[mt][nt][j] = 0.f;

    // loader: 8 chunks/row (c<4: hi, c>=4: lo), rows rbase+16p
    const int chunk = tid & 7;
    const int rbase = tid >> 3;          // 0..15
    const bool use_hi = (chunk < 4);
    const int ccol = (chunk & 3) * 8;
    const __nv_bfloat16* Asrc = use_hi ? Ahi : Alo;
    const __nv_bfloat16* Bsrc = use_hi ? Bhi : Blo;
    uint32_t sofs[8];
#pragma unroll
    for (int p = 0; p < 8; p++)
        sofs[p] = SWZ((uint32_t)((rbase + 16 * p) * 128 + chunk * 16));

    auto issue = [&](int kt, int st) {
        const uint32_t sb = smb + (uint32_t)st * GSTAGE;
        const int col = kt * 32 + ccol;
#pragma unroll
        for (int p = 0; p < 8; p++)
            CP_ASYNC16(sb + GS_A + sofs[p],
                       Asrc + (size_t)(bm * 128 + rbase + 16 * p) * E_DIM + col);
#pragma unroll
        for (int p = 0; p < 4; p++)
            CP_ASYNC16(sb + GS_B + sofs[p],
                       Bsrc + (size_t)(bn * 64 + rbase + 16 * p) * E_DIM + col);
        CP_COMMIT();
    };

    issue(0, 0);
    issue(1, 1);

    const int a_r   = (lane & 7) + ((lane >> 3) & 1) * 8;
    const int a_c16 = lane >> 4;
    const int b_r   = (lane & 7) + ((lane >> 4) & 1) * 8;
    const int b_c16 = (lane >> 3) & 1;

    int st = 0;
    for (int kt = 0; kt < NKT; kt++) {
        if (kt < NKT - 1) CP_WAIT1(); else CP_WAIT0();
        __syncthreads();
        const uint32_t sb = smb + (uint32_t)st * GSTAGE;

        if (kt + 2 < NKT) {
            int st2 = st + 2; if (st2 >= 3) st2 -= 3;
            issue(kt + 2, st2);
        }

#pragma unroll
        for (int ks = 0; ks < 2; ks++) {
            uint32_t bfh[4][2], bfl[4][2];
#pragma unroll
            for (int ntp = 0; ntp < 2; ntp++) {
                int nrow = n0w + ntp * 16 + b_r;
                uint32_t offh = SWZ((uint32_t)(nrow * 128 + ks * 32 + b_c16 * 16));
                uint32_t offl = SWZ((uint32_t)(nrow * 128 + 64 + ks * 32 + b_c16 * 16));
                LDMATRIX_X4(bfh[2 * ntp][0], bfh[2 * ntp][1],
                            bfh[2 * ntp + 1][0], bfh[2 * ntp + 1][1], sb + GS_B + offh);
                LDMATRIX_X4(bfl[2 * ntp][0], bfl[2 * ntp][1],
                            bfl[2 * ntp + 1][0], bfl[2 * ntp + 1][1], sb + GS_B + offl);
            }
#pragma unroll
            for (int mt = 0; mt < 4; mt++) {
                uint32_t afh[4], afl[4];
                int row = m0w + mt * 16 + a_r;
                uint32_t offh = SWZ((uint32_t)(row * 128 + ks * 32 + a_c16 * 16));
                uint32_t offl = SWZ((uint32_t)(row * 128 + 64 + ks * 32 + a_c16 * 16));
                LDMATRIX_X4(afh[0], afh[1], afh[2], afh[3], sb + GS_A + offh);
                LDMATRIX_X4(afl[0], afl[1], afl[2], afl[3], sb + GS_A + offl);
#pragma unroll
                for (int nt = 0; nt < 4; nt++) {
                    MMA_BF16(acc[mt][nt], afh, bfh[nt]);
                    MMA_BF16(acc[mt][nt], afh, bfl[nt]);
                    MMA_BF16(acc[mt][nt], afl, bfh[nt]);
                }
            }
        }
        st++; if (st >= 3) st = 0;
    }

#pragma unroll
    for (int mt = 0; mt < 4; mt++) {
        size_t m = (size_t)(bm * 128 + m0w + mt * 16 + (lane >> 2));
#pragma unroll
        for (int nt = 0; nt < 4; nt++) {
            size_t n = (size_t)(bn * 64 + n0w + nt * 8 + (lane & 3) * 2);
            if (outfmt == 0) {
                float* p = Cf + m * E_DIM + n;
                *(float2*)p = make_float2(acc[mt][nt][0], acc[mt][nt][1]);
                *(float2*)(p + (size_t)8 * E_DIM) = make_float2(acc[mt][nt][2], acc[mt][nt][3]);
            } else if (outfmt == 1) {
                unsigned hh, ll;
                pack_hilo(acc[mt][nt][0] * scale, acc[mt][nt][1] * scale, hh, ll);
                *(unsigned*)(Chi + m * E_DIM + n) = hh;
                *(unsigned*)(Clo + m * E_DIM + n) = ll;
                pack_hilo(acc[mt][nt][2] * scale, acc[mt][nt][3] * scale, hh, ll);
                *(unsigned*)(Chi + (m + 8) * E_DIM + n) = hh;
                *(unsigned*)(Clo + (m + 8) * E_DIM + n) = ll;
            } else {
                unsigned hh, ll;
                pack_hilo_f16(acc[mt][nt][0], acc[mt][nt][1], hh, ll);
                *(unsigned*)(Chi + m * E_DIM + n) = hh;
                *(unsigned*)(Clo + m * E_DIM + n) = ll;
                pack_hilo_f16(acc[mt][nt][2], acc[mt][nt][3], hh, ll);
                *(unsigned*)(Chi + (m + 8) * E_DIM + n) = hh;
                *(unsigned*)(Clo + (m + 8) * E_DIM + n) = ll;
            }
        }
    }
}

__global__ __launch_bounds__(128, 3) void qkv_gemm_mma()
{
    int z = blockIdx.z;
    __nv_bfloat16* Chi = (z == 0) ? g_qhi : (z == 1) ? g_khi : g_vhi;
    __nv_bfloat16* Clo = (z == 0) ? g_qlo : (z == 1) ? g_klo : g_vlo;
    float scale = (z == 0) ? 0.125f : 1.0f;       // fold 1/sqrt(dk) into Q
    int fmt = (z == 2) ? 2 : 1;                   // V in fp16 hi/lo
    gemm_mma_body(g_xhi, g_xlo, g_whi[z], g_wlo[z], nullptr, Chi, Clo, scale, fmt);
}

__global__ __launch_bounds__(128, 3) void out_gemm_mma(float* __restrict__ C)
{
    gemm_mma_body(g_mhi, g_mlo, g_whi[3], g_wlo[3], C, nullptr, nullptr, 1.0f, 0);
}

// ---------------------------------------------------------------------------
// Flash attention, mma.sync. Per CTA: 128 q rows of one (b,h), 128 threads,
// 4 warps x 32 q-rows (2 m16 tiles). QK: bf16 hi/lo 3-pass. PV: fp16 P (1 word)
// x fp16 V hi/lo, 2-pass. KV tile 64, 2-stage cp.async, ONE sync per iter.
// smem = 32KB Q + 2x32KB stages = 96KB -> 2 CTAs/SM.
// ---------------------------------------------------------------------------
#define AQ_HI 0
#define AQ_LO 16384
#define AST0  32768
#define A_KHI 0
#define A_KLO 8192
#define A_VHI 16384
#define A_VLO 24576
#define ASTAGE 32768
#define ATTN_SMEM (AST0 + 2 * ASTAGE)
#define NKV (SEQ / 64)   // 32
#define QBLK 128

__global__ __launch_bounds__(128, 2) void attn_mma(const float* __restrict__ qp)
{
    extern __shared__ __align__(1024) char sm[];
    const uint32_t smb = smem_to_u32(sm);
    const int tid  = threadIdx.x;
    const int wid  = tid >> 5;
    const int lane = tid & 31;
    const int bh   = blockIdx.y;
    const int b    = bh >> 4;
    const int h    = bh & 15;
    const int qbase = blockIdx.x * QBLK;
    const int wq0   = wid * 32;
    const float cq  = cosf(qp[0] + qp[1]);

    const size_t bS = (size_t)b * SEQ;
    const int h64 = h * 64;

    // ---- cp.async loader geometry (K/V): 4 buffers x 64 rows ----
    const __nv_bfloat16* khg = g_khi + bS * E_DIM + h64;
    const __nv_bfloat16* klg = g_klo + bS * E_DIM + h64;
    const __nv_bfloat16* vhg = g_vhi + bS * E_DIM + h64;
    const __nv_bfloat16* vlg = g_vlo + bS * E_DIM + h64;
    const int chunk = tid & 7;
    const int crow  = tid >> 3;           // 0..15
    const int ccol  = chunk * 8;
    uint32_t sco[4];
#pragma unroll
    for (int p = 0; p < 4; p++)
        sco[p] = SWZ((uint32_t)((crow + 16 * p) * 128 + chunk * 16));

    auto issue_stage = [&](int it, int st) {
        const uint32_t sb = smb + AST0 + (uint32_t)st * ASTAGE;
#pragma unroll
        for (int p = 0; p < 4; p++) {
            const size_t r = (size_t)(it * 64 + crow + 16 * p) * E_DIM + ccol;
            CP_ASYNC16(sb + A_KHI + sco[p], khg + r);
            CP_ASYNC16(sb + A_KLO + sco[p], klg + r);
            CP_ASYNC16(sb + A_VHI + sco[p], vhg + r);
            CP_ASYNC16(sb + A_VLO + sco[p], vlg + r);
        }
        CP_COMMIT();
    };

    issue_stage(0, 0);

    // ---- stage Q (hi/lo) into smem: 128 rows x 128B each ----
    {
        const __nv_bfloat16* qhg = g_qhi + (bS + qbase) * E_DIM + h64;
        const __nv_bfloat16* qlg = g_qlo + (bS + qbase) * E_DIM + h64;
#pragma unroll
        for (int p = 0; p < 8; p++) {
            int r = crow + 16 * p;
            uint32_t so = SWZ((uint32_t)(r * 128 + chunk * 16));
            *(uint4*)(sm + AQ_HI + so) = *(const uint4*)(qhg + (size_t)r * E_DIM + ccol);
            *(uint4*)(sm + AQ_LO + so) = *(const uint4*)(qlg + (size_t)r * E_DIM + ccol);
        }
    }

    float mx[2][2], lsum[2][2];
    float oacc[2][8][4];
#pragma unroll
    for (int mt = 0; mt < 2; mt++) {
        mx[mt][0] = -1e30f; mx[mt][1] = -1e30f;
        lsum[mt][0] = 0.f;  lsum[mt][1] = 0.f;
#pragma unroll
        for (int nt = 0; nt < 8; nt++)
#pragma unroll
            for (int j = 0; j < 4; j++) oacc[mt][nt][j] = 0.f;
    }

    const int a_r   = (lane & 7) + ((lane >> 3) & 1) * 8;
    const int a_c16 = lane >> 4;
    const int brow  = (lane & 7) + ((lane >> 4) & 1) * 8;
    const int bc16  = (lane >> 3) & 1;
    const int vrow  = lane & 15;
    const int vcs   = (lane >> 4) * 16;

    for (int it = 0; it < NKV; it++) {
        CP_WAIT0();
        __syncthreads();   // stage 'it' ready; other stage fully consumed last iter

        const uint32_t sb = smb + AST0 + (uint32_t)(it & 1) * ASTAGE;

        if (it + 1 < NKV) issue_stage(it + 1, (it + 1) & 1);

        // ---- S = Q.K^T (bf16 hi/lo, 3 passes), 2 m-tiles ----
        float sacc[2][8][4];
#pragma unroll
        for (int mt = 0; mt < 2; mt++)
#pragma unroll
            for (int nt = 0; nt < 8; nt++)
#pragma unroll
                for (int j = 0; j < 4; j++) sacc[mt][nt][j] = 0.f;

#pragma unroll
        for (int ks = 0; ks < 4; ks++) {
            unsigned kh2[8][2], kl2[8][2];
#pragma unroll
            for (int ntp = 0; ntp < 4; ntp++) {
                uint32_t off = SWZ((uint32_t)((ntp * 16 + brow) * 128 + ks * 32 + bc16 * 16));
                LDMATRIX_X4(kh2[2 * ntp][0], kh2[2 * ntp][1],
                            kh2[2 * ntp + 1][0], kh2[2 * ntp + 1][1], sb + A_KHI + off);
                LDMATRIX_X4(kl2[2 * ntp][0], kl2[2 * ntp][1],
                            kl2[2 * ntp + 1][0], kl2[2 * ntp + 1][1], sb + A_KLO + off);
            }
#pragma unroll
            for (int mt = 0; mt < 2; mt++) {
                unsigned qfh[4], qfl[4];
                uint32_t qoff = SWZ((uint32_t)((wq0 + mt * 16 + a_r) * 128 + ks * 32 + a_c16 * 16));
                LDMATRIX_X4(qfh[0], qfh[1], qfh[2], qfh[3], smb + AQ_HI + qoff);
                LDMATRIX_X4(qfl[0], qfl[1], qfl[2], qfl[3], smb + AQ_LO + qoff);
#pragma unroll
                for (int nt = 0; nt < 8; nt++) {
                    MMA_BF16(sacc[mt][nt], qfh, kh2[nt]);
                    MMA_BF16(sacc[mt][nt], qfh, kl2[nt]);
                    MMA_BF16(sacc[mt][nt], qfl, kh2[nt]);
                }
            }
        }

        // ---- online softmax per m-tile ----
#pragma unroll
        for (int mt = 0; mt < 2; mt++) {
            float mn0 = mx[mt][0], mn1 = mx[mt][1];
#pragma unroll
            for (int nt = 0; nt < 8; nt++) {
                mn0 = fmaxf(mn0, fmaxf(sacc[mt][nt][0], sacc[mt][nt][1]));
                mn1 = fmaxf(mn1, fmaxf(sacc[mt][nt][2], sacc[mt][nt][3]));
            }
            mn0 = fmaxf(mn0, __shfl_xor_sync(0xffffffffu, mn0, 1));
            mn0 = fmaxf(mn0, __shfl_xor_sync(0xffffffffu, mn0, 2));
            mn1 = fmaxf(mn1, __shfl_xor_sync(0xffffffffu, mn1, 1));
            mn1 = fmaxf(mn1, __shfl_xor_sync(0xffffffffu, mn1, 2));
            float sc0 = __expf(mx[mt][0] - mn0);
            float sc1 = __expf(mx[mt][1] - mn1);
            mx[mt][0] = mn0; mx[mt][1] = mn1;
            float rs0 = 0.f, rs1 = 0.f;
#pragma unroll
            for (int nt = 0; nt < 8; nt++) {
                sacc[mt][nt][0] = __expf(sacc[mt][nt][0] - mn0); rs0 += sacc[mt][nt][0];
                sacc[mt][nt][1] = __expf(sacc[mt][nt][1] - mn0); rs0 += sacc[mt][nt][1];
                sacc[mt][nt][2] = __expf(sacc[mt][nt][2] - mn1); rs1 += sacc[mt][nt][2];
                sacc[mt][nt][3] = __expf(sacc[mt][nt][3] - mn1); rs1 += sacc[mt][nt][3];
            }
            rs0 += __shfl_xor_sync(0xffffffffu, rs0, 1);
            rs0 += __shfl_xor_sync(0xffffffffu, rs0, 2);
            rs1 += __shfl_xor_sync(0xffffffffu, rs1, 1);
            rs1 += __shfl_xor_sync(0xffffffffu, rs1, 2);
            lsum[mt][0] = lsum[mt][0] * sc0 + rs0;
            lsum[mt][1] = lsum[mt][1] * sc1 + rs1;
#pragma unroll
            for (int nt = 0; nt < 8; nt++) {
                oacc[mt][nt][0] *= sc0; oacc[mt][nt][1] *= sc0;
                oacc[mt][nt][2] *= sc1; oacc[mt][nt][3] *= sc1;
            }
        }

        // ---- O += P.V: P fp16 single, V fp16 hi/lo (2 passes) ----
#pragma unroll
        for (int j = 0; j < 4; j++) {
            unsigned vh2[8][2], vl2[8][2];
#pragma unroll
            for (int dp = 0; dp < 4; dp++) {
                uint32_t off = SWZ((uint32_t)((j * 16 + vrow) * 128 + dp * 32 + vcs));
                LDMATRIX_X4_T(vh2[2 * dp][0], vh2[2 * dp][1],
                              vh2[2 * dp + 1][0], vh2[2 * dp + 1][1], sb + A_VHI + off);
                LDMATRIX_X4_T(vl2[2 * dp][0], vl2[2 * dp][1],
                              vl2[2 * dp + 1][0], vl2[2 * dp + 1][1], sb + A_VLO + off);
            }
#pragma unroll
            for (int mt = 0; mt < 2; mt++) {
                unsigned ph[4];
                ph[0] = pack_f16(sacc[mt][2 * j][0],     sacc[mt][2 * j][1]);
                ph[1] = pack_f16(sacc[mt][2 * j][2],     sacc[mt][2 * j][3]);
                ph[2] = pack_f16(sacc[mt][2 * j + 1][0], sacc[mt][2 * j + 1][1]);
                ph[3] = pack_f16(sacc[mt][2 * j + 1][2], sacc[mt][2 * j + 1][3]);
#pragma unroll
                for (int nt = 0; nt < 8; nt++) {
                    MMA_F16(oacc[mt][nt], ph, vh2[nt]);
                    MMA_F16(oacc[mt][nt], ph, vl2[nt]);
                }
            }
        }
    }

    // ---- epilogue: normalize, +c on dk<4, write hi/lo bf16 mix ----
    const bool adds = ((lane & 3) < 2);
#pragma unroll
    for (int mt = 0; mt < 2; mt++) {
        const float inv0 = 1.f / lsum[mt][0];
        const float inv1 = 1.f / lsum[mt][1];
        const size_t row0 = (bS + qbase + wq0 + mt * 16 + (lane >> 2)) * E_DIM
                            + h64 + (lane & 3) * 2;
        const size_t row1 = row0 + 8 * E_DIM;
#pragma unroll
        for (int nt = 0; nt < 8; nt++) {
            const float add = (nt == 0 && adds) ? cq : 0.f;
            float v0 = oacc[mt][nt][0] * inv0 + add;
            float v1 = oacc[mt][nt][1] * inv0 + add;
            float v2 = oacc[mt][nt][2] * inv1 + add;
            float v3 = oacc[mt][nt][3] * inv1 + add;
            unsigned hh, ll;
            pack_hilo(v0, v1, hh, ll);
            *(unsigned*)(g_mhi + row0 + nt * 8) = hh;
            *(unsigned*)(g_mlo + row0 + nt * 8) = ll;
            pack_hilo(v2, v3, hh, ll);
            *(unsigned*)(g_mhi + row1 + nt * 8) = hh;
            *(unsigned*)(g_mlo + row1 + nt * 8) = ll;
        }
    }
}

// ---------------------------------------------------------------------------
extern "C" void kernel_launch(void* const* d_in, const int* in_sizes, int n_in,
                              void* d_out, int out_size)
{
    const float* x  = (const float*)d_in[0];
    const float* Wq = (const float*)d_in[1];
    const float* Wk = (const float*)d_in[2];
    const float* Wv = (const float*)d_in[3];
    const float* Wo = (const float*)d_in[4];
    const float* qp = (const float*)d_in[5];
    float* out = (float*)d_out;

    cudaFuncSetAttribute(qkv_gemm_mma, cudaFuncAttributeMaxDynamicSharedMemorySize, G_SMEM);
    cudaFuncSetAttribute(out_gemm_mma, cudaFuncAttributeMaxDynamicSharedMemorySize, G_SMEM);
    cudaFuncSetAttribute(attn_mma,     cudaFuncAttributeMaxDynamicSharedMemorySize, ATTN_SMEM);

    const int NPREP = NX4 + 4 * NW4;   // 2M float4 units
    prep_all<<<(NPREP + 255) / 256, 256>>>(x, Wq, Wk, Wv, Wo);

    qkv_gemm_mma<<<dim3(16, 32, 3), 128, G_SMEM>>>();
    attn_mma<<<dim3(SEQ / QBLK, BATCH * NHEAD), 128, ATTN_SMEM>>>(qp);
    out_gemm_mma<<<dim3(16, 32), 128, G_SMEM>>>(out);
}

// round 9
// speedup vs baseline: 4.6774x; 1.1257x over previous
#include <cuda_runtime.h>
#include <cuda_bf16.h>
#include <cuda_fp16.h>
#include <math.h>
#include <cstdint>

#define E_DIM 1024
#define SEQ   2048
#define BATCH 2
#define NHEAD 16
#define DK    64
#define MROWS (BATCH * SEQ)   // 4096

// ---------------------------------------------------------------------------
// Scratch (device globals; no allocations allowed)
// ---------------------------------------------------------------------------
__device__ __nv_bfloat16 g_xhi[MROWS * E_DIM];
__device__ __nv_bfloat16 g_xlo[MROWS * E_DIM];
__device__ __nv_bfloat16 g_whi[4][E_DIM * E_DIM];   // q,k,v,o
__device__ __nv_bfloat16 g_wlo[4][E_DIM * E_DIM];
__device__ __nv_bfloat16 g_qf[MROWS * E_DIM];       // fp16 single (scaled)
__device__ __nv_bfloat16 g_khi[MROWS * E_DIM];      // fp16 hi/lo (bits)
__device__ __nv_bfloat16 g_klo[MROWS * E_DIM];
__device__ __nv_bfloat16 g_vhi[MROWS * E_DIM];      // fp16 hi/lo (bits)
__device__ __nv_bfloat16 g_vlo[MROWS * E_DIM];
__device__ __nv_bfloat16 g_mhi[MROWS * E_DIM];      // bf16 hi/lo
__device__ __nv_bfloat16 g_mlo[MROWS * E_DIM];

// ---------------------------------------------------------------------------
// Helpers
// ---------------------------------------------------------------------------
__device__ __forceinline__ uint32_t smem_to_u32(const void* p) {
    uint32_t a;
    asm("{ .reg .u64 t; cvta.to.shared.u64 t, %1; cvt.u32.u64 %0, t; }"
        : "=r"(a) : "l"(p));
    return a;
}
#define SWZ(o) ((o) ^ (((o) >> 3) & 0x70))

#define LDMATRIX_X4(r0, r1, r2, r3, addr) \
    asm volatile("ldmatrix.sync.aligned.m8n8.x4.shared.b16 {%0,%1,%2,%3}, [%4];" \
                 : "=r"(r0), "=r"(r1), "=r"(r2), "=r"(r3) : "r"(addr))

#define LDMATRIX_X4_T(r0, r1, r2, r3, addr) \
    asm volatile("ldmatrix.sync.aligned.m8n8.x4.trans.shared.b16 {%0,%1,%2,%3}, [%4];" \
                 : "=r"(r0), "=r"(r1), "=r"(r2), "=r"(r3) : "r"(addr))

#define MMA_BF16(d, a, b) \
    asm volatile("mma.sync.aligned.m16n8k16.row.col.f32.bf16.bf16.f32 " \
                 "{%0,%1,%2,%3}, {%4,%5,%6,%7}, {%8,%9}, {%0,%1,%2,%3};" \
                 : "+f"((d)[0]), "+f"((d)[1]), "+f"((d)[2]), "+f"((d)[3]) \
                 : "r"((a)[0]), "r"((a)[1]), "r"((a)[2]), "r"((a)[3]), \
                   "r"((b)[0]), "r"((b)[1]))

#define MMA_F16(d, a, b) \
    asm volatile("mma.sync.aligned.m16n8k16.row.col.f32.f16.f16.f32 " \
                 "{%0,%1,%2,%3}, {%4,%5,%6,%7}, {%8,%9}, {%0,%1,%2,%3};" \
                 : "+f"((d)[0]), "+f"((d)[1]), "+f"((d)[2]), "+f"((d)[3]) \
                 : "r"((a)[0]), "r"((a)[1]), "r"((a)[2]), "r"((a)[3]), \
                   "r"((b)[0]), "r"((b)[1]))

#define CP_ASYNC16(s, g) \
    asm volatile("cp.async.cg.shared.global [%0], [%1], 16;" :: "r"(s), "l"(g))
#define CP_COMMIT() asm volatile("cp.async.commit_group;" ::: "memory")
#define CP_WAIT0() asm volatile("cp.async.wait_group 0;" ::: "memory")

// bf16 hi/lo pack: low half = first arg
__device__ __forceinline__ void pack_hilo(float a, float b, unsigned& h, unsigned& l) {
    asm("cvt.rn.bf16x2.f32 %0, %1, %2;" : "=r"(h) : "f"(b), "f"(a));
    float fa = __uint_as_float(h << 16);
    float fb = __uint_as_float(h & 0xffff0000u);
    asm("cvt.rn.bf16x2.f32 %0, %1, %2;" : "=r"(l) : "f"(b - fb), "f"(a - fa));
}
// fp16 hi/lo pack
__device__ __forceinline__ void pack_hilo_f16(float a, float b, unsigned& h, unsigned& l) {
    asm("cvt.rn.f16x2.f32 %0, %1, %2;" : "=r"(h) : "f"(b), "f"(a));
    __half2 h2 = *reinterpret_cast<__half2*>(&h);
    float2 f = __half22float2(h2);
    asm("cvt.rn.f16x2.f32 %0, %1, %2;" : "=r"(l) : "f"(b - f.y), "f"(a - f.x));
}
// fp16 single pack
__device__ __forceinline__ unsigned pack_f16(float a, float b) {
    unsigned r;
    asm("cvt.rn.f16x2.f32 %0, %1, %2;" : "=r"(r) : "f"(b), "f"(a));
    return r;
}

// ---------------------------------------------------------------------------
// Prep (single launch): fp32 -> (hi, lo) bf16 split for x and all 4 weights
// ---------------------------------------------------------------------------
#define NX4 (MROWS * E_DIM / 4)     // 1M float4 (x)
#define NW4 (E_DIM * E_DIM / 4)     // 256K float4 (each weight)

__global__ __launch_bounds__(256) void prep_all(const float* __restrict__ x,
                                                const float* __restrict__ Wq,
                                                const float* __restrict__ Wk,
                                                const float* __restrict__ Wv,
                                                const float* __restrict__ Wo)
{
    int i = blockIdx.x * 256 + threadIdx.x;
    const float* src;
    __nv_bfloat16 *hi, *lo;
    int j;
    if (i < NX4) {
        src = x; hi = g_xhi; lo = g_xlo; j = i;
    } else {
        int t = i - NX4;
        int w = t >> 18;            // / NW4
        j = t & (NW4 - 1);
        src = (w == 0) ? Wq : (w == 1) ? Wk : (w == 2) ? Wv : Wo;
        hi = g_whi[w]; lo = g_wlo[w];
    }
    float4 v = ((const float4*)src)[j];
    unsigned h0, l0, h1, l1;
    pack_hilo(v.x, v.y, h0, l0);
    pack_hilo(v.z, v.w, h1, l1);
    ((uint2*)hi)[j] = make_uint2(h0, h1);
    ((uint2*)lo)[j] = make_uint2(l0, l1);
}

// ---------------------------------------------------------------------------
// Pipelined GEMM: C[M,N] = A[M,K]*B[N,K]^T, hi/lo bf16 3-pass, fp32 acc.
// CTA 128x64 (128 threads, 4 warps of 64m x 32n), BK=64, 2-stage cp.async,
// ONE sync per kt (16 syncs total; 192 mma/warp between syncs).
// smem per stage: A_HI 16K, A_LO 16K, B_HI 8K, B_LO 8K = 48KB. 2 stages 96KB.
// outfmt: 0 = fp32, 2 = fp16 hi/lo, 3 = fp16 single (scaled, hi only)
// ---------------------------------------------------------------------------
#define GS_AHI 0
#define GS_ALO 16384
#define GS_BHI 32768
#define GS_BLO 40960
#define GSTAGE 49152
#define G_SMEM (2 * GSTAGE)
#define NKT (E_DIM / 64)   // 16

__device__ __forceinline__ void gemm_mma_body(const __nv_bfloat16* __restrict__ Ahi,
                                              const __nv_bfloat16* __restrict__ Alo,
                                              const __nv_bfloat16* __restrict__ Bhi,
                                              const __nv_bfloat16* __restrict__ Blo,
                                              float* __restrict__ Cf,
                                              __nv_bfloat16* __restrict__ Chi,
                                              __nv_bfloat16* __restrict__ Clo,
                                              float scale, int outfmt)
{
    extern __shared__ __align__(1024) char sm[];
    const uint32_t smb = smem_to_u32(sm);
    const int tid  = threadIdx.x;
    const int w    = tid >> 5;
    const int lane = tid & 31;
    const int bm   = blockIdx.y;
    const int bn   = blockIdx.x;
    const int m0w  = (w & 1) * 64;
    const int n0w  = (w >> 1) * 32;

    float acc[4][4][4];
#pragma unroll
    for (int mt = 0; mt < 4; mt++)
#pragma unroll
        for (int nt = 0; nt < 4; nt++)
#pragma unroll
            for (int j = 0; j < 4; j++) acc[mt][nt][j] = 0.f;

    // loader: chunk = 16B column slice (8 of them = 64 cols), rowgroup = tid>>3
    const int chunk = tid & 7;
    const int rbase = tid >> 3;          // 0..15
    const int ccol  = chunk * 8;         // element col within BK=64
    uint32_t sofs[8];
#pragma unroll
    for (int p = 0; p < 8; p++)
        sofs[p] = SWZ((uint32_t)((rbase + 16 * p) * 128 + chunk * 16));

    auto issue = [&](int kt, int st) {
        const uint32_t sb = smb + (uint32_t)st * GSTAGE;
        const int col = kt * 64 + ccol;
#pragma unroll
        for (int p = 0; p < 8; p++) {
            size_t ga = (size_t)(bm * 128 + rbase + 16 * p) * E_DIM + col;
            CP_ASYNC16(sb + GS_AHI + sofs[p], Ahi + ga);
            CP_ASYNC16(sb + GS_ALO + sofs[p], Alo + ga);
        }
#pragma unroll
        for (int p = 0; p < 4; p++) {
            size_t gb = (size_t)(bn * 64 + rbase + 16 * p) * E_DIM + col;
            CP_ASYNC16(sb + GS_BHI + sofs[p], Bhi + gb);
            CP_ASYNC16(sb + GS_BLO + sofs[p], Blo + gb);
        }
        CP_COMMIT();
    };

    issue(0, 0);

    const int a_r   = (lane & 7) + ((lane >> 3) & 1) * 8;
    const int a_c16 = lane >> 4;
    const int b_r   = (lane & 7) + ((lane >> 4) & 1) * 8;
    const int b_c16 = (lane >> 3) & 1;

    for (int kt = 0; kt < NKT; kt++) {
        CP_WAIT0();
        __syncthreads();   // stage kt ready; other stage fully consumed last iter
        const uint32_t sb = smb + (uint32_t)(kt & 1) * GSTAGE;

        if (kt + 1 < NKT) issue(kt + 1, (kt + 1) & 1);

#pragma unroll
        for (int ks = 0; ks < 4; ks++) {
            uint32_t bfh[4][2], bfl[4][2];
#pragma unroll
            for (int ntp = 0; ntp < 2; ntp++) {
                int nrow = n0w + ntp * 16 + b_r;
                uint32_t off = SWZ((uint32_t)(nrow * 128 + ks * 32 + b_c16 * 16));
                LDMATRIX_X4(bfh[2 * ntp][0], bfh[2 * ntp][1],
                            bfh[2 * ntp + 1][0], bfh[2 * ntp + 1][1], sb + GS_BHI + off);
                LDMATRIX_X4(bfl[2 * ntp][0], bfl[2 * ntp][1],
                            bfl[2 * ntp + 1][0], bfl[2 * ntp + 1][1], sb + GS_BLO + off);
            }
#pragma unroll
            for (int mt = 0; mt < 4; mt++) {
                uint32_t afh[4], afl[4];
                int row = m0w + mt * 16 + a_r;
                uint32_t off = SWZ((uint32_t)(row * 128 + ks * 32 + a_c16 * 16));
                LDMATRIX_X4(afh[0], afh[1], afh[2], afh[3], sb + GS_AHI + off);
                LDMATRIX_X4(afl[0], afl[1], afl[2], afl[3], sb + GS_ALO + off);
#pragma unroll
                for (int nt = 0; nt < 4; nt++) {
                    MMA_BF16(acc[mt][nt], afh, bfh[nt]);
                    MMA_BF16(acc[mt][nt], afh, bfl[nt]);
                    MMA_BF16(acc[mt][nt], afl, bfh[nt]);
                }
            }
        }
    }

#pragma unroll
    for (int mt = 0; mt < 4; mt++) {
        size_t m = (size_t)(bm * 128 + m0w + mt * 16 + (lane >> 2));
#pragma unroll
        for (int nt = 0; nt < 4; nt++) {
            size_t n = (size_t)(bn * 64 + n0w + nt * 8 + (lane & 3) * 2);
            if (outfmt == 0) {
                float* p = Cf + m * E_DIM + n;
                *(float2*)p = make_float2(acc[mt][nt][0], acc[mt][nt][1]);
                *(float2*)(p + (size_t)8 * E_DIM) = make_float2(acc[mt][nt][2], acc[mt][nt][3]);
            } else if (outfmt == 2) {
                unsigned hh, ll;
                pack_hilo_f16(acc[mt][nt][0], acc[mt][nt][1], hh, ll);
                *(unsigned*)(Chi + m * E_DIM + n) = hh;
                *(unsigned*)(Clo + m * E_DIM + n) = ll;
                pack_hilo_f16(acc[mt][nt][2], acc[mt][nt][3], hh, ll);
                *(unsigned*)(Chi + (m + 8) * E_DIM + n) = hh;
                *(unsigned*)(Clo + (m + 8) * E_DIM + n) = ll;
            } else {
                *(unsigned*)(Chi + m * E_DIM + n) =
                    pack_f16(acc[mt][nt][0] * scale, acc[mt][nt][1] * scale);
                *(unsigned*)(Chi + (m + 8) * E_DIM + n) =
                    pack_f16(acc[mt][nt][2] * scale, acc[mt][nt][3] * scale);
            }
        }
    }
}

__global__ __launch_bounds__(128, 2) void qkv_gemm_mma()
{
    int z = blockIdx.z;
    if (z == 0)       // Q: fp16 single, 1/sqrt(dk) folded
        gemm_mma_body(g_xhi, g_xlo, g_whi[0], g_wlo[0], nullptr, g_qf, nullptr, 0.125f, 3);
    else if (z == 1)  // K: fp16 hi/lo
        gemm_mma_body(g_xhi, g_xlo, g_whi[1], g_wlo[1], nullptr, g_khi, g_klo, 1.0f, 2);
    else              // V: fp16 hi/lo
        gemm_mma_body(g_xhi, g_xlo, g_whi[2], g_wlo[2], nullptr, g_vhi, g_vlo, 1.0f, 2);
}

__global__ __launch_bounds__(128, 2) void out_gemm_mma(float* __restrict__ C)
{
    gemm_mma_body(g_mhi, g_mlo, g_whi[3], g_wlo[3], C, nullptr, nullptr, 1.0f, 0);
}

// ---------------------------------------------------------------------------
// Flash attention, mma.sync, all-fp16. Per CTA: 128 q rows of one (b,h),
// 128 threads, 4 warps x 32 q-rows. QK: Q fp16 single x K fp16 hi/lo, 2-pass.
// PV: P fp16 single x V fp16 hi/lo, 2-pass. KV tile 64, 2-stage cp.async,
// one sync/iter. smem = 16KB Q + 2x32KB = 80KB -> 2 CTAs/SM.
// ---------------------------------------------------------------------------
#define AQ    0
#define AST0  16384
#define A_KHI 0
#define A_KLO 8192
#define A_VHI 16384
#define A_VLO 24576
#define ASTAGE 32768
#define ATTN_SMEM (AST0 + 2 * ASTAGE)
#define NKV (SEQ / 64)   // 32
#define QBLK 128

__global__ __launch_bounds__(128, 2) void attn_mma(const float* __restrict__ qp)
{
    extern __shared__ __align__(1024) char sm[];
    const uint32_t smb = smem_to_u32(sm);
    const int tid  = threadIdx.x;
    const int wid  = tid >> 5;
    const int lane = tid & 31;
    const int bh   = blockIdx.y;
    const int b    = bh >> 4;
    const int h    = bh & 15;
    const int qbase = blockIdx.x * QBLK;
    const int wq0   = wid * 32;
    const float cq  = cosf(qp[0] + qp[1]);

    const size_t bS = (size_t)b * SEQ;
    const int h64 = h * 64;

    // ---- cp.async loader geometry (K/V) ----
    const __nv_bfloat16* khg = g_khi + bS * E_DIM + h64;
    const __nv_bfloat16* klg = g_klo + bS * E_DIM + h64;
    const __nv_bfloat16* vhg = g_vhi + bS * E_DIM + h64;
    const __nv_bfloat16* vlg = g_vlo + bS * E_DIM + h64;
    const int chunk = tid & 7;
    const int crow  = tid >> 3;           // 0..15
    const int ccol  = chunk * 8;
    uint32_t sco[4];
#pragma unroll
    for (int p = 0; p < 4; p++)
        sco[p] = SWZ((uint32_t)((crow + 16 * p) * 128 + chunk * 16));

    auto issue_stage = [&](int it, int st) {
        const uint32_t sb = smb + AST0 + (uint32_t)st * ASTAGE;
#pragma unroll
        for (int p = 0; p < 4; p++) {
            const size_t r = (size_t)(it * 64 + crow + 16 * p) * E_DIM + ccol;
            CP_ASYNC16(sb + A_KHI + sco[p], khg + r);
            CP_ASYNC16(sb + A_KLO + sco[p], klg + r);
            CP_ASYNC16(sb + A_VHI + sco[p], vhg + r);
            CP_ASYNC16(sb + A_VLO + sco[p], vlg + r);
        }
        CP_COMMIT();
    };

    issue_stage(0, 0);

    // ---- stage Q (fp16 single) into smem: 128 rows x 128B ----
    {
        const __nv_bfloat16* qg = g_qf + (bS + qbase) * E_DIM + h64;
#pragma unroll
        for (int p = 0; p < 8; p++) {
            int r = crow + 16 * p;
            uint32_t so = SWZ((uint32_t)(r * 128 + chunk * 16));
            *(uint4*)(sm + AQ + so) = *(const uint4*)(qg + (size_t)r * E_DIM + ccol);
        }
    }

    float mx[2][2], lsum[2][2];
    float oacc[2][8][4];
#pragma unroll
    for (int mt = 0; mt < 2; mt++) {
        mx[mt][0] = -1e30f; mx[mt][1] = -1e30f;
        lsum[mt][0] = 0.f;  lsum[mt][1] = 0.f;
#pragma unroll
        for (int nt = 0; nt < 8; nt++)
#pragma unroll
            for (int j = 0; j < 4; j++) oacc[mt][nt][j] = 0.f;
    }

    const int a_r   = (lane & 7) + ((lane >> 3) & 1) * 8;
    const int a_c16 = lane >> 4;
    const int brow  = (lane & 7) + ((lane >> 4) & 1) * 8;
    const int bc16  = (lane >> 3) & 1;
    const int vrow  = lane & 15;
    const int vcs   = (lane >> 4) * 16;

    for (int it = 0; it < NKV; it++) {
        CP_WAIT0();
        __syncthreads();   // stage 'it' ready; other stage fully consumed

        const uint32_t sb = smb + AST0 + (uint32_t)(it & 1) * ASTAGE;

        if (it + 1 < NKV) issue_stage(it + 1, (it + 1) & 1);

        // ---- S = Q.K^T (Q fp16 x K fp16 hi/lo, 2 passes), 2 m-tiles ----
        float sacc[2][8][4];
#pragma unroll
        for (int mt = 0; mt < 2; mt++)
#pragma unroll
            for (int nt = 0; nt < 8; nt++)
#pragma unroll
                for (int j = 0; j < 4; j++) sacc[mt][nt][j] = 0.f;

#pragma unroll
        for (int ks = 0; ks < 4; ks++) {
            unsigned kh2[8][2], kl2[8][2];
#pragma unroll
            for (int ntp = 0; ntp < 4; ntp++) {
                uint32_t off = SWZ((uint32_t)((ntp * 16 + brow) * 128 + ks * 32 + bc16 * 16));
                LDMATRIX_X4(kh2[2 * ntp][0], kh2[2 * ntp][1],
                            kh2[2 * ntp + 1][0], kh2[2 * ntp + 1][1], sb + A_KHI + off);
                LDMATRIX_X4(kl2[2 * ntp][0], kl2[2 * ntp][1],
                            kl2[2 * ntp + 1][0], kl2[2 * ntp + 1][1], sb + A_KLO + off);
            }
#pragma unroll
            for (int mt = 0; mt < 2; mt++) {
                unsigned qf[4];
                uint32_t qoff = SWZ((uint32_t)((wq0 + mt * 16 + a_r) * 128 + ks * 32 + a_c16 * 16));
                LDMATRIX_X4(qf[0], qf[1], qf[2], qf[3], smb + AQ + qoff);
#pragma unroll
                for (int nt = 0; nt < 8; nt++) {
                    MMA_F16(sacc[mt][nt], qf, kh2[nt]);
                    MMA_F16(sacc[mt][nt], qf, kl2[nt]);
                }
            }
        }

        // ---- online softmax per m-tile ----
#pragma unroll
        for (int mt = 0; mt < 2; mt++) {
            float mn0 = mx[mt][0], mn1 = mx[mt][1];
#pragma unroll
            for (int nt = 0; nt < 8; nt++) {
                mn0 = fmaxf(mn0, fmaxf(sacc[mt][nt][0], sacc[mt][nt][1]));
                mn1 = fmaxf(mn1, fmaxf(sacc[mt][nt][2], sacc[mt][nt][3]));
            }
            mn0 = fmaxf(mn0, __shfl_xor_sync(0xffffffffu, mn0, 1));
            mn0 = fmaxf(mn0, __shfl_xor_sync(0xffffffffu, mn0, 2));
            mn1 = fmaxf(mn1, __shfl_xor_sync(0xffffffffu, mn1, 1));
            mn1 = fmaxf(mn1, __shfl_xor_sync(0xffffffffu, mn1, 2));
            float sc0 = __expf(mx[mt][0] - mn0);
            float sc1 = __expf(mx[mt][1] - mn1);
            mx[mt][0] = mn0; mx[mt][1] = mn1;
            float rs0 = 0.f, rs1 = 0.f;
#pragma unroll
            for (int nt = 0; nt < 8; nt++) {
                sacc[mt][nt][0] = __expf(sacc[mt][nt][0] - mn0); rs0 += sacc[mt][nt][0];
                sacc[mt][nt][1] = __expf(sacc[mt][nt][1] - mn0); rs0 += sacc[mt][nt][1];
                sacc[mt][nt][2] = __expf(sacc[mt][nt][2] - mn1); rs1 += sacc[mt][nt][2];
                sacc[mt][nt][3] = __expf(sacc[mt][nt][3] - mn1); rs1 += sacc[mt][nt][3];
            }
            rs0 += __shfl_xor_sync(0xffffffffu, rs0, 1);
            rs0 += __shfl_xor_sync(0xffffffffu, rs0, 2);
            rs1 += __shfl_xor_sync(0xffffffffu, rs1, 1);
            rs1 += __shfl_xor_sync(0xffffffffu, rs1, 2);
            lsum[mt][0] = lsum[mt][0] * sc0 + rs0;
            lsum[mt][1] = lsum[mt][1] * sc1 + rs1;
#pragma unroll
            for (int nt = 0; nt < 8; nt++) {
                oacc[mt][nt][0] *= sc0; oacc[mt][nt][1] *= sc0;
                oacc[mt][nt][2] *= sc1; oacc[mt][nt][3] *= sc1;
            }
        }

        // ---- O += P.V: P fp16 single, V fp16 hi/lo (2 passes) ----
#pragma unroll
        for (int j = 0; j < 4; j++) {
            unsigned vh2[8][2], vl2[8][2];
#pragma unroll
            for (int dp = 0; dp < 4; dp++) {
                uint32_t off = SWZ((uint32_t)((j * 16 + vrow) * 128 + dp * 32 + vcs));
                LDMATRIX_X4_T(vh2[2 * dp][0], vh2[2 * dp][1],
                              vh2[2 * dp + 1][0], vh2[2 * dp + 1][1], sb + A_VHI + off);
                LDMATRIX_X4_T(vl2[2 * dp][0], vl2[2 * dp][1],
                              vl2[2 * dp + 1][0], vl2[2 * dp + 1][1], sb + A_VLO + off);
            }
#pragma unroll
            for (int mt = 0; mt < 2; mt++) {
                unsigned ph[4];
                ph[0] = pack_f16(sacc[mt][2 * j][0],     sacc[mt][2 * j][1]);
                ph[1] = pack_f16(sacc[mt][2 * j][2],     sacc[mt][2 * j][3]);
                ph[2] = pack_f16(sacc[mt][2 * j + 1][0], sacc[mt][2 * j + 1][1]);
                ph[3] = pack_f16(sacc[mt][2 * j + 1][2], sacc[mt][2 * j + 1][3]);
#pragma unroll
                for (int nt = 0; nt < 8; nt++) {
                    MMA_F16(oacc[mt][nt], ph, vh2[nt]);
                    MMA_F16(oacc[mt][nt], ph, vl2[nt]);
                }
            }
        }
    }

    // ---- epilogue: normalize, +c on dk<4, write hi/lo bf16 mix ----
    const bool adds = ((lane & 3) < 2);
#pragma unroll
    for (int mt = 0; mt < 2; mt++) {
        const float inv0 = 1.f / lsum[mt][0];
        const float inv1 = 1.f / lsum[mt][1];
        const size_t row0 = (bS + qbase + wq0 + mt * 16 + (lane >> 2)) * E_DIM
                            + h64 + (lane & 3) * 2;
        const size_t row1 = row0 + 8 * E_DIM;
#pragma unroll
        for (int nt = 0; nt < 8; nt++) {
            const float add = (nt == 0 && adds) ? cq : 0.f;
            float v0 = oacc[mt][nt][0] * inv0 + add;
            float v1 = oacc[mt][nt][1] * inv0 + add;
            float v2 = oacc[mt][nt][2] * inv1 + add;
            float v3 = oacc[mt][nt][3] * inv1 + add;
            unsigned hh, ll;
            pack_hilo(v0, v1, hh, ll);
            *(unsigned*)(g_mhi + row0 + nt * 8) = hh;
            *(unsigned*)(g_mlo + row0 + nt * 8) = ll;
            pack_hilo(v2, v3, hh, ll);
            *(unsigned*)(g_mhi + row1 + nt * 8) = hh;
            *(unsigned*)(g_mlo + row1 + nt * 8) = ll;
        }
    }
}

// ---------------------------------------------------------------------------
extern "C" void kernel_launch(void* const* d_in, const int* in_sizes, int n_in,
                              void* d_out, int out_size)
{
    const float* x  = (const float*)d_in[0];
    const float* Wq = (const float*)d_in[1];
    const float* Wk = (const float*)d_in[2];
    const float* Wv = (const float*)d_in[3];
    const float* Wo = (const float*)d_in[4];
    const float* qp = (const float*)d_in[5];
    float* out = (float*)d_out;

    cudaFuncSetAttribute(qkv_gemm_mma, cudaFuncAttributeMaxDynamicSharedMemorySize, G_SMEM);
    cudaFuncSetAttribute(out_gemm_mma, cudaFuncAttributeMaxDynamicSharedMemorySize, G_SMEM);
    cudaFuncSetAttribute(attn_mma,     cudaFuncAttributeMaxDynamicSharedMemorySize, ATTN_SMEM);

    const int NPREP = NX4 + 4 * NW4;   // 2M float4 units
    prep_all<<<(NPREP + 255) / 256, 256>>>(x, Wq, Wk, Wv, Wo);

    qkv_gemm_mma<<<dim3(16, 32, 3), 128, G_SMEM>>>();
    attn_mma<<<dim3(SEQ / QBLK, BATCH * NHEAD), 128, ATTN_SMEM>>>(qp);
    out_gemm_mma<<<dim3(16, 32), 128, G_SMEM>>>(out);
}

// round 10
// speedup vs baseline: 7.3202x; 1.5650x over previous
#include <cuda_runtime.h>
#include <cuda_bf16.h>
#include <cuda_fp16.h>
#include <math.h>
#include <cstdint>

#define E_DIM 1024
#define SEQ   2048
#define BATCH 2
#define NHEAD 16
#define DK    64
#define MROWS (BATCH * SEQ)   // 4096

// ---------------------------------------------------------------------------
// Scratch (device globals; 16-bit storage, bits are fp16)
// ---------------------------------------------------------------------------
__device__ __nv_bfloat16 g_xf[MROWS * E_DIM];       // x fp16 single
__device__ __nv_bfloat16 g_wh[4][E_DIM * E_DIM];    // W fp16 hi (q,k,v,o)
__device__ __nv_bfloat16 g_wl[4][E_DIM * E_DIM];    // W fp16 lo
__device__ __nv_bfloat16 g_qf[MROWS * E_DIM];       // Q fp16 (scaled 1/8)
__device__ __nv_bfloat16 g_kf[MROWS * E_DIM];       // K fp16
__device__ __nv_bfloat16 g_vf[MROWS * E_DIM];       // V fp16
__device__ __nv_bfloat16 g_mf[MROWS * E_DIM];       // mix fp16

// ---------------------------------------------------------------------------
// Helpers
// ---------------------------------------------------------------------------
__device__ __forceinline__ uint32_t smem_to_u32(const void* p) {
    uint32_t a;
    asm("{ .reg .u64 t; cvta.to.shared.u64 t, %1; cvt.u32.u64 %0, t; }"
        : "=r"(a) : "l"(p));
    return a;
}
#define SWZ(o) ((o) ^ (((o) >> 3) & 0x70))

#define LDMATRIX_X4(r0, r1, r2, r3, addr) \
    asm volatile("ldmatrix.sync.aligned.m8n8.x4.shared.b16 {%0,%1,%2,%3}, [%4];" \
                 : "=r"(r0), "=r"(r1), "=r"(r2), "=r"(r3) : "r"(addr))

#define LDMATRIX_X4_T(r0, r1, r2, r3, addr) \
    asm volatile("ldmatrix.sync.aligned.m8n8.x4.trans.shared.b16 {%0,%1,%2,%3}, [%4];" \
                 : "=r"(r0), "=r"(r1), "=r"(r2), "=r"(r3) : "r"(addr))

#define MMA_F16(d, a, b) \
    asm volatile("mma.sync.aligned.m16n8k16.row.col.f32.f16.f16.f32 " \
                 "{%0,%1,%2,%3}, {%4,%5,%6,%7}, {%8,%9}, {%0,%1,%2,%3};" \
                 : "+f"((d)[0]), "+f"((d)[1]), "+f"((d)[2]), "+f"((d)[3]) \
                 : "r"((a)[0]), "r"((a)[1]), "r"((a)[2]), "r"((a)[3]), \
                   "r"((b)[0]), "r"((b)[1]))

#define CP_ASYNC16(s, g) \
    asm volatile("cp.async.cg.shared.global [%0], [%1], 16;" :: "r"(s), "l"(g))
#define CP_COMMIT() asm volatile("cp.async.commit_group;" ::: "memory")
#define CP_WAIT0() asm volatile("cp.async.wait_group 0;" ::: "memory")

// fp16 hi/lo pack
__device__ __forceinline__ void pack_hilo_f16(float a, float b, unsigned& h, unsigned& l) {
    asm("cvt.rn.f16x2.f32 %0, %1, %2;" : "=r"(h) : "f"(b), "f"(a));
    __half2 h2 = *reinterpret_cast<__half2*>(&h);
    float2 f = __half22float2(h2);
    asm("cvt.rn.f16x2.f32 %0, %1, %2;" : "=r"(l) : "f"(b - f.y), "f"(a - f.x));
}
// fp16 single pack
__device__ __forceinline__ unsigned pack_f16(float a, float b) {
    unsigned r;
    asm("cvt.rn.f16x2.f32 %0, %1, %2;" : "=r"(r) : "f"(b), "f"(a));
    return r;
}

// ---------------------------------------------------------------------------
// Prep: x -> fp16 single; W -> fp16 hi/lo
// ---------------------------------------------------------------------------
#define NX4 (MROWS * E_DIM / 4)     // 1M float4 (x)
#define NW4 (E_DIM * E_DIM / 4)     // 256K float4 (each weight)

__global__ __launch_bounds__(256) void prep_all(const float* __restrict__ x,
                                                const float* __restrict__ Wq,
                                                const float* __restrict__ Wk,
                                                const float* __restrict__ Wv,
                                                const float* __restrict__ Wo)
{
    int i = blockIdx.x * 256 + threadIdx.x;
    if (i < NX4) {
        float4 v = ((const float4*)x)[i];
        ((uint2*)g_xf)[i] = make_uint2(pack_f16(v.x, v.y), pack_f16(v.z, v.w));
    } else {
        int t = i - NX4;
        int w = t >> 18;            // / NW4
        int j = t & (NW4 - 1);
        const float* src = (w == 0) ? Wq : (w == 1) ? Wk : (w == 2) ? Wv : Wo;
        float4 v = ((const float4*)src)[j];
        unsigned h0, l0, h1, l1;
        pack_hilo_f16(v.x, v.y, h0, l0);
        pack_hilo_f16(v.z, v.w, h1, l1);
        ((uint2*)g_wh[w])[j] = make_uint2(h0, h1);
        ((uint2*)g_wl[w])[j] = make_uint2(l0, l1);
    }
}

// ---------------------------------------------------------------------------
// Pipelined GEMM: C[M,N] = A[M,K]*B[N,K]^T.
// A fp16 single, B fp16 hi/lo -> 2 passes, fp32 acc.
// CTA 128x64 (128 threads, 4 warps of 64m x 32n), BK=64, 2-stage cp.async,
// one sync per kt. Stage = A 16KB + Bhi 8KB + Blo 8KB = 32KB; 2 stages 64KB.
// outfmt: 0 = fp32, 3 = fp16 single (scaled)
// ---------------------------------------------------------------------------
#define GS_A   0
#define GS_BHI 16384
#define GS_BLO 24576
#define GSTAGE 32768
#define G_SMEM (2 * GSTAGE)
#define NKT (E_DIM / 64)   // 16

__device__ __forceinline__ void gemm_mma_body(const __nv_bfloat16* __restrict__ Af,
                                              const __nv_bfloat16* __restrict__ Bhi,
                                              const __nv_bfloat16* __restrict__ Blo,
                                              float* __restrict__ Cf,
                                              __nv_bfloat16* __restrict__ Ch,
                                              float scale, int outfmt)
{
    extern __shared__ __align__(1024) char sm[];
    const uint32_t smb = smem_to_u32(sm);
    const int tid  = threadIdx.x;
    const int w    = tid >> 5;
    const int lane = tid & 31;
    const int bm   = blockIdx.y;
    const int bn   = blockIdx.x;
    const int m0w  = (w & 1) * 64;
    const int n0w  = (w >> 1) * 32;

    float acc[4][4][4];
#pragma unroll
    for (int mt = 0; mt < 4; mt++)
#pragma unroll
        for (int nt = 0; nt < 4; nt++)
#pragma unroll
            for (int j = 0; j < 4; j++) acc[mt][nt][j] = 0.f;

    const int chunk = tid & 7;
    const int rbase = tid >> 3;          // 0..15
    const int ccol  = chunk * 8;         // element col within BK=64
    uint32_t sofs[8];
#pragma unroll
    for (int p = 0; p < 8; p++)
        sofs[p] = SWZ((uint32_t)((rbase + 16 * p) * 128 + chunk * 16));

    auto issue = [&](int kt, int st) {
        const uint32_t sb = smb + (uint32_t)st * GSTAGE;
        const int col = kt * 64 + ccol;
#pragma unroll
        for (int p = 0; p < 8; p++)
            CP_ASYNC16(sb + GS_A + sofs[p],
                       Af + (size_t)(bm * 128 + rbase + 16 * p) * E_DIM + col);
#pragma unroll
        for (int p = 0; p < 4; p++) {
            size_t gb = (size_t)(bn * 64 + rbase + 16 * p) * E_DIM + col;
            CP_ASYNC16(sb + GS_BHI + sofs[p], Bhi + gb);
            CP_ASYNC16(sb + GS_BLO + sofs[p], Blo + gb);
        }
        CP_COMMIT();
    };

    issue(0, 0);

    const int a_r   = (lane & 7) + ((lane >> 3) & 1) * 8;
    const int a_c16 = lane >> 4;
    const int b_r   = (lane & 7) + ((lane >> 4) & 1) * 8;
    const int b_c16 = (lane >> 3) & 1;

    for (int kt = 0; kt < NKT; kt++) {
        CP_WAIT0();
        __syncthreads();
        const uint32_t sb = smb + (uint32_t)(kt & 1) * GSTAGE;

        if (kt + 1 < NKT) issue(kt + 1, (kt + 1) & 1);

#pragma unroll
        for (int ks = 0; ks < 4; ks++) {
            uint32_t bfh[4][2], bfl[4][2];
#pragma unroll
            for (int ntp = 0; ntp < 2; ntp++) {
                int nrow = n0w + ntp * 16 + b_r;
                uint32_t off = SWZ((uint32_t)(nrow * 128 + ks * 32 + b_c16 * 16));
                LDMATRIX_X4(bfh[2 * ntp][0], bfh[2 * ntp][1],
                            bfh[2 * ntp + 1][0], bfh[2 * ntp + 1][1], sb + GS_BHI + off);
                LDMATRIX_X4(bfl[2 * ntp][0], bfl[2 * ntp][1],
                            bfl[2 * ntp + 1][0], bfl[2 * ntp + 1][1], sb + GS_BLO + off);
            }
#pragma unroll
            for (int mt = 0; mt < 4; mt++) {
                uint32_t af[4];
                int row = m0w + mt * 16 + a_r;
                uint32_t off = SWZ((uint32_t)(row * 128 + ks * 32 + a_c16 * 16));
                LDMATRIX_X4(af[0], af[1], af[2], af[3], sb + GS_A + off);
#pragma unroll
                for (int nt = 0; nt < 4; nt++) {
                    MMA_F16(acc[mt][nt], af, bfh[nt]);
                    MMA_F16(acc[mt][nt], af, bfl[nt]);
                }
            }
        }
    }

#pragma unroll
    for (int mt = 0; mt < 4; mt++) {
        size_t m = (size_t)(bm * 128 + m0w + mt * 16 + (lane >> 2));
#pragma unroll
        for (int nt = 0; nt < 4; nt++) {
            size_t n = (size_t)(bn * 64 + n0w + nt * 8 + (lane & 3) * 2);
            if (outfmt == 0) {
                float* p = Cf + m * E_DIM + n;
                *(float2*)p = make_float2(acc[mt][nt][0], acc[mt][nt][1]);
                *(float2*)(p + (size_t)8 * E_DIM) = make_float2(acc[mt][nt][2], acc[mt][nt][3]);
            } else {
                *(unsigned*)(Ch + m * E_DIM + n) =
                    pack_f16(acc[mt][nt][0] * scale, acc[mt][nt][1] * scale);
                *(unsigned*)(Ch + (m + 8) * E_DIM + n) =
                    pack_f16(acc[mt][nt][2] * scale, acc[mt][nt][3] * scale);
            }
        }
    }
}

__global__ __launch_bounds__(128, 3) void qkv_gemm_mma()
{
    int z = blockIdx.z;
    __nv_bfloat16* C = (z == 0) ? g_qf : (z == 1) ? g_kf : g_vf;
    float scale = (z == 0) ? 0.125f : 1.0f;   // fold 1/sqrt(dk) into Q
    gemm_mma_body(g_xf, g_wh[z], g_wl[z], nullptr, C, scale, 3);
}

__global__ __launch_bounds__(128, 3) void out_gemm_mma(float* __restrict__ C)
{
    gemm_mma_body(g_mf, g_wh[3], g_wl[3], C, nullptr, 1.0f, 0);
}

// ---------------------------------------------------------------------------
// Flash attention, all single fp16, 1-pass QK and 1-pass PV.
// Per CTA: 128 q rows of one (b,h), 128 threads, 4 warps x 32 q-rows.
// KV tile 64, 2-stage cp.async, one sync/iter. smem = 16KB Q + 2x16KB = 48KB.
// ---------------------------------------------------------------------------
#define AQ    0
#define AST0  16384
#define A_K   0
#define A_V   8192
#define ASTAGE 16384
#define ATTN_SMEM (AST0 + 2 * ASTAGE)
#define NKV (SEQ / 64)   // 32
#define QBLK 128

__global__ __launch_bounds__(128, 2) void attn_mma(const float* __restrict__ qp)
{
    extern __shared__ __align__(1024) char sm[];
    const uint32_t smb = smem_to_u32(sm);
    const int tid  = threadIdx.x;
    const int wid  = tid >> 5;
    const int lane = tid & 31;
    const int bh   = blockIdx.y;
    const int b    = bh >> 4;
    const int h    = bh & 15;
    const int qbase = blockIdx.x * QBLK;
    const int wq0   = wid * 32;
    const float cq  = cosf(qp[0] + qp[1]);

    const size_t bS = (size_t)b * SEQ;
    const int h64 = h * 64;

    const __nv_bfloat16* kg = g_kf + bS * E_DIM + h64;
    const __nv_bfloat16* vg = g_vf + bS * E_DIM + h64;
    const int chunk = tid & 7;
    const int crow  = tid >> 3;           // 0..15
    const int ccol  = chunk * 8;
    uint32_t sco[4];
#pragma unroll
    for (int p = 0; p < 4; p++)
        sco[p] = SWZ((uint32_t)((crow + 16 * p) * 128 + chunk * 16));

    auto issue_stage = [&](int it, int st) {
        const uint32_t sb = smb + AST0 + (uint32_t)st * ASTAGE;
#pragma unroll
        for (int p = 0; p < 4; p++) {
            const size_t r = (size_t)(it * 64 + crow + 16 * p) * E_DIM + ccol;
            CP_ASYNC16(sb + A_K + sco[p], kg + r);
            CP_ASYNC16(sb + A_V + sco[p], vg + r);
        }
        CP_COMMIT();
    };

    issue_stage(0, 0);

    // stage Q (fp16 single): 128 rows x 128B
    {
        const __nv_bfloat16* qg = g_qf + (bS + qbase) * E_DIM + h64;
#pragma unroll
        for (int p = 0; p < 8; p++) {
            int r = crow + 16 * p;
            uint32_t so = SWZ((uint32_t)(r * 128 + chunk * 16));
            *(uint4*)(sm + AQ + so) = *(const uint4*)(qg + (size_t)r * E_DIM + ccol);
        }
    }

    float mx[2][2], lsum[2][2];
    float oacc[2][8][4];
#pragma unroll
    for (int mt = 0; mt < 2; mt++) {
        mx[mt][0] = -1e30f; mx[mt][1] = -1e30f;
        lsum[mt][0] = 0.f;  lsum[mt][1] = 0.f;
#pragma unroll
        for (int nt = 0; nt < 8; nt++)
#pragma unroll
            for (int j = 0; j < 4; j++) oacc[mt][nt][j] = 0.f;
    }

    const int a_r   = (lane & 7) + ((lane >> 3) & 1) * 8;
    const int a_c16 = lane >> 4;
    const int brow  = (lane & 7) + ((lane >> 4) & 1) * 8;
    const int bc16  = (lane >> 3) & 1;
    const int vrow  = lane & 15;
    const int vcs   = (lane >> 4) * 16;

    for (int it = 0; it < NKV; it++) {
        CP_WAIT0();
        __syncthreads();

        const uint32_t sb = smb + AST0 + (uint32_t)(it & 1) * ASTAGE;

        if (it + 1 < NKV) issue_stage(it + 1, (it + 1) & 1);

        // ---- S = Q.K^T (fp16 x fp16, 1 pass), 2 m-tiles ----
        float sacc[2][8][4];
#pragma unroll
        for (int mt = 0; mt < 2; mt++)
#pragma unroll
            for (int nt = 0; nt < 8; nt++)
#pragma unroll
                for (int j = 0; j < 4; j++) sacc[mt][nt][j] = 0.f;

#pragma unroll
        for (int ks = 0; ks < 4; ks++) {
            unsigned kf2[8][2];
#pragma unroll
            for (int ntp = 0; ntp < 4; ntp++) {
                uint32_t off = SWZ((uint32_t)((ntp * 16 + brow) * 128 + ks * 32 + bc16 * 16));
                LDMATRIX_X4(kf2[2 * ntp][0], kf2[2 * ntp][1],
                            kf2[2 * ntp + 1][0], kf2[2 * ntp + 1][1], sb + A_K + off);
            }
#pragma unroll
            for (int mt = 0; mt < 2; mt++) {
                unsigned qf[4];
                uint32_t qoff = SWZ((uint32_t)((wq0 + mt * 16 + a_r) * 128 + ks * 32 + a_c16 * 16));
                LDMATRIX_X4(qf[0], qf[1], qf[2], qf[3], smb + AQ + qoff);
#pragma unroll
                for (int nt = 0; nt < 8; nt++)
                    MMA_F16(sacc[mt][nt], qf, kf2[nt]);
            }
        }

        // ---- online softmax per m-tile ----
#pragma unroll
        for (int mt = 0; mt < 2; mt++) {
            float mn0 = mx[mt][0], mn1 = mx[mt][1];
#pragma unroll
            for (int nt = 0; nt < 8; nt++) {
                mn0 = fmaxf(mn0, fmaxf(sacc[mt][nt][0], sacc[mt][nt][1]));
                mn1 = fmaxf(mn1, fmaxf(sacc[mt][nt][2], sacc[mt][nt][3]));
            }
            mn0 = fmaxf(mn0, __shfl_xor_sync(0xffffffffu, mn0, 1));
            mn0 = fmaxf(mn0, __shfl_xor_sync(0xffffffffu, mn0, 2));
            mn1 = fmaxf(mn1, __shfl_xor_sync(0xffffffffu, mn1, 1));
            mn1 = fmaxf(mn1, __shfl_xor_sync(0xffffffffu, mn1, 2));
            float sc0 = __expf(mx[mt][0] - mn0);
            float sc1 = __expf(mx[mt][1] - mn1);
            mx[mt][0] = mn0; mx[mt][1] = mn1;
            float rs0 = 0.f, rs1 = 0.f;
#pragma unroll
            for (int nt = 0; nt < 8; nt++) {
                sacc[mt][nt][0] = __expf(sacc[mt][nt][0] - mn0); rs0 += sacc[mt][nt][0];
                sacc[mt][nt][1] = __expf(sacc[mt][nt][1] - mn0); rs0 += sacc[mt][nt][1];
                sacc[mt][nt][2] = __expf(sacc[mt][nt][2] - mn1); rs1 += sacc[mt][nt][2];
                sacc[mt][nt][3] = __expf(sacc[mt][nt][3] - mn1); rs1 += sacc[mt][nt][3];
            }
            rs0 += __shfl_xor_sync(0xffffffffu, rs0, 1);
            rs0 += __shfl_xor_sync(0xffffffffu, rs0, 2);
            rs1 += __shfl_xor_sync(0xffffffffu, rs1, 1);
            rs1 += __shfl_xor_sync(0xffffffffu, rs1, 2);
            lsum[mt][0] = lsum[mt][0] * sc0 + rs0;
            lsum[mt][1] = lsum[mt][1] * sc1 + rs1;
#pragma unroll
            for (int nt = 0; nt < 8; nt++) {
                oacc[mt][nt][0] *= sc0; oacc[mt][nt][1] *= sc0;
                oacc[mt][nt][2] *= sc1; oacc[mt][nt][3] *= sc1;
            }
        }

        // ---- O += P.V (fp16 x fp16, 1 pass) ----
#pragma unroll
        for (int j = 0; j < 4; j++) {
            unsigned vf2[8][2];
#pragma unroll
            for (int dp = 0; dp < 4; dp++) {
                uint32_t off = SWZ((uint32_t)((j * 16 + vrow) * 128 + dp * 32 + vcs));
                LDMATRIX_X4_T(vf2[2 * dp][0], vf2[2 * dp][1],
                              vf2[2 * dp + 1][0], vf2[2 * dp + 1][1], sb + A_V + off);
            }
#pragma unroll
            for (int mt = 0; mt < 2; mt++) {
                unsigned ph[4];
                ph[0] = pack_f16(sacc[mt][2 * j][0],     sacc[mt][2 * j][1]);
                ph[1] = pack_f16(sacc[mt][2 * j][2],     sacc[mt][2 * j][3]);
                ph[2] = pack_f16(sacc[mt][2 * j + 1][0], sacc[mt][2 * j + 1][1]);
                ph[3] = pack_f16(sacc[mt][2 * j + 1][2], sacc[mt][2 * j + 1][3]);
#pragma unroll
                for (int nt = 0; nt < 8; nt++)
                    MMA_F16(oacc[mt][nt], ph, vf2[nt]);
            }
        }
    }

    // ---- epilogue: normalize, +c on dk<4, write fp16 mix ----
    const bool adds = ((lane & 3) < 2);
#pragma unroll
    for (int mt = 0; mt < 2; mt++) {
        const float inv0 = 1.f / lsum[mt][0];
        const float inv1 = 1.f / lsum[mt][1];
        const size_t row0 = (bS + qbase + wq0 + mt * 16 + (lane >> 2)) * E_DIM
                            + h64 + (lane & 3) * 2;
        const size_t row1 = row0 + 8 * E_DIM;
#pragma unroll
        for (int nt = 0; nt < 8; nt++) {
            const float add = (nt == 0 && adds) ? cq : 0.f;
            *(unsigned*)(g_mf + row0 + nt * 8) =
                pack_f16(oacc[mt][nt][0] * inv0 + add, oacc[mt][nt][1] * inv0 + add);
            *(unsigned*)(g_mf + row1 + nt * 8) =
                pack_f16(oacc[mt][nt][2] * inv1 + add, oacc[mt][nt][3] * inv1 + add);
        }
    }
}

// ---------------------------------------------------------------------------
extern "C" void kernel_launch(void* const* d_in, const int* in_sizes, int n_in,
                              void* d_out, int out_size)
{
    const float* x  = (const float*)d_in[0];
    const float* Wq = (const float*)d_in[1];
    const float* Wk = (const float*)d_in[2];
    const float* Wv = (const float*)d_in[3];
    const float* Wo = (const float*)d_in[4];
    const float* qp = (const float*)d_in[5];
    float* out = (float*)d_out;

    cudaFuncSetAttribute(qkv_gemm_mma, cudaFuncAttributeMaxDynamicSharedMemorySize, G_SMEM);
    cudaFuncSetAttribute(out_gemm_mma, cudaFuncAttributeMaxDynamicSharedMemorySize, G_SMEM);
    cudaFuncSetAttribute(attn_mma,     cudaFuncAttributeMaxDynamicSharedMemorySize, ATTN_SMEM);

    const int NPREP = NX4 + 4 * NW4;   // 2M float4 units
    prep_all<<<(NPREP + 255) / 256, 256>>>(x, Wq, Wk, Wv, Wo);

    qkv_gemm_mma<<<dim3(16, 32, 3), 128, G_SMEM>>>();
    attn_mma<<<dim3(SEQ / QBLK, BATCH * NHEAD), 128, ATTN_SMEM>>>(qp);
    out_gemm_mma<<<dim3(16, 32), 128, G_SMEM>>>(out);
}